// round 1
// baseline (speedup 1.0000x reference)
#include <cuda_runtime.h>
#include <math.h>

#define B_   4
#define CIN  1024
#define CB   256
#define H_   64
#define W_   64
#define HW   (H_*W_)
#define KOFF 9

// ---------------- scratch (device globals; no runtime allocation) ----------
__device__ float g_out1[(size_t)B_*CB*HW];              // 16.7 MB
__device__ float g_om  [(size_t)B_*27*HW];              // 1.8 MB
__device__ float g_samp[(size_t)B_*CB*KOFF*HW];         // 151 MB
__device__ float g_out2[(size_t)B_*CB*HW];              // 16.7 MB
__device__ float g_out3[(size_t)B_*CIN*HW];             // 67 MB

// ---------------- generic batched SGEMM: C[b] = A @ B[b] -------------------
// A: [M,K] row-major (weights, shared over batch). B: [K,N]. C: [M,N].
// Requires M%128==0, N%128==0, K%8==0 (true for all call sites).
__global__ void __launch_bounds__(256) sgemm_kernel(
    const float* __restrict__ A, const float* __restrict__ Bm,
    float* __restrict__ Cm, int M, int N, int K,
    size_t strideB, size_t strideC)
{
    const float* Bp = Bm + (size_t)blockIdx.z * strideB;
    float*       Cp = Cm + (size_t)blockIdx.z * strideC;
    const int bm = blockIdx.y * 128;
    const int bn = blockIdx.x * 128;

    __shared__ float As[8][128];
    __shared__ float Bs[8][128];

    const int tid  = threadIdx.x;
    const int arow = tid >> 1;            // 0..127
    const int acol = (tid & 1) * 4;       // 0 or 4
    const int brow = tid >> 5;            // 0..7
    const int bcol = (tid & 31) * 4;      // 0..124
    const int ty   = tid >> 4;            // 0..15
    const int tx   = tid & 15;            // 0..15

    float acc[8][8];
#pragma unroll
    for (int i = 0; i < 8; i++)
#pragma unroll
        for (int j = 0; j < 8; j++) acc[i][j] = 0.f;

    const float* Aptr = A  + (size_t)(bm + arow) * K + acol;
    const float* Bptr = Bp + (size_t)brow * N + bn + bcol;

    for (int k0 = 0; k0 < K; k0 += 8) {
        float4 av = *(const float4*)(Aptr + k0);
        As[acol + 0][arow] = av.x;
        As[acol + 1][arow] = av.y;
        As[acol + 2][arow] = av.z;
        As[acol + 3][arow] = av.w;
        float4 bv = *(const float4*)(Bptr + (size_t)k0 * N);
        *(float4*)(&Bs[brow][bcol]) = bv;
        __syncthreads();
#pragma unroll
        for (int kk = 0; kk < 8; kk++) {
            float a[8], bb[8];
#pragma unroll
            for (int i = 0; i < 8; i++) a[i]  = As[kk][ty * 8 + i];
#pragma unroll
            for (int j = 0; j < 8; j++) bb[j] = Bs[kk][tx * 8 + j];
#pragma unroll
            for (int i = 0; i < 8; i++)
#pragma unroll
                for (int j = 0; j < 8; j++) acc[i][j] += a[i] * bb[j];
        }
        __syncthreads();
    }
#pragma unroll
    for (int i = 0; i < 8; i++) {
        float* crow = Cp + (size_t)(bm + ty * 8 + i) * N + bn + tx * 8;
#pragma unroll
        for (int j = 0; j < 8; j += 4) {
            float4 v = make_float4(acc[i][j], acc[i][j+1], acc[i][j+2], acc[i][j+3]);
            *(float4*)(crow + j) = v;
        }
    }
}

// ---------------- block reduction helper -----------------------------------
__device__ __forceinline__ void block_reduce2(float& s, float& ss) {
#pragma unroll
    for (int o = 16; o > 0; o >>= 1) {
        s  += __shfl_down_sync(0xFFFFFFFFu, s,  o);
        ss += __shfl_down_sync(0xFFFFFFFFu, ss, o);
    }
    __shared__ float as_[32], ass_[32];
    int lane = threadIdx.x & 31, wid = threadIdx.x >> 5;
    if (lane == 0) { as_[wid] = s; ass_[wid] = ss; }
    __syncthreads();
    int nw = blockDim.x >> 5;
    if (wid == 0) {
        s  = (lane < nw) ? as_[lane]  : 0.f;
        ss = (lane < nw) ? ass_[lane] : 0.f;
#pragma unroll
        for (int o = 16; o > 0; o >>= 1) {
            s  += __shfl_down_sync(0xFFFFFFFFu, s,  o);
            ss += __shfl_down_sync(0xFFFFFFFFu, ss, o);
        }
    }
}

// ---------------- GroupNorm (+ReLU), in-place; one block per (b, group) ----
__global__ void gn_relu_kernel(float* __restrict__ data,
                               const float* __restrict__ scale,
                               const float* __restrict__ bias,
                               int C, int cpg)
{
    const int G  = C / cpg;
    const int b  = blockIdx.x / G;
    const int gi = blockIdx.x % G;
    float* p = data + ((size_t)b * C + (size_t)gi * cpg) * HW;
    const int n = cpg * HW;

    float s = 0.f, ss = 0.f;
    for (int i = threadIdx.x; i < n; i += blockDim.x) {
        float v = p[i]; s += v; ss += v * v;
    }
    block_reduce2(s, ss);
    __shared__ float sh_mean, sh_rstd;
    if (threadIdx.x == 0) {
        float mean = s / n;
        float var  = ss / n - mean * mean;
        sh_mean = mean;
        sh_rstd = rsqrtf(var + 1e-5f);
    }
    __syncthreads();
    const float mean = sh_mean, rstd = sh_rstd;
    for (int i = threadIdx.x; i < n; i += blockDim.x) {
        int c = gi * cpg + i / HW;
        float v = (p[i] - mean) * rstd * scale[c] + bias[c];
        p[i] = fmaxf(v, 0.f);
    }
}

// ---------------- GN3 + residual + ReLU -> output --------------------------
__global__ void gn_res_relu_kernel(const float* __restrict__ in,
                                   const float* __restrict__ xres,
                                   const float* __restrict__ scale,
                                   const float* __restrict__ bias,
                                   float* __restrict__ out,
                                   int C, int cpg)
{
    const int G  = C / cpg;
    const int b  = blockIdx.x / G;
    const int gi = blockIdx.x % G;
    const size_t base = ((size_t)b * C + (size_t)gi * cpg) * HW;
    const float* p = in + base;
    const int n = cpg * HW;

    float s = 0.f, ss = 0.f;
    for (int i = threadIdx.x; i < n; i += blockDim.x) {
        float v = p[i]; s += v; ss += v * v;
    }
    block_reduce2(s, ss);
    __shared__ float sh_mean, sh_rstd;
    if (threadIdx.x == 0) {
        float mean = s / n;
        float var  = ss / n - mean * mean;
        sh_mean = mean;
        sh_rstd = rsqrtf(var + 1e-5f);
    }
    __syncthreads();
    const float mean = sh_mean, rstd = sh_rstd;
    for (int i = threadIdx.x; i < n; i += blockDim.x) {
        int c = gi * cpg + i / HW;
        float v = (p[i] - mean) * rstd * scale[c] + bias[c] + xres[base + i];
        out[base + i] = fmaxf(v, 0.f);
    }
}

// ---------------- 3x3 offset conv (27 out channels), pad=1 -----------------
// One block per (16x16 spatial tile, batch). Streams C in chunks of 8.
__global__ void __launch_bounds__(256) conv_off_kernel(
    const float* __restrict__ in,    // g_out1 [B][CB][H][W]
    const float* __restrict__ w,     // [27][CB][3][3]
    const float* __restrict__ bias,  // [27]
    float* __restrict__ om)          // [B][27][H][W]
{
    const int bx = blockIdx.x;   // 0..3
    const int by = blockIdx.y;   // 0..3
    const int b  = blockIdx.z;
    const int tid = threadIdx.x;
    const int tx = tid & 15, ty = tid >> 4;

    __shared__ float s_in[8][18][18];
    __shared__ float s_w[8][9][27];

    float acc[27];
#pragma unroll
    for (int j = 0; j < 27; j++) acc[j] = 0.f;

    const int x0 = bx * 16, y0 = by * 16;
    const float* inb = in + (size_t)b * CB * HW;

    for (int c0 = 0; c0 < CB; c0 += 8) {
        for (int e = tid; e < 8 * 18 * 18; e += 256) {
            int c = e / 324;
            int r = (e / 18) % 18;
            int col = e % 18;
            int y = y0 + r - 1, x = x0 + col - 1;
            float v = 0.f;
            if (y >= 0 && y < H_ && x >= 0 && x < W_)
                v = inb[(size_t)(c0 + c) * HW + y * W_ + x];
            s_in[c][r][col] = v;
        }
        for (int e = tid; e < 8 * 9 * 27; e += 256) {
            int c = e / (9 * 27);
            int k = (e / 27) % 9;
            int j = e % 27;
            s_w[c][k][j] = w[((size_t)j * CB + c0 + c) * 9 + k];
        }
        __syncthreads();
#pragma unroll
        for (int c = 0; c < 8; c++) {
#pragma unroll
            for (int k = 0; k < 9; k++) {
                float v = s_in[c][ty + k / 3][tx + k % 3];
#pragma unroll
                for (int j = 0; j < 27; j++)
                    acc[j] += v * s_w[c][k][j];
            }
        }
        __syncthreads();
    }
    const int hw = (y0 + ty) * W_ + x0 + tx;
#pragma unroll
    for (int j = 0; j < 27; j++)
        om[((size_t)b * 27 + j) * HW + hw] = acc[j] + bias[j];
}

// ---------------- deformable bilinear sampling -----------------------------
// Thread per (b, k, pixel); loops channels. Writes [b][c][k][hw] so that the
// einsum becomes a K=2304 GEMM against w2 flat [o][c*9+k].
__global__ void deform_sample_kernel(const float* __restrict__ out1,
                                     const float* __restrict__ om,
                                     float* __restrict__ sampled)
{
    const int idx = blockIdx.x * blockDim.x + threadIdx.x;
    if (idx >= B_ * KOFF * HW) return;
    const int hw = idx % HW;
    const int k  = (idx / HW) % KOFF;
    const int b  = idx / (HW * KOFF);
    const int h = hw / W_, w = hw % W_;

    const float* omb = om + (size_t)b * 27 * HW;
    const float offx = omb[(size_t)k * HW + hw];
    const float offy = omb[(size_t)(KOFF + k) * HW + hw];
    const float mval = 1.f / (1.f + expf(-omb[(size_t)(18 + k) * HW + hw]));

    const float py = (float)(h + k / 3 - 1) + offy;
    const float px = (float)(w + k % 3 - 1) + offx;
    const float y0f = floorf(py), x0f = floorf(px);
    const int y0 = (int)y0f, x0 = (int)x0f;
    const float wy1 = py - y0f, wx1 = px - x0f;
    const float wy0 = 1.f - wy1, wx0 = 1.f - wx1;
    const int y1 = y0 + 1, x1 = x0 + 1;
    const bool vy0 = (y0 >= 0) && (y0 < H_), vy1 = (y1 >= 0) && (y1 < H_);
    const bool vx0 = (x0 >= 0) && (x0 < W_), vx1 = (x1 >= 0) && (x1 < W_);
    const int cy0 = min(max(y0, 0), H_ - 1), cy1 = min(max(y1, 0), H_ - 1);
    const int cx0 = min(max(x0, 0), W_ - 1), cx1 = min(max(x1, 0), W_ - 1);
    const int i00 = cy0 * W_ + cx0, i01 = cy0 * W_ + cx1;
    const int i10 = cy1 * W_ + cx0, i11 = cy1 * W_ + cx1;
    const float w00 = (vy0 && vx0) ? wy0 * wx0 * mval : 0.f;
    const float w01 = (vy0 && vx1) ? wy0 * wx1 * mval : 0.f;
    const float w10 = (vy1 && vx0) ? wy1 * wx0 * mval : 0.f;
    const float w11 = (vy1 && vx1) ? wy1 * wx1 * mval : 0.f;

    const float* base = out1 + (size_t)b * CB * HW;
    const size_t obase = (size_t)b * CB * KOFF * HW + (size_t)k * HW + hw;
#pragma unroll 4
    for (int c = 0; c < CB; c++) {
        const float* p = base + (size_t)c * HW;
        float v = w00 * p[i00] + w01 * p[i01] + w10 * p[i10] + w11 * p[i11];
        sampled[obase + (size_t)c * (KOFF * HW)] = v;
    }
}

// ---------------- host launcher --------------------------------------------
extern "C" void kernel_launch(void* const* d_in, const int* in_sizes, int n_in,
                              void* d_out, int out_size)
{
    const float* x     = (const float*)d_in[0];
    const float* w1    = (const float*)d_in[1];
    const float* gn1s  = (const float*)d_in[2];
    const float* gn1b  = (const float*)d_in[3];
    const float* w_off = (const float*)d_in[4];
    const float* b_off = (const float*)d_in[5];
    const float* w2    = (const float*)d_in[6];
    const float* gn2s  = (const float*)d_in[7];
    const float* gn2b  = (const float*)d_in[8];
    const float* w3    = (const float*)d_in[9];
    const float* gn3s  = (const float*)d_in[10];
    const float* gn3b  = (const float*)d_in[11];
    float* out = (float*)d_out;

    float *p_out1, *p_om, *p_samp, *p_out2, *p_out3;
    cudaGetSymbolAddress((void**)&p_out1, g_out1);
    cudaGetSymbolAddress((void**)&p_om,   g_om);
    cudaGetSymbolAddress((void**)&p_samp, g_samp);
    cudaGetSymbolAddress((void**)&p_out2, g_out2);
    cudaGetSymbolAddress((void**)&p_out3, g_out3);

    // 1) out1 = w1 @ x            (M=256, K=1024, N=4096, batch 4)
    sgemm_kernel<<<dim3(HW / 128, CB / 128, B_), 256>>>(
        w1, x, p_out1, CB, HW, CIN, (size_t)CIN * HW, (size_t)CB * HW);

    // 2) GN1 + ReLU (in place)
    gn_relu_kernel<<<B_ * 32, 256>>>(p_out1, gn1s, gn1b, CB, CB / 32);

    // 3) offset conv (27 channels, 3x3, pad 1) + bias
    conv_off_kernel<<<dim3(W_ / 16, H_ / 16, B_), 256>>>(p_out1, w_off, b_off, p_om);

    // 4) deformable bilinear sample * sigmoid(mask) -> [b][c*9+k][hw]
    deform_sample_kernel<<<(B_ * KOFF * HW + 255) / 256, 256>>>(p_out1, p_om, p_samp);

    // 5) out2 = w2_flat @ sampled (M=256, K=2304, N=4096, batch 4)
    sgemm_kernel<<<dim3(HW / 128, CB / 128, B_), 256>>>(
        w2, p_samp, p_out2, CB, HW, CB * KOFF,
        (size_t)CB * KOFF * HW, (size_t)CB * HW);

    // 6) GN2 + ReLU (in place)
    gn_relu_kernel<<<B_ * 32, 256>>>(p_out2, gn2s, gn2b, CB, CB / 32);

    // 7) out3 = w3 @ out2         (M=1024, K=256, N=4096, batch 4)
    sgemm_kernel<<<dim3(HW / 128, CIN / 128, B_), 256>>>(
        w3, p_out2, p_out3, CIN, HW, CB, (size_t)CB * HW, (size_t)CIN * HW);

    // 8) out = relu(GN3(out3) + x)
    gn_res_relu_kernel<<<B_ * 32, 512>>>(p_out3, x, gn3s, gn3b, out, CIN, CIN / 32);
}

// round 2
// speedup vs baseline: 1.7515x; 1.7515x over previous
#include <cuda_runtime.h>
#include <math.h>

#define B_   4
#define CIN  1024
#define CB   256
#define H_   64
#define W_   64
#define HW   (H_*W_)
#define KOFF 9

// ---------------- scratch (device globals; no runtime allocation) ----------
__device__ float g_out1[(size_t)B_*CB*HW];              // 16.7 MB
__device__ float g_om  [(size_t)B_*27*HW];              // 1.8 MB
__device__ float g_samp[(size_t)B_*CB*KOFF*HW];         // 151 MB
__device__ float g_out2[(size_t)B_*CB*HW];              // 16.7 MB
__device__ float g_out3[(size_t)B_*CIN*HW];             // 67 MB

__device__ __forceinline__ unsigned f2tf32(float f) {
    unsigned u;
    asm("cvt.rna.tf32.f32 %0, %1;" : "=r"(u) : "f"(f));
    return u;
}

// ---------------- batched TF32 tensor-core GEMM: C[b] = A @ B[b] -----------
// A: [M,K] row-major (shared over batch). B: [K,N]. C: [M,N].
// Requires M%128==0, N%128==0, K%16==0 (true for all call sites).
// CTA tile 128x128x16, 8 warps as 2(M)x4(N), warp tile 64x32, mma m16n8k8.
__global__ void __launch_bounds__(256) tf32_gemm_kernel(
    const float* __restrict__ A, const float* __restrict__ Bm,
    float* __restrict__ Cm, int M, int N, int K,
    size_t strideB, size_t strideC)
{
    __shared__ unsigned As[16][136];   // [k][m], pad 8 -> conflict-free frags
    __shared__ unsigned Bs[16][136];   // [k][n]

    const float* Bp = Bm + (size_t)blockIdx.z * strideB;
    float*       Cp = Cm + (size_t)blockIdx.z * strideC;
    const int bm = blockIdx.y * 128;
    const int bn = blockIdx.x * 128;

    const int tid  = threadIdx.x;
    const int lane = tid & 31;
    const int warp = tid >> 5;
    const int wm = (warp & 1) * 64;     // warp M offset
    const int wn = (warp >> 1) * 32;    // warp N offset
    const int grp = lane >> 2;          // 0..7
    const int tig = lane & 3;           // 0..3

    // global-load indexing
    const int arow = tid >> 1;          // 0..127
    const int acol = (tid & 1) * 8;     // 0 or 8
    const int brow = tid >> 5;          // 0..7
    const int bcol = (tid & 31) * 4;    // 0..124

    float acc[4][4][4];
#pragma unroll
    for (int mi = 0; mi < 4; mi++)
#pragma unroll
        for (int ni = 0; ni < 4; ni++)
#pragma unroll
            for (int i = 0; i < 4; i++) acc[mi][ni][i] = 0.f;

    const float* Aptr = A + (size_t)(bm + arow) * K;

    for (int k0 = 0; k0 < K; k0 += 16) {
        // global -> regs
        float4 av0 = *(const float4*)(Aptr + k0 + acol);
        float4 av1 = *(const float4*)(Aptr + k0 + acol + 4);
        float4 bv0 = *(const float4*)(Bp + (size_t)(k0 + brow)     * N + bn + bcol);
        float4 bv1 = *(const float4*)(Bp + (size_t)(k0 + brow + 8) * N + bn + bcol);

        __syncthreads();  // previous tile's compute done
        As[acol + 0][arow] = f2tf32(av0.x);
        As[acol + 1][arow] = f2tf32(av0.y);
        As[acol + 2][arow] = f2tf32(av0.z);
        As[acol + 3][arow] = f2tf32(av0.w);
        As[acol + 4][arow] = f2tf32(av1.x);
        As[acol + 5][arow] = f2tf32(av1.y);
        As[acol + 6][arow] = f2tf32(av1.z);
        As[acol + 7][arow] = f2tf32(av1.w);
        Bs[brow][bcol + 0] = f2tf32(bv0.x);
        Bs[brow][bcol + 1] = f2tf32(bv0.y);
        Bs[brow][bcol + 2] = f2tf32(bv0.z);
        Bs[brow][bcol + 3] = f2tf32(bv0.w);
        Bs[brow + 8][bcol + 0] = f2tf32(bv1.x);
        Bs[brow + 8][bcol + 1] = f2tf32(bv1.y);
        Bs[brow + 8][bcol + 2] = f2tf32(bv1.z);
        Bs[brow + 8][bcol + 3] = f2tf32(bv1.w);
        __syncthreads();

#pragma unroll
        for (int kk = 0; kk < 16; kk += 8) {
            unsigned a[4][4], b[4][2];
#pragma unroll
            for (int mi = 0; mi < 4; mi++) {
                const int m = wm + mi * 16 + grp;
                a[mi][0] = As[kk + tig    ][m];
                a[mi][1] = As[kk + tig    ][m + 8];
                a[mi][2] = As[kk + tig + 4][m];
                a[mi][3] = As[kk + tig + 4][m + 8];
            }
#pragma unroll
            for (int ni = 0; ni < 4; ni++) {
                const int n = wn + ni * 8 + grp;
                b[ni][0] = Bs[kk + tig    ][n];
                b[ni][1] = Bs[kk + tig + 4][n];
            }
#pragma unroll
            for (int mi = 0; mi < 4; mi++)
#pragma unroll
                for (int ni = 0; ni < 4; ni++) {
                    asm volatile(
                        "mma.sync.aligned.m16n8k8.row.col.f32.tf32.tf32.f32 "
                        "{%0,%1,%2,%3}, {%4,%5,%6,%7}, {%8,%9}, {%0,%1,%2,%3};\n"
                        : "+f"(acc[mi][ni][0]), "+f"(acc[mi][ni][1]),
                          "+f"(acc[mi][ni][2]), "+f"(acc[mi][ni][3])
                        : "r"(a[mi][0]), "r"(a[mi][1]), "r"(a[mi][2]), "r"(a[mi][3]),
                          "r"(b[ni][0]), "r"(b[ni][1]));
                }
        }
    }

    // epilogue
#pragma unroll
    for (int mi = 0; mi < 4; mi++) {
        const int row = bm + wm + mi * 16 + grp;
#pragma unroll
        for (int ni = 0; ni < 4; ni++) {
            const int col = bn + wn + ni * 8 + tig * 2;
            float2 v0 = make_float2(acc[mi][ni][0], acc[mi][ni][1]);
            float2 v1 = make_float2(acc[mi][ni][2], acc[mi][ni][3]);
            *(float2*)(Cp + (size_t)row * N + col)       = v0;
            *(float2*)(Cp + (size_t)(row + 8) * N + col) = v1;
        }
    }
}

// ---------------- block reduction helper -----------------------------------
__device__ __forceinline__ void block_reduce2(float& s, float& ss) {
#pragma unroll
    for (int o = 16; o > 0; o >>= 1) {
        s  += __shfl_down_sync(0xFFFFFFFFu, s,  o);
        ss += __shfl_down_sync(0xFFFFFFFFu, ss, o);
    }
    __shared__ float as_[32], ass_[32];
    int lane = threadIdx.x & 31, wid = threadIdx.x >> 5;
    if (lane == 0) { as_[wid] = s; ass_[wid] = ss; }
    __syncthreads();
    int nw = blockDim.x >> 5;
    if (wid == 0) {
        s  = (lane < nw) ? as_[lane]  : 0.f;
        ss = (lane < nw) ? ass_[lane] : 0.f;
#pragma unroll
        for (int o = 16; o > 0; o >>= 1) {
            s  += __shfl_down_sync(0xFFFFFFFFu, s,  o);
            ss += __shfl_down_sync(0xFFFFFFFFu, ss, o);
        }
    }
}

// ---------------- GroupNorm (+ReLU), in-place; one block per (b, group) ----
__global__ void gn_relu_kernel(float* __restrict__ data,
                               const float* __restrict__ scale,
                               const float* __restrict__ bias,
                               int C, int cpg)
{
    const int G  = C / cpg;
    const int b  = blockIdx.x / G;
    const int gi = blockIdx.x % G;
    float* p = data + ((size_t)b * C + (size_t)gi * cpg) * HW;
    const int n = cpg * HW;

    float s = 0.f, ss = 0.f;
    for (int i = threadIdx.x; i < n; i += blockDim.x) {
        float v = p[i]; s += v; ss += v * v;
    }
    block_reduce2(s, ss);
    __shared__ float sh_mean, sh_rstd;
    if (threadIdx.x == 0) {
        float mean = s / n;
        float var  = ss / n - mean * mean;
        sh_mean = mean;
        sh_rstd = rsqrtf(var + 1e-5f);
    }
    __syncthreads();
    const float mean = sh_mean, rstd = sh_rstd;
    for (int i = threadIdx.x; i < n; i += blockDim.x) {
        int c = gi * cpg + i / HW;
        float v = (p[i] - mean) * rstd * scale[c] + bias[c];
        p[i] = fmaxf(v, 0.f);
    }
}

// ---------------- GN3 + residual + ReLU -> output --------------------------
__global__ void gn_res_relu_kernel(const float* __restrict__ in,
                                   const float* __restrict__ xres,
                                   const float* __restrict__ scale,
                                   const float* __restrict__ bias,
                                   float* __restrict__ out,
                                   int C, int cpg)
{
    const int G  = C / cpg;
    const int b  = blockIdx.x / G;
    const int gi = blockIdx.x % G;
    const size_t base = ((size_t)b * C + (size_t)gi * cpg) * HW;
    const float* p = in + base;
    const int n = cpg * HW;

    float s = 0.f, ss = 0.f;
    for (int i = threadIdx.x; i < n; i += blockDim.x) {
        float v = p[i]; s += v; ss += v * v;
    }
    block_reduce2(s, ss);
    __shared__ float sh_mean, sh_rstd;
    if (threadIdx.x == 0) {
        float mean = s / n;
        float var  = ss / n - mean * mean;
        sh_mean = mean;
        sh_rstd = rsqrtf(var + 1e-5f);
    }
    __syncthreads();
    const float mean = sh_mean, rstd = sh_rstd;
    for (int i = threadIdx.x; i < n; i += blockDim.x) {
        int c = gi * cpg + i / HW;
        float v = (p[i] - mean) * rstd * scale[c] + bias[c] + xres[base + i];
        out[base + i] = fmaxf(v, 0.f);
    }
}

// ---------------- 3x3 offset conv (27 out channels), pad=1 -----------------
__global__ void __launch_bounds__(256) conv_off_kernel(
    const float* __restrict__ in,    // g_out1 [B][CB][H][W]
    const float* __restrict__ w,     // [27][CB][3][3]
    const float* __restrict__ bias,  // [27]
    float* __restrict__ om)          // [B][27][H][W]
{
    const int bx = blockIdx.x;   // 0..3
    const int by = blockIdx.y;   // 0..3
    const int b  = blockIdx.z;
    const int tid = threadIdx.x;
    const int tx = tid & 15, ty = tid >> 4;

    __shared__ float s_in[8][18][18];
    __shared__ float s_w[8][9][27];

    float acc[27];
#pragma unroll
    for (int j = 0; j < 27; j++) acc[j] = 0.f;

    const int x0 = bx * 16, y0 = by * 16;
    const float* inb = in + (size_t)b * CB * HW;

    for (int c0 = 0; c0 < CB; c0 += 8) {
        for (int e = tid; e < 8 * 18 * 18; e += 256) {
            int c = e / 324;
            int r = (e / 18) % 18;
            int col = e % 18;
            int y = y0 + r - 1, x = x0 + col - 1;
            float v = 0.f;
            if (y >= 0 && y < H_ && x >= 0 && x < W_)
                v = inb[(size_t)(c0 + c) * HW + y * W_ + x];
            s_in[c][r][col] = v;
        }
        for (int e = tid; e < 8 * 9 * 27; e += 256) {
            int c = e / (9 * 27);
            int k = (e / 27) % 9;
            int j = e % 27;
            s_w[c][k][j] = w[((size_t)j * CB + c0 + c) * 9 + k];
        }
        __syncthreads();
#pragma unroll
        for (int c = 0; c < 8; c++) {
#pragma unroll
            for (int k = 0; k < 9; k++) {
                float v = s_in[c][ty + k / 3][tx + k % 3];
#pragma unroll
                for (int j = 0; j < 27; j++)
                    acc[j] += v * s_w[c][k][j];
            }
        }
        __syncthreads();
    }
    const int hw = (y0 + ty) * W_ + x0 + tx;
#pragma unroll
    for (int j = 0; j < 27; j++)
        om[((size_t)b * 27 + j) * HW + hw] = acc[j] + bias[j];
}

// ---------------- deformable bilinear sampling -----------------------------
__global__ void deform_sample_kernel(const float* __restrict__ out1,
                                     const float* __restrict__ om,
                                     float* __restrict__ sampled)
{
    const int idx = blockIdx.x * blockDim.x + threadIdx.x;
    if (idx >= B_ * KOFF * HW) return;
    const int hw = idx % HW;
    const int k  = (idx / HW) % KOFF;
    const int b  = idx / (HW * KOFF);
    const int h = hw / W_, w = hw % W_;

    const float* omb = om + (size_t)b * 27 * HW;
    const float offx = omb[(size_t)k * HW + hw];
    const float offy = omb[(size_t)(KOFF + k) * HW + hw];
    const float mval = 1.f / (1.f + expf(-omb[(size_t)(18 + k) * HW + hw]));

    const float py = (float)(h + k / 3 - 1) + offy;
    const float px = (float)(w + k % 3 - 1) + offx;
    const float y0f = floorf(py), x0f = floorf(px);
    const int y0 = (int)y0f, x0 = (int)x0f;
    const float wy1 = py - y0f, wx1 = px - x0f;
    const float wy0 = 1.f - wy1, wx0 = 1.f - wx1;
    const int y1 = y0 + 1, x1 = x0 + 1;
    const bool vy0 = (y0 >= 0) && (y0 < H_), vy1 = (y1 >= 0) && (y1 < H_);
    const bool vx0 = (x0 >= 0) && (x0 < W_), vx1 = (x1 >= 0) && (x1 < W_);
    const int cy0 = min(max(y0, 0), H_ - 1), cy1 = min(max(y1, 0), H_ - 1);
    const int cx0 = min(max(x0, 0), W_ - 1), cx1 = min(max(x1, 0), W_ - 1);
    const int i00 = cy0 * W_ + cx0, i01 = cy0 * W_ + cx1;
    const int i10 = cy1 * W_ + cx0, i11 = cy1 * W_ + cx1;
    const float w00 = (vy0 && vx0) ? wy0 * wx0 * mval : 0.f;
    const float w01 = (vy0 && vx1) ? wy0 * wx1 * mval : 0.f;
    const float w10 = (vy1 && vx0) ? wy1 * wx0 * mval : 0.f;
    const float w11 = (vy1 && vx1) ? wy1 * wx1 * mval : 0.f;

    const float* base = out1 + (size_t)b * CB * HW;
    const size_t obase = (size_t)b * CB * KOFF * HW + (size_t)k * HW + hw;
#pragma unroll 4
    for (int c = 0; c < CB; c++) {
        const float* p = base + (size_t)c * HW;
        float v = w00 * p[i00] + w01 * p[i01] + w10 * p[i10] + w11 * p[i11];
        sampled[obase + (size_t)c * (KOFF * HW)] = v;
    }
}

// ---------------- host launcher --------------------------------------------
extern "C" void kernel_launch(void* const* d_in, const int* in_sizes, int n_in,
                              void* d_out, int out_size)
{
    const float* x     = (const float*)d_in[0];
    const float* w1    = (const float*)d_in[1];
    const float* gn1s  = (const float*)d_in[2];
    const float* gn1b  = (const float*)d_in[3];
    const float* w_off = (const float*)d_in[4];
    const float* b_off = (const float*)d_in[5];
    const float* w2    = (const float*)d_in[6];
    const float* gn2s  = (const float*)d_in[7];
    const float* gn2b  = (const float*)d_in[8];
    const float* w3    = (const float*)d_in[9];
    const float* gn3s  = (const float*)d_in[10];
    const float* gn3b  = (const float*)d_in[11];
    float* out = (float*)d_out;

    float *p_out1, *p_om, *p_samp, *p_out2, *p_out3;
    cudaGetSymbolAddress((void**)&p_out1, g_out1);
    cudaGetSymbolAddress((void**)&p_om,   g_om);
    cudaGetSymbolAddress((void**)&p_samp, g_samp);
    cudaGetSymbolAddress((void**)&p_out2, g_out2);
    cudaGetSymbolAddress((void**)&p_out3, g_out3);

    // 1) out1 = w1 @ x            (M=256, K=1024, N=4096, batch 4)
    tf32_gemm_kernel<<<dim3(HW / 128, CB / 128, B_), 256>>>(
        w1, x, p_out1, CB, HW, CIN, (size_t)CIN * HW, (size_t)CB * HW);

    // 2) GN1 + ReLU (in place)
    gn_relu_kernel<<<B_ * 32, 256>>>(p_out1, gn1s, gn1b, CB, CB / 32);

    // 3) offset conv (27 channels, 3x3, pad 1) + bias
    conv_off_kernel<<<dim3(W_ / 16, H_ / 16, B_), 256>>>(p_out1, w_off, b_off, p_om);

    // 4) deformable bilinear sample * sigmoid(mask) -> [b][c*9+k][hw]
    deform_sample_kernel<<<(B_ * KOFF * HW + 255) / 256, 256>>>(p_out1, p_om, p_samp);

    // 5) out2 = w2_flat @ sampled (M=256, K=2304, N=4096, batch 4)
    tf32_gemm_kernel<<<dim3(HW / 128, CB / 128, B_), 256>>>(
        w2, p_samp, p_out2, CB, HW, CB * KOFF,
        (size_t)CB * KOFF * HW, (size_t)CB * HW);

    // 6) GN2 + ReLU (in place)
    gn_relu_kernel<<<B_ * 32, 256>>>(p_out2, gn2s, gn2b, CB, CB / 32);

    // 7) out3 = w3 @ out2         (M=1024, K=256, N=4096, batch 4)
    tf32_gemm_kernel<<<dim3(HW / 128, CIN / 128, B_), 256>>>(
        w3, p_out2, p_out3, CIN, HW, CB, (size_t)CB * HW, (size_t)CIN * HW);

    // 8) out = relu(GN3(out3) + x)
    gn_res_relu_kernel<<<B_ * 32, 512>>>(p_out3, x, gn3s, gn3b, out, CIN, CIN / 32);
}

// round 3
// speedup vs baseline: 2.0516x; 1.1714x over previous
#include <cuda_runtime.h>
#include <math.h>

#define B_   4
#define CIN  1024
#define CB   256
#define H_   64
#define W_   64
#define HW   (H_*W_)
#define KOFF 9

// ---------------- scratch (device globals; no runtime allocation) ----------
__device__ float g_out1[(size_t)B_*CB*HW];              // 16.7 MB
__device__ float g_om  [(size_t)B_*27*HW];              // 1.8 MB
__device__ float g_samp[(size_t)B_*CB*KOFF*HW];         // 151 MB
__device__ float g_out2[(size_t)B_*CB*HW];              // 16.7 MB
__device__ float g_out3[(size_t)B_*CIN*HW];             // 67 MB

__device__ __forceinline__ unsigned f2tf32(float f) {
    unsigned u;
    asm("cvt.rna.tf32.f32 %0, %1;" : "=r"(u) : "f"(f));
    return u;
}

// ---------------- batched TF32 tensor-core GEMM: C[b] = A @ B[b] -----------
// A: [M,K] row-major (shared over batch). B: [K,N]. C: [M,N].
// Requires M%128==0, N%128==0, K%16==0 (true for all call sites).
// CTA tile 128x128x16, double-buffered smem, 8 warps as 2(M)x4(N),
// warp tile 64x32, mma m16n8k8.tf32.
__global__ void __launch_bounds__(256, 2) tf32_gemm_kernel(
    const float* __restrict__ A, const float* __restrict__ Bm,
    float* __restrict__ Cm, int M, int N, int K,
    size_t strideB, size_t strideC)
{
    __shared__ unsigned As[2][16][136];   // [stage][k][m], pad -> conflict-free
    __shared__ unsigned Bs[2][16][136];   // [stage][k][n]

    const float* Bp = Bm + (size_t)blockIdx.z * strideB;
    float*       Cp = Cm + (size_t)blockIdx.z * strideC;
    const int bm = blockIdx.y * 128;
    const int bn = blockIdx.x * 128;

    const int tid  = threadIdx.x;
    const int lane = tid & 31;
    const int warp = tid >> 5;
    const int wm = (warp & 1) * 64;     // warp M offset
    const int wn = (warp >> 1) * 32;    // warp N offset
    const int grp = lane >> 2;          // 0..7
    const int tig = lane & 3;           // 0..3

    // global-load indexing
    const int arow = tid >> 1;          // 0..127
    const int acol = (tid & 1) * 8;     // 0 or 8
    const int brow = tid >> 5;          // 0..7
    const int bcol = (tid & 31) * 4;    // 0..124

    float acc[4][4][4];
#pragma unroll
    for (int mi = 0; mi < 4; mi++)
#pragma unroll
        for (int ni = 0; ni < 4; ni++)
#pragma unroll
            for (int i = 0; i < 4; i++) acc[mi][ni][i] = 0.f;

    const float* Aptr = A + (size_t)(bm + arow) * K;

    float4 av0, av1, bv0, bv1;

    // prologue: load tile 0 -> regs -> smem stage 0
    av0 = *(const float4*)(Aptr + acol);
    av1 = *(const float4*)(Aptr + acol + 4);
    bv0 = *(const float4*)(Bp + (size_t)(brow)     * N + bn + bcol);
    bv1 = *(const float4*)(Bp + (size_t)(brow + 8) * N + bn + bcol);

    As[0][acol + 0][arow] = f2tf32(av0.x);
    As[0][acol + 1][arow] = f2tf32(av0.y);
    As[0][acol + 2][arow] = f2tf32(av0.z);
    As[0][acol + 3][arow] = f2tf32(av0.w);
    As[0][acol + 4][arow] = f2tf32(av1.x);
    As[0][acol + 5][arow] = f2tf32(av1.y);
    As[0][acol + 6][arow] = f2tf32(av1.z);
    As[0][acol + 7][arow] = f2tf32(av1.w);
    Bs[0][brow][bcol + 0] = f2tf32(bv0.x);
    Bs[0][brow][bcol + 1] = f2tf32(bv0.y);
    Bs[0][brow][bcol + 2] = f2tf32(bv0.z);
    Bs[0][brow][bcol + 3] = f2tf32(bv0.w);
    Bs[0][brow + 8][bcol + 0] = f2tf32(bv1.x);
    Bs[0][brow + 8][bcol + 1] = f2tf32(bv1.y);
    Bs[0][brow + 8][bcol + 2] = f2tf32(bv1.z);
    Bs[0][brow + 8][bcol + 3] = f2tf32(bv1.w);
    __syncthreads();

    int cur = 0;
    for (int k0 = 0; k0 < K; k0 += 16) {
        const bool has_next = (k0 + 16 < K);
        if (has_next) {
            av0 = *(const float4*)(Aptr + k0 + 16 + acol);
            av1 = *(const float4*)(Aptr + k0 + 16 + acol + 4);
            bv0 = *(const float4*)(Bp + (size_t)(k0 + 16 + brow)     * N + bn + bcol);
            bv1 = *(const float4*)(Bp + (size_t)(k0 + 16 + brow + 8) * N + bn + bcol);
        }

#pragma unroll
        for (int kk = 0; kk < 16; kk += 8) {
            unsigned a[4][4], b[4][2];
#pragma unroll
            for (int mi = 0; mi < 4; mi++) {
                const int m = wm + mi * 16 + grp;
                a[mi][0] = As[cur][kk + tig    ][m];
                a[mi][1] = As[cur][kk + tig    ][m + 8];
                a[mi][2] = As[cur][kk + tig + 4][m];
                a[mi][3] = As[cur][kk + tig + 4][m + 8];
            }
#pragma unroll
            for (int ni = 0; ni < 4; ni++) {
                const int n = wn + ni * 8 + grp;
                b[ni][0] = Bs[cur][kk + tig    ][n];
                b[ni][1] = Bs[cur][kk + tig + 4][n];
            }
#pragma unroll
            for (int mi = 0; mi < 4; mi++)
#pragma unroll
                for (int ni = 0; ni < 4; ni++) {
                    asm volatile(
                        "mma.sync.aligned.m16n8k8.row.col.f32.tf32.tf32.f32 "
                        "{%0,%1,%2,%3}, {%4,%5,%6,%7}, {%8,%9}, {%0,%1,%2,%3};\n"
                        : "+f"(acc[mi][ni][0]), "+f"(acc[mi][ni][1]),
                          "+f"(acc[mi][ni][2]), "+f"(acc[mi][ni][3])
                        : "r"(a[mi][0]), "r"(a[mi][1]), "r"(a[mi][2]), "r"(a[mi][3]),
                          "r"(b[ni][0]), "r"(b[ni][1]));
                }
        }

        if (has_next) {
            const int nxt = cur ^ 1;
            As[nxt][acol + 0][arow] = f2tf32(av0.x);
            As[nxt][acol + 1][arow] = f2tf32(av0.y);
            As[nxt][acol + 2][arow] = f2tf32(av0.z);
            As[nxt][acol + 3][arow] = f2tf32(av0.w);
            As[nxt][acol + 4][arow] = f2tf32(av1.x);
            As[nxt][acol + 5][arow] = f2tf32(av1.y);
            As[nxt][acol + 6][arow] = f2tf32(av1.z);
            As[nxt][acol + 7][arow] = f2tf32(av1.w);
            Bs[nxt][brow][bcol + 0] = f2tf32(bv0.x);
            Bs[nxt][brow][bcol + 1] = f2tf32(bv0.y);
            Bs[nxt][brow][bcol + 2] = f2tf32(bv0.z);
            Bs[nxt][brow][bcol + 3] = f2tf32(bv0.w);
            Bs[nxt][brow + 8][bcol + 0] = f2tf32(bv1.x);
            Bs[nxt][brow + 8][bcol + 1] = f2tf32(bv1.y);
            Bs[nxt][brow + 8][bcol + 2] = f2tf32(bv1.z);
            Bs[nxt][brow + 8][bcol + 3] = f2tf32(bv1.w);
            __syncthreads();
            cur = nxt;
        }
    }

    // epilogue
#pragma unroll
    for (int mi = 0; mi < 4; mi++) {
        const int row = bm + wm + mi * 16 + grp;
#pragma unroll
        for (int ni = 0; ni < 4; ni++) {
            const int col = bn + wn + ni * 8 + tig * 2;
            float2 v0 = make_float2(acc[mi][ni][0], acc[mi][ni][1]);
            float2 v1 = make_float2(acc[mi][ni][2], acc[mi][ni][3]);
            *(float2*)(Cp + (size_t)row * N + col)       = v0;
            *(float2*)(Cp + (size_t)(row + 8) * N + col) = v1;
        }
    }
}

// ---------------- block reduction helper -----------------------------------
__device__ __forceinline__ void block_reduce2(float& s, float& ss) {
#pragma unroll
    for (int o = 16; o > 0; o >>= 1) {
        s  += __shfl_down_sync(0xFFFFFFFFu, s,  o);
        ss += __shfl_down_sync(0xFFFFFFFFu, ss, o);
    }
    __shared__ float as_[32], ass_[32];
    int lane = threadIdx.x & 31, wid = threadIdx.x >> 5;
    if (lane == 0) { as_[wid] = s; ass_[wid] = ss; }
    __syncthreads();
    int nw = blockDim.x >> 5;
    if (wid == 0) {
        s  = (lane < nw) ? as_[lane]  : 0.f;
        ss = (lane < nw) ? ass_[lane] : 0.f;
#pragma unroll
        for (int o = 16; o > 0; o >>= 1) {
            s  += __shfl_down_sync(0xFFFFFFFFu, s,  o);
            ss += __shfl_down_sync(0xFFFFFFFFu, ss, o);
        }
    }
}

// ---------------- GroupNorm (+ReLU), in-place; one block per (b, group) ----
// n = cpg*HW is a multiple of 4 -> float4 paths.
__global__ void gn_relu_kernel(float* __restrict__ data,
                               const float* __restrict__ scale,
                               const float* __restrict__ bias,
                               int C, int cpg)
{
    const int G  = C / cpg;
    const int b  = blockIdx.x / G;
    const int gi = blockIdx.x % G;
    float* p = data + ((size_t)b * C + (size_t)gi * cpg) * HW;
    const int n4 = (cpg * HW) >> 2;

    float s = 0.f, ss = 0.f;
    for (int i = threadIdx.x; i < n4; i += blockDim.x) {
        float4 v = ((const float4*)p)[i];
        s  += v.x + v.y + v.z + v.w;
        ss += v.x * v.x + v.y * v.y + v.z * v.z + v.w * v.w;
    }
    block_reduce2(s, ss);
    __shared__ float sh_mean, sh_rstd;
    if (threadIdx.x == 0) {
        const float n = (float)(cpg * HW);
        float mean = s / n;
        float var  = ss / n - mean * mean;
        sh_mean = mean;
        sh_rstd = rsqrtf(var + 1e-5f);
    }
    __syncthreads();
    const float mean = sh_mean, rstd = sh_rstd;
    for (int i = threadIdx.x; i < n4; i += blockDim.x) {
        int c = gi * cpg + (i * 4) / HW;
        const float a = rstd * scale[c];
        const float d = bias[c] - mean * a;
        float4 v = ((const float4*)p)[i];
        v.x = fmaxf(v.x * a + d, 0.f);
        v.y = fmaxf(v.y * a + d, 0.f);
        v.z = fmaxf(v.z * a + d, 0.f);
        v.w = fmaxf(v.w * a + d, 0.f);
        ((float4*)p)[i] = v;
    }
}

// ---------------- GN3 + residual + ReLU -> output --------------------------
__global__ void gn_res_relu_kernel(const float* __restrict__ in,
                                   const float* __restrict__ xres,
                                   const float* __restrict__ scale,
                                   const float* __restrict__ bias,
                                   float* __restrict__ out,
                                   int C, int cpg)
{
    const int G  = C / cpg;
    const int b  = blockIdx.x / G;
    const int gi = blockIdx.x % G;
    const size_t base = ((size_t)b * C + (size_t)gi * cpg) * HW;
    const float* p = in + base;
    const float* r = xres + base;
    float* o = out + base;
    const int n4 = (cpg * HW) >> 2;

    float s = 0.f, ss = 0.f;
    for (int i = threadIdx.x; i < n4; i += blockDim.x) {
        float4 v = ((const float4*)p)[i];
        s  += v.x + v.y + v.z + v.w;
        ss += v.x * v.x + v.y * v.y + v.z * v.z + v.w * v.w;
    }
    block_reduce2(s, ss);
    __shared__ float sh_mean, sh_rstd;
    if (threadIdx.x == 0) {
        const float n = (float)(cpg * HW);
        float mean = s / n;
        float var  = ss / n - mean * mean;
        sh_mean = mean;
        sh_rstd = rsqrtf(var + 1e-5f);
    }
    __syncthreads();
    const float mean = sh_mean, rstd = sh_rstd;
    for (int i = threadIdx.x; i < n4; i += blockDim.x) {
        int c = gi * cpg + (i * 4) / HW;
        const float a = rstd * scale[c];
        const float d = bias[c] - mean * a;
        float4 v = ((const float4*)p)[i];
        float4 rr = ((const float4*)r)[i];
        v.x = fmaxf(v.x * a + d + rr.x, 0.f);
        v.y = fmaxf(v.y * a + d + rr.y, 0.f);
        v.z = fmaxf(v.z * a + d + rr.z, 0.f);
        v.w = fmaxf(v.w * a + d + rr.w, 0.f);
        ((float4*)o)[i] = v;
    }
}

// ---------------- 3x3 offset conv (27 out channels), pad=1 -----------------
__global__ void __launch_bounds__(256) conv_off_kernel(
    const float* __restrict__ in,    // g_out1 [B][CB][H][W]
    const float* __restrict__ w,     // [27][CB][3][3]
    const float* __restrict__ bias,  // [27]
    float* __restrict__ om)          // [B][27][H][W]
{
    const int bx = blockIdx.x;   // 0..3
    const int by = blockIdx.y;   // 0..3
    const int b  = blockIdx.z;
    const int tid = threadIdx.x;
    const int tx = tid & 15, ty = tid >> 4;

    __shared__ float s_in[8][18][18];
    __shared__ float s_w[8][9][27];

    float acc[27];
#pragma unroll
    for (int j = 0; j < 27; j++) acc[j] = 0.f;

    const int x0 = bx * 16, y0 = by * 16;
    const float* inb = in + (size_t)b * CB * HW;

    for (int c0 = 0; c0 < CB; c0 += 8) {
        for (int e = tid; e < 8 * 18 * 18; e += 256) {
            int c = e / 324;
            int r = (e / 18) % 18;
            int col = e % 18;
            int y = y0 + r - 1, x = x0 + col - 1;
            float v = 0.f;
            if (y >= 0 && y < H_ && x >= 0 && x < W_)
                v = inb[(size_t)(c0 + c) * HW + y * W_ + x];
            s_in[c][r][col] = v;
        }
        for (int e = tid; e < 8 * 9 * 27; e += 256) {
            int c = e / (9 * 27);
            int k = (e / 27) % 9;
            int j = e % 27;
            s_w[c][k][j] = w[((size_t)j * CB + c0 + c) * 9 + k];
        }
        __syncthreads();
#pragma unroll
        for (int c = 0; c < 8; c++) {
#pragma unroll
            for (int k = 0; k < 9; k++) {
                float v = s_in[c][ty + k / 3][tx + k % 3];
#pragma unroll
                for (int j = 0; j < 27; j++)
                    acc[j] += v * s_w[c][k][j];
            }
        }
        __syncthreads();
    }
    const int hw = (y0 + ty) * W_ + x0 + tx;
#pragma unroll
    for (int j = 0; j < 27; j++)
        om[((size_t)b * 27 + j) * HW + hw] = acc[j] + bias[j];
}

// ---------------- deformable bilinear sampling -----------------------------
__global__ void deform_sample_kernel(const float* __restrict__ out1,
                                     const float* __restrict__ om,
                                     float* __restrict__ sampled)
{
    const int idx = blockIdx.x * blockDim.x + threadIdx.x;
    if (idx >= B_ * KOFF * HW) return;
    const int hw = idx % HW;
    const int k  = (idx / HW) % KOFF;
    const int b  = idx / (HW * KOFF);
    const int h = hw / W_, w = hw % W_;

    const float* omb = om + (size_t)b * 27 * HW;
    const float offx = omb[(size_t)k * HW + hw];
    const float offy = omb[(size_t)(KOFF + k) * HW + hw];
    const float mval = 1.f / (1.f + expf(-omb[(size_t)(18 + k) * HW + hw]));

    const float py = (float)(h + k / 3 - 1) + offy;
    const float px = (float)(w + k % 3 - 1) + offx;
    const float y0f = floorf(py), x0f = floorf(px);
    const int y0 = (int)y0f, x0 = (int)x0f;
    const float wy1 = py - y0f, wx1 = px - x0f;
    const float wy0 = 1.f - wy1, wx0 = 1.f - wx1;
    const int y1 = y0 + 1, x1 = x0 + 1;
    const bool vy0 = (y0 >= 0) && (y0 < H_), vy1 = (y1 >= 0) && (y1 < H_);
    const bool vx0 = (x0 >= 0) && (x0 < W_), vx1 = (x1 >= 0) && (x1 < W_);
    const int cy0 = min(max(y0, 0), H_ - 1), cy1 = min(max(y1, 0), H_ - 1);
    const int cx0 = min(max(x0, 0), W_ - 1), cx1 = min(max(x1, 0), W_ - 1);
    const int i00 = cy0 * W_ + cx0, i01 = cy0 * W_ + cx1;
    const int i10 = cy1 * W_ + cx0, i11 = cy1 * W_ + cx1;
    const float w00 = (vy0 && vx0) ? wy0 * wx0 * mval : 0.f;
    const float w01 = (vy0 && vx1) ? wy0 * wx1 * mval : 0.f;
    const float w10 = (vy1 && vx0) ? wy1 * wx0 * mval : 0.f;
    const float w11 = (vy1 && vx1) ? wy1 * wx1 * mval : 0.f;

    const float* base = out1 + (size_t)b * CB * HW;
    const size_t obase = (size_t)b * CB * KOFF * HW + (size_t)k * HW + hw;
#pragma unroll 4
    for (int c = 0; c < CB; c++) {
        const float* p = base + (size_t)c * HW;
        float v = w00 * p[i00] + w01 * p[i01] + w10 * p[i10] + w11 * p[i11];
        sampled[obase + (size_t)c * (KOFF * HW)] = v;
    }
}

// ---------------- host launcher --------------------------------------------
extern "C" void kernel_launch(void* const* d_in, const int* in_sizes, int n_in,
                              void* d_out, int out_size)
{
    const float* x     = (const float*)d_in[0];
    const float* w1    = (const float*)d_in[1];
    const float* gn1s  = (const float*)d_in[2];
    const float* gn1b  = (const float*)d_in[3];
    const float* w_off = (const float*)d_in[4];
    const float* b_off = (const float*)d_in[5];
    const float* w2    = (const float*)d_in[6];
    const float* gn2s  = (const float*)d_in[7];
    const float* gn2b  = (const float*)d_in[8];
    const float* w3    = (const float*)d_in[9];
    const float* gn3s  = (const float*)d_in[10];
    const float* gn3b  = (const float*)d_in[11];
    float* out = (float*)d_out;

    float *p_out1, *p_om, *p_samp, *p_out2, *p_out3;
    cudaGetSymbolAddress((void**)&p_out1, g_out1);
    cudaGetSymbolAddress((void**)&p_om,   g_om);
    cudaGetSymbolAddress((void**)&p_samp, g_samp);
    cudaGetSymbolAddress((void**)&p_out2, g_out2);
    cudaGetSymbolAddress((void**)&p_out3, g_out3);

    // 1) out1 = w1 @ x            (M=256, K=1024, N=4096, batch 4)
    tf32_gemm_kernel<<<dim3(HW / 128, CB / 128, B_), 256>>>(
        w1, x, p_out1, CB, HW, CIN, (size_t)CIN * HW, (size_t)CB * HW);

    // 2) GN1 + ReLU (in place)
    gn_relu_kernel<<<B_ * 32, 256>>>(p_out1, gn1s, gn1b, CB, CB / 32);

    // 3) offset conv (27 channels, 3x3, pad 1) + bias
    conv_off_kernel<<<dim3(W_ / 16, H_ / 16, B_), 256>>>(p_out1, w_off, b_off, p_om);

    // 4) deformable bilinear sample * sigmoid(mask) -> [b][c*9+k][hw]
    deform_sample_kernel<<<(B_ * KOFF * HW + 255) / 256, 256>>>(p_out1, p_om, p_samp);

    // 5) out2 = w2_flat @ sampled (M=256, K=2304, N=4096, batch 4)
    tf32_gemm_kernel<<<dim3(HW / 128, CB / 128, B_), 256>>>(
        w2, p_samp, p_out2, CB, HW, CB * KOFF,
        (size_t)CB * KOFF * HW, (size_t)CB * HW);

    // 6) GN2 + ReLU (in place)
    gn_relu_kernel<<<B_ * 32, 256>>>(p_out2, gn2s, gn2b, CB, CB / 32);

    // 7) out3 = w3 @ out2         (M=1024, K=256, N=4096, batch 4)
    tf32_gemm_kernel<<<dim3(HW / 128, CIN / 128, B_), 256>>>(
        w3, p_out2, p_out3, CIN, HW, CB, (size_t)CB * HW, (size_t)CIN * HW);

    // 8) out = relu(GN3(out3) + x)
    gn_res_relu_kernel<<<B_ * 32, 512>>>(p_out3, x, gn3s, gn3b, out, CIN, CIN / 32);
}

// round 4
// speedup vs baseline: 2.2369x; 1.0903x over previous
#include <cuda_runtime.h>
#include <math.h>

#define B_   4
#define CIN  1024
#define CB   256
#define H_   64
#define W_   64
#define HW   (H_*W_)
#define KOFF 9

// ---------------- scratch (device globals; no runtime allocation) ----------
__device__ float g_out1[(size_t)B_*CB*HW];              // 16.7 MB
__device__ float g_om  [(size_t)B_*27*HW];              // 1.8 MB
__device__ float g_samp[(size_t)B_*CB*KOFF*HW];         // 151 MB
__device__ float g_out2[(size_t)B_*CB*HW];              // 16.7 MB
__device__ float g_out3[(size_t)B_*CIN*HW];             // 67 MB (also: rounded-x before GEMM3)
__device__ float g_at1[(size_t)CIN*CB];                 // w1^T  [1024][256]
__device__ float g_at2[(size_t)CB*KOFF*CB];             // w2^T  [2304][256]
__device__ float g_at3[(size_t)CB*CIN];                 // w3^T  [256][1024]

__device__ __forceinline__ unsigned f2tf32(float f) {
    unsigned u;
    asm("cvt.rna.tf32.f32 %0, %1;" : "=r"(u) : "f"(f));
    return u;
}
__device__ __forceinline__ float round_tf32(float f) {
    return __uint_as_float(f2tf32(f));
}

__device__ __forceinline__ void cp_async16(void* smem_dst, const void* gsrc) {
    unsigned s = (unsigned)__cvta_generic_to_shared(smem_dst);
    asm volatile("cp.async.cg.shared.global [%0], [%1], 16;\n" :: "r"(s), "l"(gsrc));
}
__device__ __forceinline__ void cp_commit() {
    asm volatile("cp.async.commit_group;\n");
}
template <int N>
__device__ __forceinline__ void cp_wait() {
    asm volatile("cp.async.wait_group %0;\n" :: "n"(N));
}

// ---------------- batched TF32 tensor-core GEMM: C[b] = A^T-form @ B[b] ----
// AT: [K,M] row-major (pre-transposed, pre-rounded tf32 bits, shared over batch).
// B:  [K,N] row-major (pre-rounded tf32 bits). C: [M,N].
// Requires M%128==0, N%128==0, K%8==0, K/8>=3.
// CTA tile 128x128, 4-stage cp.async pipeline with K=8 stages.
// 8 warps as 2(M)x4(N), warp tile 64x32, mma m16n8k8.tf32.
__global__ void __launch_bounds__(256, 2) tf32_gemm_kernel(
    const float* __restrict__ AT, const float* __restrict__ Bm,
    float* __restrict__ Cm, int M, int N, int K,
    size_t strideB, size_t strideC)
{
    __shared__ float As[4][8][136];   // [stage][k][m], pad 8 -> conflict-free
    __shared__ float Bs[4][8][136];   // [stage][k][n]

    const float* Bp = Bm + (size_t)blockIdx.z * strideB;
    float*       Cp = Cm + (size_t)blockIdx.z * strideC;
    const int bm = blockIdx.y * 128;
    const int bn = blockIdx.x * 128;

    const int tid  = threadIdx.x;
    const int lane = tid & 31;
    const int warp = tid >> 5;
    const int wm = (warp & 1) * 64;     // warp M offset
    const int wn = (warp >> 1) * 32;    // warp N offset
    const int grp = lane >> 2;          // 0..7
    const int tig = lane & 3;           // 0..3

    // stage-load indexing (identical shape for A^T and B)
    const int lrow = tid >> 5;          // k within stage: 0..7
    const int lcol = (tid & 31) * 4;    // 0..124

    float acc[4][4][4];
#pragma unroll
    for (int mi = 0; mi < 4; mi++)
#pragma unroll
        for (int ni = 0; ni < 4; ni++)
#pragma unroll
            for (int i = 0; i < 4; i++) acc[mi][ni][i] = 0.f;

    const int nstage = K >> 3;

    // prologue: issue 3 stages
#pragma unroll
    for (int s = 0; s < 3; s++) {
        const int k = s * 8 + lrow;
        cp_async16(&As[s][lrow][lcol], AT + (size_t)k * M + bm + lcol);
        cp_async16(&Bs[s][lrow][lcol], Bp + (size_t)k * N + bn + lcol);
        cp_commit();
    }

    int cur = 0;
    for (int ks = 0; ks < nstage; ks++) {
        cp_wait<2>();
        __syncthreads();

        unsigned a[4][4], b[4][2];
#pragma unroll
        for (int mi = 0; mi < 4; mi++) {
            const int m = wm + mi * 16 + grp;
            a[mi][0] = __float_as_uint(As[cur][tig    ][m]);
            a[mi][1] = __float_as_uint(As[cur][tig    ][m + 8]);
            a[mi][2] = __float_as_uint(As[cur][tig + 4][m]);
            a[mi][3] = __float_as_uint(As[cur][tig + 4][m + 8]);
        }
#pragma unroll
        for (int ni = 0; ni < 4; ni++) {
            const int n = wn + ni * 8 + grp;
            b[ni][0] = __float_as_uint(Bs[cur][tig    ][n]);
            b[ni][1] = __float_as_uint(Bs[cur][tig + 4][n]);
        }
#pragma unroll
        for (int mi = 0; mi < 4; mi++)
#pragma unroll
            for (int ni = 0; ni < 4; ni++) {
                asm volatile(
                    "mma.sync.aligned.m16n8k8.row.col.f32.tf32.tf32.f32 "
                    "{%0,%1,%2,%3}, {%4,%5,%6,%7}, {%8,%9}, {%0,%1,%2,%3};\n"
                    : "+f"(acc[mi][ni][0]), "+f"(acc[mi][ni][1]),
                      "+f"(acc[mi][ni][2]), "+f"(acc[mi][ni][3])
                    : "r"(a[mi][0]), "r"(a[mi][1]), "r"(a[mi][2]), "r"(a[mi][3]),
                      "r"(b[ni][0]), "r"(b[ni][1]));
            }

        if (ks + 3 < nstage) {
            const int buf = (cur + 3) & 3;
            const int k = (ks + 3) * 8 + lrow;
            cp_async16(&As[buf][lrow][lcol], AT + (size_t)k * M + bm + lcol);
            cp_async16(&Bs[buf][lrow][lcol], Bp + (size_t)k * N + bn + lcol);
        }
        cp_commit();
        cur = (cur + 1) & 3;
    }

    // epilogue
#pragma unroll
    for (int mi = 0; mi < 4; mi++) {
        const int row = bm + wm + mi * 16 + grp;
#pragma unroll
        for (int ni = 0; ni < 4; ni++) {
            const int col = bn + wn + ni * 8 + tig * 2;
            float2 v0 = make_float2(acc[mi][ni][0], acc[mi][ni][1]);
            float2 v1 = make_float2(acc[mi][ni][2], acc[mi][ni][3]);
            *(float2*)(Cp + (size_t)row * N + col)       = v0;
            *(float2*)(Cp + (size_t)(row + 8) * N + col) = v1;
        }
    }
}

// ---------------- transpose + tf32-round: A[M][K] -> AT[K][M] --------------
__global__ void transpose_round_kernel(const float* __restrict__ A,
                                       float* __restrict__ AT, int M, int K)
{
    __shared__ float t[32][33];
    const int kx = blockIdx.x * 32;
    const int my = blockIdx.y * 32;
    const int tx = threadIdx.x, ty = threadIdx.y;
    // read A[my+ty..][kx+tx]
#pragma unroll
    for (int i = 0; i < 32; i += 8)
        t[ty + i][tx] = A[(size_t)(my + ty + i) * K + kx + tx];
    __syncthreads();
#pragma unroll
    for (int i = 0; i < 32; i += 8)
        AT[(size_t)(kx + ty + i) * M + my + tx] = round_tf32(t[tx][ty + i]);
}

// ---------------- tf32 round-copy (for x -> GEMM1 B) -----------------------
__global__ void round_copy_kernel(const float* __restrict__ in,
                                  float* __restrict__ out, int n4)
{
    const int i = blockIdx.x * blockDim.x + threadIdx.x;
    if (i >= n4) return;
    float4 v = ((const float4*)in)[i];
    v.x = round_tf32(v.x); v.y = round_tf32(v.y);
    v.z = round_tf32(v.z); v.w = round_tf32(v.w);
    ((float4*)out)[i] = v;
}

// ---------------- block reduction helper -----------------------------------
__device__ __forceinline__ void block_reduce2(float& s, float& ss) {
#pragma unroll
    for (int o = 16; o > 0; o >>= 1) {
        s  += __shfl_down_sync(0xFFFFFFFFu, s,  o);
        ss += __shfl_down_sync(0xFFFFFFFFu, ss, o);
    }
    __shared__ float as_[32], ass_[32];
    int lane = threadIdx.x & 31, wid = threadIdx.x >> 5;
    if (lane == 0) { as_[wid] = s; ass_[wid] = ss; }
    __syncthreads();
    int nw = blockDim.x >> 5;
    if (wid == 0) {
        s  = (lane < nw) ? as_[lane]  : 0.f;
        ss = (lane < nw) ? ass_[lane] : 0.f;
#pragma unroll
        for (int o = 16; o > 0; o >>= 1) {
            s  += __shfl_down_sync(0xFFFFFFFFu, s,  o);
            ss += __shfl_down_sync(0xFFFFFFFFu, ss, o);
        }
    }
}

// ---------------- GroupNorm (+ReLU), in-place; one block per (b, group) ----
// ROUND: emit tf32-rounded bits (when output feeds a GEMM B operand).
template <bool ROUND>
__global__ void gn_relu_kernel(float* __restrict__ data,
                               const float* __restrict__ scale,
                               const float* __restrict__ bias,
                               int C, int cpg)
{
    const int G  = C / cpg;
    const int b  = blockIdx.x / G;
    const int gi = blockIdx.x % G;
    float* p = data + ((size_t)b * C + (size_t)gi * cpg) * HW;
    const int n4 = (cpg * HW) >> 2;

    float s = 0.f, ss = 0.f;
    for (int i = threadIdx.x; i < n4; i += blockDim.x) {
        float4 v = ((const float4*)p)[i];
        s  += v.x + v.y + v.z + v.w;
        ss += v.x * v.x + v.y * v.y + v.z * v.z + v.w * v.w;
    }
    block_reduce2(s, ss);
    __shared__ float sh_mean, sh_rstd;
    if (threadIdx.x == 0) {
        const float n = (float)(cpg * HW);
        float mean = s / n;
        float var  = ss / n - mean * mean;
        sh_mean = mean;
        sh_rstd = rsqrtf(var + 1e-5f);
    }
    __syncthreads();
    const float mean = sh_mean, rstd = sh_rstd;
    for (int i = threadIdx.x; i < n4; i += blockDim.x) {
        int c = gi * cpg + (i * 4) / HW;
        const float a = rstd * scale[c];
        const float d = bias[c] - mean * a;
        float4 v = ((const float4*)p)[i];
        v.x = fmaxf(v.x * a + d, 0.f);
        v.y = fmaxf(v.y * a + d, 0.f);
        v.z = fmaxf(v.z * a + d, 0.f);
        v.w = fmaxf(v.w * a + d, 0.f);
        if (ROUND) {
            v.x = round_tf32(v.x); v.y = round_tf32(v.y);
            v.z = round_tf32(v.z); v.w = round_tf32(v.w);
        }
        ((float4*)p)[i] = v;
    }
}

// ---------------- GN3 + residual + ReLU -> output --------------------------
__global__ void gn_res_relu_kernel(const float* __restrict__ in,
                                   const float* __restrict__ xres,
                                   const float* __restrict__ scale,
                                   const float* __restrict__ bias,
                                   float* __restrict__ out,
                                   int C, int cpg)
{
    const int G  = C / cpg;
    const int b  = blockIdx.x / G;
    const int gi = blockIdx.x % G;
    const size_t base = ((size_t)b * C + (size_t)gi * cpg) * HW;
    const float* p = in + base;
    const float* r = xres + base;
    float* o = out + base;
    const int n4 = (cpg * HW) >> 2;

    float s = 0.f, ss = 0.f;
    for (int i = threadIdx.x; i < n4; i += blockDim.x) {
        float4 v = ((const float4*)p)[i];
        s  += v.x + v.y + v.z + v.w;
        ss += v.x * v.x + v.y * v.y + v.z * v.z + v.w * v.w;
    }
    block_reduce2(s, ss);
    __shared__ float sh_mean, sh_rstd;
    if (threadIdx.x == 0) {
        const float n = (float)(cpg * HW);
        float mean = s / n;
        float var  = ss / n - mean * mean;
        sh_mean = mean;
        sh_rstd = rsqrtf(var + 1e-5f);
    }
    __syncthreads();
    const float mean = sh_mean, rstd = sh_rstd;
    for (int i = threadIdx.x; i < n4; i += blockDim.x) {
        int c = gi * cpg + (i * 4) / HW;
        const float a = rstd * scale[c];
        const float d = bias[c] - mean * a;
        float4 v = ((const float4*)p)[i];
        float4 rr = ((const float4*)r)[i];
        v.x = fmaxf(v.x * a + d + rr.x, 0.f);
        v.y = fmaxf(v.y * a + d + rr.y, 0.f);
        v.z = fmaxf(v.z * a + d + rr.z, 0.f);
        v.w = fmaxf(v.w * a + d + rr.w, 0.f);
        ((float4*)o)[i] = v;
    }
}

// ---------------- 3x3 offset conv (27 out channels), pad=1 -----------------
__global__ void __launch_bounds__(256) conv_off_kernel(
    const float* __restrict__ in,    // g_out1 [B][CB][H][W]
    const float* __restrict__ w,     // [27][CB][3][3]
    const float* __restrict__ bias,  // [27]
    float* __restrict__ om)          // [B][27][H][W]
{
    const int bx = blockIdx.x;   // 0..3
    const int by = blockIdx.y;   // 0..3
    const int b  = blockIdx.z;
    const int tid = threadIdx.x;
    const int tx = tid & 15, ty = tid >> 4;

    __shared__ float s_in[8][18][18];
    __shared__ float s_w[8][9][27];

    float acc[27];
#pragma unroll
    for (int j = 0; j < 27; j++) acc[j] = 0.f;

    const int x0 = bx * 16, y0 = by * 16;
    const float* inb = in + (size_t)b * CB * HW;

    for (int c0 = 0; c0 < CB; c0 += 8) {
        for (int e = tid; e < 8 * 18 * 18; e += 256) {
            int c = e / 324;
            int r = (e / 18) % 18;
            int col = e % 18;
            int y = y0 + r - 1, x = x0 + col - 1;
            float v = 0.f;
            if (y >= 0 && y < H_ && x >= 0 && x < W_)
                v = inb[(size_t)(c0 + c) * HW + y * W_ + x];
            s_in[c][r][col] = v;
        }
        for (int e = tid; e < 8 * 9 * 27; e += 256) {
            int c = e / (9 * 27);
            int k = (e / 27) % 9;
            int j = e % 27;
            s_w[c][k][j] = w[((size_t)j * CB + c0 + c) * 9 + k];
        }
        __syncthreads();
#pragma unroll
        for (int c = 0; c < 8; c++) {
#pragma unroll
            for (int k = 0; k < 9; k++) {
                float v = s_in[c][ty + k / 3][tx + k % 3];
#pragma unroll
                for (int j = 0; j < 27; j++)
                    acc[j] += v * s_w[c][k][j];
            }
        }
        __syncthreads();
    }
    const int hw = (y0 + ty) * W_ + x0 + tx;
#pragma unroll
    for (int j = 0; j < 27; j++)
        om[((size_t)b * 27 + j) * HW + hw] = acc[j] + bias[j];
}

// ---------------- deformable bilinear sampling (emits tf32-rounded) --------
__global__ void deform_sample_kernel(const float* __restrict__ out1,
                                     const float* __restrict__ om,
                                     float* __restrict__ sampled)
{
    const int idx = blockIdx.x * blockDim.x + threadIdx.x;
    if (idx >= B_ * KOFF * HW) return;
    const int hw = idx % HW;
    const int k  = (idx / HW) % KOFF;
    const int b  = idx / (HW * KOFF);
    const int h = hw / W_, w = hw % W_;

    const float* omb = om + (size_t)b * 27 * HW;
    const float offx = omb[(size_t)k * HW + hw];
    const float offy = omb[(size_t)(KOFF + k) * HW + hw];
    const float mval = 1.f / (1.f + expf(-omb[(size_t)(18 + k) * HW + hw]));

    const float py = (float)(h + k / 3 - 1) + offy;
    const float px = (float)(w + k % 3 - 1) + offx;
    const float y0f = floorf(py), x0f = floorf(px);
    const int y0 = (int)y0f, x0 = (int)x0f;
    const float wy1 = py - y0f, wx1 = px - x0f;
    const float wy0 = 1.f - wy1, wx0 = 1.f - wx1;
    const int y1 = y0 + 1, x1 = x0 + 1;
    const bool vy0 = (y0 >= 0) && (y0 < H_), vy1 = (y1 >= 0) && (y1 < H_);
    const bool vx0 = (x0 >= 0) && (x0 < W_), vx1 = (x1 >= 0) && (x1 < W_);
    const int cy0 = min(max(y0, 0), H_ - 1), cy1 = min(max(y1, 0), H_ - 1);
    const int cx0 = min(max(x0, 0), W_ - 1), cx1 = min(max(x1, 0), W_ - 1);
    const int i00 = cy0 * W_ + cx0, i01 = cy0 * W_ + cx1;
    const int i10 = cy1 * W_ + cx0, i11 = cy1 * W_ + cx1;
    const float w00 = (vy0 && vx0) ? wy0 * wx0 * mval : 0.f;
    const float w01 = (vy0 && vx1) ? wy0 * wx1 * mval : 0.f;
    const float w10 = (vy1 && vx0) ? wy1 * wx0 * mval : 0.f;
    const float w11 = (vy1 && vx1) ? wy1 * wx1 * mval : 0.f;

    const float* base = out1 + (size_t)b * CB * HW;
    const size_t obase = (size_t)b * CB * KOFF * HW + (size_t)k * HW + hw;
#pragma unroll 4
    for (int c = 0; c < CB; c++) {
        const float* p = base + (size_t)c * HW;
        float v = w00 * p[i00] + w01 * p[i01] + w10 * p[i10] + w11 * p[i11];
        sampled[obase + (size_t)c * (KOFF * HW)] = round_tf32(v);
    }
}

// ---------------- host launcher --------------------------------------------
extern "C" void kernel_launch(void* const* d_in, const int* in_sizes, int n_in,
                              void* d_out, int out_size)
{
    const float* x     = (const float*)d_in[0];
    const float* w1    = (const float*)d_in[1];
    const float* gn1s  = (const float*)d_in[2];
    const float* gn1b  = (const float*)d_in[3];
    const float* w_off = (const float*)d_in[4];
    const float* b_off = (const float*)d_in[5];
    const float* w2    = (const float*)d_in[6];
    const float* gn2s  = (const float*)d_in[7];
    const float* gn2b  = (const float*)d_in[8];
    const float* w3    = (const float*)d_in[9];
    const float* gn3s  = (const float*)d_in[10];
    const float* gn3b  = (const float*)d_in[11];
    float* out = (float*)d_out;

    float *p_out1, *p_om, *p_samp, *p_out2, *p_out3, *p_at1, *p_at2, *p_at3;
    cudaGetSymbolAddress((void**)&p_out1, g_out1);
    cudaGetSymbolAddress((void**)&p_om,   g_om);
    cudaGetSymbolAddress((void**)&p_samp, g_samp);
    cudaGetSymbolAddress((void**)&p_out2, g_out2);
    cudaGetSymbolAddress((void**)&p_out3, g_out3);
    cudaGetSymbolAddress((void**)&p_at1,  g_at1);
    cudaGetSymbolAddress((void**)&p_at2,  g_at2);
    cudaGetSymbolAddress((void**)&p_at3,  g_at3);

    // 0a) transpose + round weights:  w1[256][1024] -> at1[1024][256], etc.
    transpose_round_kernel<<<dim3(CIN/32, CB/32), dim3(32, 8)>>>(w1, p_at1, CB, CIN);
    transpose_round_kernel<<<dim3(CB*KOFF/32, CB/32), dim3(32, 8)>>>(w2, p_at2, CB, CB*KOFF);
    transpose_round_kernel<<<dim3(CB/32, CIN/32), dim3(32, 8)>>>(w3, p_at3, CIN, CB);
    // 0b) round x into g_out3 (GEMM1's B; g_out3 is rewritten later by GEMM3)
    round_copy_kernel<<<(B_*CIN*HW/4 + 255)/256, 256>>>(x, p_out3, B_*CIN*HW/4);

    // 1) out1 = w1 @ x            (M=256, K=1024, N=4096, batch 4)
    tf32_gemm_kernel<<<dim3(HW/128, CB/128, B_), 256>>>(
        p_at1, p_out3, p_out1, CB, HW, CIN, (size_t)CIN*HW, (size_t)CB*HW);

    // 2) GN1 + ReLU (in place, full precision — feeds conv/deform)
    gn_relu_kernel<false><<<B_*32, 256>>>(p_out1, gn1s, gn1b, CB, CB/32);

    // 3) offset conv (27 channels, 3x3, pad 1) + bias
    conv_off_kernel<<<dim3(W_/16, H_/16, B_), 256>>>(p_out1, w_off, b_off, p_om);

    // 4) deform sample * sigmoid(mask) -> rounded [b][c*9+k][hw]
    deform_sample_kernel<<<(B_*KOFF*HW + 255)/256, 256>>>(p_out1, p_om, p_samp);

    // 5) out2 = w2_flat @ sampled (M=256, K=2304, N=4096, batch 4)
    tf32_gemm_kernel<<<dim3(HW/128, CB/128, B_), 256>>>(
        p_at2, p_samp, p_out2, CB, HW, CB*KOFF,
        (size_t)CB*KOFF*HW, (size_t)CB*HW);

    // 6) GN2 + ReLU (in place, rounded — feeds GEMM3 B)
    gn_relu_kernel<true><<<B_*32, 256>>>(p_out2, gn2s, gn2b, CB, CB/32);

    // 7) out3 = w3 @ out2         (M=1024, K=256, N=4096, batch 4)
    tf32_gemm_kernel<<<dim3(HW/128, CIN/128, B_), 256>>>(
        p_at3, p_out2, p_out3, CIN, HW, CB, (size_t)CB*HW, (size_t)CIN*HW);

    // 8) out = relu(GN3(out3) + x)
    gn_res_relu_kernel<<<B_*32, 512>>>(p_out3, x, gn3s, gn3b, out, CIN, CIN/32);
}

// round 6
// speedup vs baseline: 2.8485x; 1.2734x over previous
#include <cuda_runtime.h>
#include <math.h>

#define B_   4
#define CIN  1024
#define CB   256
#define H_   64
#define W_   64
#define HW   (H_*W_)
#define KOFF 9

// ---------------- scratch (device globals; no runtime allocation) ----------
__device__ float g_out1[(size_t)B_*CB*HW];              // 16.7 MB
__device__ float g_om  [(size_t)B_*27*HW];              // 1.8 MB
__device__ float g_omp [(size_t)2*B_*27*HW];            // partial sums, 3.5 MB
__device__ float g_samp[(size_t)B_*CB*KOFF*HW];         // 151 MB
__device__ float g_out2[(size_t)B_*CB*HW];              // 16.7 MB
__device__ float g_out3[(size_t)B_*CIN*HW];             // 67 MB (also rounded-x before GEMM3)
__device__ float g_at1[(size_t)CIN*CB];                 // w1^T  [1024][256]
__device__ float g_at2[(size_t)CB*KOFF*CB];             // w2^T  [2304][256]
__device__ float g_at3[(size_t)CB*CIN];                 // w3^T  [256][1024]

__device__ __forceinline__ unsigned f2tf32(float f) {
    unsigned u;
    asm("cvt.rna.tf32.f32 %0, %1;" : "=r"(u) : "f"(f));
    return u;
}
__device__ __forceinline__ float round_tf32(float f) {
    return __uint_as_float(f2tf32(f));
}

__device__ __forceinline__ void cp_async16(void* smem_dst, const void* gsrc) {
    unsigned s = (unsigned)__cvta_generic_to_shared(smem_dst);
    asm volatile("cp.async.cg.shared.global [%0], [%1], 16;\n" :: "r"(s), "l"(gsrc));
}
__device__ __forceinline__ void cp_commit() {
    asm volatile("cp.async.commit_group;\n");
}
template <int N>
__device__ __forceinline__ void cp_wait() {
    asm volatile("cp.async.wait_group %0;\n" :: "n"(N));
}

// ---------------- batched TF32 tensor-core GEMM: C[b] = A^T-form @ B[b] ----
// AT: [K,M] row-major (pre-transposed, pre-rounded tf32 bits, shared over batch).
// B:  [K,N] row-major (pre-rounded tf32 bits). C: [M,N].
// Requires M%128==0, N%128==0, K%8==0, K/8>=3.
// CTA tile 128x128, 4-stage cp.async pipeline with K=8 stages.
// 8 warps as 2(M)x4(N), warp tile 64x32, mma m16n8k8.tf32.
__global__ void __launch_bounds__(256, 2) tf32_gemm_kernel(
    const float* __restrict__ AT, const float* __restrict__ Bm,
    float* __restrict__ Cm, int M, int N, int K,
    size_t strideB, size_t strideC)
{
    __shared__ float As[4][8][136];   // [stage][k][m], pad 8 -> conflict-free
    __shared__ float Bs[4][8][136];   // [stage][k][n]

    const float* Bp = Bm + (size_t)blockIdx.z * strideB;
    float*       Cp = Cm + (size_t)blockIdx.z * strideC;
    const int bm = blockIdx.y * 128;
    const int bn = blockIdx.x * 128;

    const int tid  = threadIdx.x;
    const int lane = tid & 31;
    const int warp = tid >> 5;
    const int wm = (warp & 1) * 64;     // warp M offset
    const int wn = (warp >> 1) * 32;    // warp N offset
    const int grp = lane >> 2;          // 0..7
    const int tig = lane & 3;           // 0..3

    // stage-load indexing (identical shape for A^T and B)
    const int lrow = tid >> 5;          // k within stage: 0..7
    const int lcol = (tid & 31) * 4;    // 0..124

    float acc[4][4][4];
#pragma unroll
    for (int mi = 0; mi < 4; mi++)
#pragma unroll
        for (int ni = 0; ni < 4; ni++)
#pragma unroll
            for (int i = 0; i < 4; i++) acc[mi][ni][i] = 0.f;

    const int nstage = K >> 3;

    // prologue: issue 3 stages
#pragma unroll
    for (int s = 0; s < 3; s++) {
        const int k = s * 8 + lrow;
        cp_async16(&As[s][lrow][lcol], AT + (size_t)k * M + bm + lcol);
        cp_async16(&Bs[s][lrow][lcol], Bp + (size_t)k * N + bn + lcol);
        cp_commit();
    }

    int cur = 0;
    for (int ks = 0; ks < nstage; ks++) {
        cp_wait<2>();
        __syncthreads();

        unsigned a[4][4], b[4][2];
#pragma unroll
        for (int mi = 0; mi < 4; mi++) {
            const int m = wm + mi * 16 + grp;
            a[mi][0] = __float_as_uint(As[cur][tig    ][m]);
            a[mi][1] = __float_as_uint(As[cur][tig    ][m + 8]);
            a[mi][2] = __float_as_uint(As[cur][tig + 4][m]);
            a[mi][3] = __float_as_uint(As[cur][tig + 4][m + 8]);
        }
#pragma unroll
        for (int ni = 0; ni < 4; ni++) {
            const int n = wn + ni * 8 + grp;
            b[ni][0] = __float_as_uint(Bs[cur][tig    ][n]);
            b[ni][1] = __float_as_uint(Bs[cur][tig + 4][n]);
        }
#pragma unroll
        for (int mi = 0; mi < 4; mi++)
#pragma unroll
            for (int ni = 0; ni < 4; ni++) {
                asm volatile(
                    "mma.sync.aligned.m16n8k8.row.col.f32.tf32.tf32.f32 "
                    "{%0,%1,%2,%3}, {%4,%5,%6,%7}, {%8,%9}, {%0,%1,%2,%3};\n"
                    : "+f"(acc[mi][ni][0]), "+f"(acc[mi][ni][1]),
                      "+f"(acc[mi][ni][2]), "+f"(acc[mi][ni][3])
                    : "r"(a[mi][0]), "r"(a[mi][1]), "r"(a[mi][2]), "r"(a[mi][3]),
                      "r"(b[ni][0]), "r"(b[ni][1]));
            }

        if (ks + 3 < nstage) {
            const int buf = (cur + 3) & 3;
            const int k = (ks + 3) * 8 + lrow;
            cp_async16(&As[buf][lrow][lcol], AT + (size_t)k * M + bm + lcol);
            cp_async16(&Bs[buf][lrow][lcol], Bp + (size_t)k * N + bn + lcol);
        }
        cp_commit();
        cur = (cur + 1) & 3;
    }

    // epilogue
#pragma unroll
    for (int mi = 0; mi < 4; mi++) {
        const int row = bm + wm + mi * 16 + grp;
#pragma unroll
        for (int ni = 0; ni < 4; ni++) {
            const int col = bn + wn + ni * 8 + tig * 2;
            float2 v0 = make_float2(acc[mi][ni][0], acc[mi][ni][1]);
            float2 v1 = make_float2(acc[mi][ni][2], acc[mi][ni][3]);
            *(float2*)(Cp + (size_t)row * N + col)       = v0;
            *(float2*)(Cp + (size_t)(row + 8) * N + col) = v1;
        }
    }
}

// ---------------- transpose + tf32-round: A[M][K] -> AT[K][M] --------------
__global__ void transpose_round_kernel(const float* __restrict__ A,
                                       float* __restrict__ AT, int M, int K)
{
    __shared__ float t[32][33];
    const int kx = blockIdx.x * 32;
    const int my = blockIdx.y * 32;
    const int tx = threadIdx.x, ty = threadIdx.y;
#pragma unroll
    for (int i = 0; i < 32; i += 8)
        t[ty + i][tx] = A[(size_t)(my + ty + i) * K + kx + tx];
    __syncthreads();
#pragma unroll
    for (int i = 0; i < 32; i += 8)
        AT[(size_t)(kx + ty + i) * M + my + tx] = round_tf32(t[tx][ty + i]);
}

// ---------------- tf32 round-copy (for x -> GEMM1 B) -----------------------
__global__ void round_copy_kernel(const float* __restrict__ in,
                                  float* __restrict__ out, int n4)
{
    const int i = blockIdx.x * blockDim.x + threadIdx.x;
    if (i >= n4) return;
    float4 v = ((const float4*)in)[i];
    v.x = round_tf32(v.x); v.y = round_tf32(v.y);
    v.z = round_tf32(v.z); v.w = round_tf32(v.w);
    ((float4*)out)[i] = v;
}

// ---------------- block reduction helper -----------------------------------
__device__ __forceinline__ void block_reduce2(float& s, float& ss) {
#pragma unroll
    for (int o = 16; o > 0; o >>= 1) {
        s  += __shfl_down_sync(0xFFFFFFFFu, s,  o);
        ss += __shfl_down_sync(0xFFFFFFFFu, ss, o);
    }
    __shared__ float as_[32], ass_[32];
    int lane = threadIdx.x & 31, wid = threadIdx.x >> 5;
    if (lane == 0) { as_[wid] = s; ass_[wid] = ss; }
    __syncthreads();
    int nw = blockDim.x >> 5;
    if (wid == 0) {
        s  = (lane < nw) ? as_[lane]  : 0.f;
        ss = (lane < nw) ? ass_[lane] : 0.f;
#pragma unroll
        for (int o = 16; o > 0; o >>= 1) {
            s  += __shfl_down_sync(0xFFFFFFFFu, s,  o);
            ss += __shfl_down_sync(0xFFFFFFFFu, ss, o);
        }
    }
}

// ---------------- GroupNorm (+ReLU), in-place; one block per (b, group) ----
// ROUND: emit tf32-rounded bits (when output feeds a GEMM B operand).
template <bool ROUND>
__global__ void gn_relu_kernel(float* __restrict__ data,
                               const float* __restrict__ scale,
                               const float* __restrict__ bias,
                               int C, int cpg)
{
    const int G  = C / cpg;
    const int b  = blockIdx.x / G;
    const int gi = blockIdx.x % G;
    float* p = data + ((size_t)b * C + (size_t)gi * cpg) * HW;
    const int n4 = (cpg * HW) >> 2;

    float s = 0.f, ss = 0.f;
    for (int i = threadIdx.x; i < n4; i += blockDim.x) {
        float4 v = ((const float4*)p)[i];
        s  += v.x + v.y + v.z + v.w;
        ss += v.x * v.x + v.y * v.y + v.z * v.z + v.w * v.w;
    }
    block_reduce2(s, ss);
    __shared__ float sh_mean, sh_rstd;
    if (threadIdx.x == 0) {
        const float n = (float)(cpg * HW);
        float mean = s / n;
        float var  = ss / n - mean * mean;
        sh_mean = mean;
        sh_rstd = rsqrtf(var + 1e-5f);
    }
    __syncthreads();
    const float mean = sh_mean, rstd = sh_rstd;
    for (int i = threadIdx.x; i < n4; i += blockDim.x) {
        int c = gi * cpg + (i * 4) / HW;
        const float a = rstd * scale[c];
        const float d = bias[c] - mean * a;
        float4 v = ((const float4*)p)[i];
        v.x = fmaxf(v.x * a + d, 0.f);
        v.y = fmaxf(v.y * a + d, 0.f);
        v.z = fmaxf(v.z * a + d, 0.f);
        v.w = fmaxf(v.w * a + d, 0.f);
        if (ROUND) {
            v.x = round_tf32(v.x); v.y = round_tf32(v.y);
            v.z = round_tf32(v.z); v.w = round_tf32(v.w);
        }
        ((float4*)p)[i] = v;
    }
}

// ---------------- GN3 + residual + ReLU -> output --------------------------
__global__ void gn_res_relu_kernel(const float* __restrict__ in,
                                   const float* __restrict__ xres,
                                   const float* __restrict__ scale,
                                   const float* __restrict__ bias,
                                   float* __restrict__ out,
                                   int C, int cpg)
{
    const int G  = C / cpg;
    const int b  = blockIdx.x / G;
    const int gi = blockIdx.x % G;
    const size_t base = ((size_t)b * C + (size_t)gi * cpg) * HW;
    const float* p = in + base;
    const float* r = xres + base;
    float* o = out + base;
    const int n4 = (cpg * HW) >> 2;

    float s = 0.f, ss = 0.f;
    for (int i = threadIdx.x; i < n4; i += blockDim.x) {
        float4 v = ((const float4*)p)[i];
        s  += v.x + v.y + v.z + v.w;
        ss += v.x * v.x + v.y * v.y + v.z * v.z + v.w * v.w;
    }
    block_reduce2(s, ss);
    __shared__ float sh_mean, sh_rstd;
    if (threadIdx.x == 0) {
        const float n = (float)(cpg * HW);
        float mean = s / n;
        float var  = ss / n - mean * mean;
        sh_mean = mean;
        sh_rstd = rsqrtf(var + 1e-5f);
    }
    __syncthreads();
    const float mean = sh_mean, rstd = sh_rstd;
    for (int i = threadIdx.x; i < n4; i += blockDim.x) {
        int c = gi * cpg + (i * 4) / HW;
        const float a = rstd * scale[c];
        const float d = bias[c] - mean * a;
        float4 v = ((const float4*)p)[i];
        float4 rr = ((const float4*)r)[i];
        v.x = fmaxf(v.x * a + d + rr.x, 0.f);
        v.y = fmaxf(v.y * a + d + rr.y, 0.f);
        v.z = fmaxf(v.z * a + d + rr.z, 0.f);
        v.w = fmaxf(v.w * a + d + rr.w, 0.f);
        ((float4*)o)[i] = v;
    }
}

// ---------------- 3x3 offset conv (27 out ch), pad=1, channel-split 2 ------
// blockIdx.z = b*2 + half; each half sums 128 channels into g_omp[half].
// Weights staged as s_w[c][k][28] (zero-padded) -> float4 loads.
__global__ void __launch_bounds__(256) conv_off_kernel(
    const float* __restrict__ in,    // g_out1 [B][CB][H][W]
    const float* __restrict__ w,     // [27][CB][3][3]
    float* __restrict__ omp)         // [2][B][27][H][W]
{
    const int bx = blockIdx.x;   // 0..3
    const int by = blockIdx.y;   // 0..3
    const int b    = blockIdx.z >> 1;
    const int half = blockIdx.z & 1;
    const int tid = threadIdx.x;
    const int tx = tid & 15, ty = tid >> 4;

    __shared__ float s_in[8][18][18];
    __shared__ float s_w[8][9][28];     // j padded 27->28 (zero)

    float acc[28];
#pragma unroll
    for (int j = 0; j < 28; j++) acc[j] = 0.f;

    const int x0 = bx * 16, y0 = by * 16;
    const int cbase = half * 128;
    const float* inb = in + (size_t)b * CB * HW;

    for (int c0 = cbase; c0 < cbase + 128; c0 += 8) {
        for (int e = tid; e < 8 * 18 * 18; e += 256) {
            int c = e / 324;
            int r = (e / 18) % 18;
            int col = e % 18;
            int y = y0 + r - 1, x = x0 + col - 1;
            float v = 0.f;
            if (y >= 0 && y < H_ && x >= 0 && x < W_)
                v = inb[(size_t)(c0 + c) * HW + y * W_ + x];
            s_in[c][r][col] = v;
        }
        for (int e = tid; e < 8 * 9 * 28; e += 256) {
            int c = e / (9 * 28);
            int k = (e / 28) % 9;
            int j = e % 28;
            s_w[c][k][j] = (j < 27) ? w[((size_t)j * CB + c0 + c) * 9 + k] : 0.f;
        }
        __syncthreads();
#pragma unroll
        for (int c = 0; c < 8; c++) {
#pragma unroll
            for (int k = 0; k < 9; k++) {
                const float v = s_in[c][ty + k / 3][tx + k % 3];
                const float4* wr = (const float4*)&s_w[c][k][0];
#pragma unroll
                for (int q = 0; q < 7; q++) {
                    const float4 w4 = wr[q];
                    acc[q * 4 + 0] += v * w4.x;
                    acc[q * 4 + 1] += v * w4.y;
                    acc[q * 4 + 2] += v * w4.z;
                    acc[q * 4 + 3] += v * w4.w;
                }
            }
        }
        __syncthreads();
    }
    const int hw = (y0 + ty) * W_ + x0 + tx;
    float* op = omp + (size_t)half * B_ * 27 * HW + (size_t)b * 27 * HW;
#pragma unroll
    for (int j = 0; j < 27; j++)
        op[(size_t)j * HW + hw] = acc[j];
}

// ---------------- combine conv halves + bias -------------------------------
__global__ void conv_combine_kernel(const float* __restrict__ omp,
                                    const float* __restrict__ bias,
                                    float* __restrict__ om)
{
    const int i = blockIdx.x * blockDim.x + threadIdx.x;
    const int n = B_ * 27 * HW;
    if (i >= n) return;
    const int j = (i / HW) % 27;
    om[i] = omp[i] + omp[(size_t)B_ * 27 * HW + i] + bias[j];
}

// ---------------- deformable bilinear sampling (emits tf32-rounded) --------
__global__ void __launch_bounds__(256) deform_sample_kernel(
    const float* __restrict__ out1,
    const float* __restrict__ om,
    float* __restrict__ sampled)
{
    const int idx = blockIdx.x * blockDim.x + threadIdx.x;
    if (idx >= B_ * KOFF * HW) return;
    const int hw = idx % HW;
    const int k  = (idx / HW) % KOFF;
    const int b  = idx / (HW * KOFF);
    const int h = hw / W_, w = hw % W_;

    const float* omb = om + (size_t)b * 27 * HW;
    const float offx = omb[(size_t)k * HW + hw];
    const float offy = omb[(size_t)(KOFF + k) * HW + hw];
    const float mval = 1.f / (1.f + expf(-omb[(size_t)(18 + k) * HW + hw]));

    const float py = (float)(h + k / 3 - 1) + offy;
    const float px = (float)(w + k % 3 - 1) + offx;
    const float y0f = floorf(py), x0f = floorf(px);
    const int y0 = (int)y0f, x0 = (int)x0f;
    const float wy1 = py - y0f, wx1 = px - x0f;
    const float wy0 = 1.f - wy1, wx0 = 1.f - wx1;
    const int y1 = y0 + 1, x1 = x0 + 1;
    const bool vy0 = (y0 >= 0) && (y0 < H_), vy1 = (y1 >= 0) && (y1 < H_);
    const bool vx0 = (x0 >= 0) && (x0 < W_), vx1 = (x1 >= 0) && (x1 < W_);
    const int cy0 = min(max(y0, 0), H_ - 1), cy1 = min(max(y1, 0), H_ - 1);
    const int cx0 = min(max(x0, 0), W_ - 1), cx1 = min(max(x1, 0), W_ - 1);
    const int i00 = cy0 * W_ + cx0, i01 = cy0 * W_ + cx1;
    const int i10 = cy1 * W_ + cx0, i11 = cy1 * W_ + cx1;
    const float w00 = (vy0 && vx0) ? wy0 * wx0 * mval : 0.f;
    const float w01 = (vy0 && vx1) ? wy0 * wx1 * mval : 0.f;
    const float w10 = (vy1 && vx0) ? wy1 * wx0 * mval : 0.f;
    const float w11 = (vy1 && vx1) ? wy1 * wx1 * mval : 0.f;

    const float* base = out1 + (size_t)b * CB * HW;
    const size_t obase = (size_t)b * CB * KOFF * HW + (size_t)k * HW + hw;
#pragma unroll 8
    for (int c = 0; c < CB; c++) {
        const float* p = base + (size_t)c * HW;
        float v = w00 * p[i00] + w01 * p[i01] + w10 * p[i10] + w11 * p[i11];
        sampled[obase + (size_t)c * (KOFF * HW)] = round_tf32(v);
    }
}

// ---------------- host launcher --------------------------------------------
extern "C" void kernel_launch(void* const* d_in, const int* in_sizes, int n_in,
                              void* d_out, int out_size)
{
    const float* x     = (const float*)d_in[0];
    const float* w1    = (const float*)d_in[1];
    const float* gn1s  = (const float*)d_in[2];
    const float* gn1b  = (const float*)d_in[3];
    const float* w_off = (const float*)d_in[4];
    const float* b_off = (const float*)d_in[5];
    const float* w2    = (const float*)d_in[6];
    const float* gn2s  = (const float*)d_in[7];
    const float* gn2b  = (const float*)d_in[8];
    const float* w3    = (const float*)d_in[9];
    const float* gn3s  = (const float*)d_in[10];
    const float* gn3b  = (const float*)d_in[11];
    float* out = (float*)d_out;

    float *p_out1, *p_om, *p_omp, *p_samp, *p_out2, *p_out3, *p_at1, *p_at2, *p_at3;
    cudaGetSymbolAddress((void**)&p_out1, g_out1);
    cudaGetSymbolAddress((void**)&p_om,   g_om);
    cudaGetSymbolAddress((void**)&p_omp,  g_omp);
    cudaGetSymbolAddress((void**)&p_samp, g_samp);
    cudaGetSymbolAddress((void**)&p_out2, g_out2);
    cudaGetSymbolAddress((void**)&p_out3, g_out3);
    cudaGetSymbolAddress((void**)&p_at1,  g_at1);
    cudaGetSymbolAddress((void**)&p_at2,  g_at2);
    cudaGetSymbolAddress((void**)&p_at3,  g_at3);

    // 0a) transpose + round weights
    transpose_round_kernel<<<dim3(CIN/32, CB/32), dim3(32, 8)>>>(w1, p_at1, CB, CIN);
    transpose_round_kernel<<<dim3(CB*KOFF/32, CB/32), dim3(32, 8)>>>(w2, p_at2, CB, CB*KOFF);
    transpose_round_kernel<<<dim3(CB/32, CIN/32), dim3(32, 8)>>>(w3, p_at3, CIN, CB);
    // 0b) round x into g_out3 (GEMM1's B; g_out3 is rewritten later by GEMM3)
    round_copy_kernel<<<(B_*CIN*HW/4 + 255)/256, 256>>>(x, p_out3, B_*CIN*HW/4);

    // 1) out1 = w1 @ x            (M=256, K=1024, N=4096, batch 4)
    tf32_gemm_kernel<<<dim3(HW/128, CB/128, B_), 256>>>(
        p_at1, p_out3, p_out1, CB, HW, CIN, (size_t)CIN*HW, (size_t)CB*HW);

    // 2) GN1 + ReLU (in place, full precision — feeds conv/deform)
    gn_relu_kernel<false><<<B_*32, 512>>>(p_out1, gn1s, gn1b, CB, CB/32);

    // 3) offset conv, channel-split 2 -> partials, then combine + bias
    conv_off_kernel<<<dim3(W_/16, H_/16, B_*2), 256>>>(p_out1, w_off, p_omp);
    conv_combine_kernel<<<(B_*27*HW + 255)/256, 256>>>(p_omp, b_off, p_om);

    // 4) deform sample * sigmoid(mask) -> rounded [b][c*9+k][hw]
    deform_sample_kernel<<<(B_*KOFF*HW + 255)/256, 256>>>(p_out1, p_om, p_samp);

    // 5) out2 = w2_flat @ sampled (M=256, K=2304, N=4096, batch 4)
    tf32_gemm_kernel<<<dim3(HW/128, CB/128, B_), 256>>>(
        p_at2, p_samp, p_out2, CB, HW, CB*KOFF,
        (size_t)CB*KOFF*HW, (size_t)CB*HW);

    // 6) GN2 + ReLU (in place, rounded — feeds GEMM3 B)
    gn_relu_kernel<true><<<B_*32, 512>>>(p_out2, gn2s, gn2b, CB, CB/32);

    // 7) out3 = w3 @ out2         (M=1024, K=256, N=4096, batch 4)
    tf32_gemm_kernel<<<dim3(HW/128, CIN/128, B_), 256>>>(
        p_at3, p_out2, p_out3, CIN, HW, CB, (size_t)CB*HW, (size_t)CIN*HW);

    // 8) out = relu(GN3(out3) + x)
    gn_res_relu_kernel<<<B_*32, 1024>>>(p_out3, x, gn3s, gn3b, out, CIN, CIN/32);
}

// round 7
// speedup vs baseline: 2.9093x; 1.0214x over previous
#include <cuda_runtime.h>
#include <math.h>

#define B_   4
#define CIN  1024
#define CB   256
#define H_   64
#define W_   64
#define HW   (H_*W_)
#define KOFF 9

// ---------------- scratch (device globals; no runtime allocation) ----------
__device__ float g_out1[(size_t)B_*CB*HW];              // 16.7 MB
__device__ float g_omp [(size_t)2*B_*27*HW];            // conv partial sums
__device__ float g_samp[(size_t)B_*CB*KOFF*HW];         // 151 MB
__device__ float g_out2[(size_t)B_*CB*HW];              // 16.7 MB
__device__ float g_out3[(size_t)B_*CIN*HW];             // 67 MB (also rounded-x before GEMM3)
__device__ float g_at1[(size_t)CIN*CB];                 // w1^T  [1024][256]
__device__ float g_at2[(size_t)CB*KOFF*CB];             // w2^T  [2304][256]
__device__ float g_at3[(size_t)CB*CIN];                 // w3^T  [256][1024]

__device__ __forceinline__ unsigned f2tf32(float f) {
    unsigned u;
    asm("cvt.rna.tf32.f32 %0, %1;" : "=r"(u) : "f"(f));
    return u;
}
__device__ __forceinline__ float round_tf32(float f) {
    return __uint_as_float(f2tf32(f));
}

__device__ __forceinline__ void cp_async16(void* smem_dst, const void* gsrc) {
    unsigned s = (unsigned)__cvta_generic_to_shared(smem_dst);
    asm volatile("cp.async.cg.shared.global [%0], [%1], 16;\n" :: "r"(s), "l"(gsrc));
}
__device__ __forceinline__ void cp_commit() {
    asm volatile("cp.async.commit_group;\n");
}
template <int N>
__device__ __forceinline__ void cp_wait() {
    asm volatile("cp.async.wait_group %0;\n" :: "n"(N));
}

// ---------------- batched TF32 tensor-core GEMM: C[b] = A^T-form @ B[b] ----
// AT: [K,M] row-major (pre-transposed, pre-rounded tf32 bits, shared over batch).
// B:  [K,N] row-major (pre-rounded tf32 bits). C: [M,N].
// Requires M%128==0, N%128==0, K%16==0, K/16>=2.
// CTA tile 128x128, 3-stage cp.async pipeline, K=16 per stage.
// 8 warps as 2(M)x4(N), warp tile 64x32, mma m16n8k8.tf32.
#define GSTAGE   3
#define GK       16
#define GROW     136
#define GEMM_SMEM (2 * GSTAGE * GK * GROW * 4)
__global__ void __launch_bounds__(256, 2) tf32_gemm_kernel(
    const float* __restrict__ AT, const float* __restrict__ Bm,
    float* __restrict__ Cm, int M, int N, int K,
    size_t strideB, size_t strideC)
{
    extern __shared__ float sm_[];
    float (*As)[GK][GROW] = (float(*)[GK][GROW])sm_;
    float (*Bs)[GK][GROW] = (float(*)[GK][GROW])(sm_ + GSTAGE * GK * GROW);

    const float* Bp = Bm + (size_t)blockIdx.z * strideB;
    float*       Cp = Cm + (size_t)blockIdx.z * strideC;
    const int bm = blockIdx.y * 128;
    const int bn = blockIdx.x * 128;

    const int tid  = threadIdx.x;
    const int lane = tid & 31;
    const int warp = tid >> 5;
    const int wm = (warp & 1) * 64;     // warp M offset
    const int wn = (warp >> 1) * 32;    // warp N offset
    const int grp = lane >> 2;          // 0..7
    const int tig = lane & 3;           // 0..3

    float acc[4][4][4];
#pragma unroll
    for (int mi = 0; mi < 4; mi++)
#pragma unroll
        for (int ni = 0; ni < 4; ni++)
#pragma unroll
            for (int i = 0; i < 4; i++) acc[mi][ni][i] = 0.f;

    const int nstage = K / GK;

    // stage loader: 512 16B-chunks per matrix per stage; 2 per thread each
#define LOAD_STAGE(buf, kbase)                                               \
    do {                                                                     \
        _Pragma("unroll")                                                    \
        for (int j = 0; j < 2; j++) {                                        \
            const int id = tid + 256 * j;                                    \
            const int kk = id >> 5;                                          \
            const int mo = (id & 31) * 4;                                    \
            cp_async16(&As[buf][kk][mo], AT + (size_t)((kbase) + kk) * M + bm + mo); \
            cp_async16(&Bs[buf][kk][mo], Bp + (size_t)((kbase) + kk) * N + bn + mo); \
        }                                                                    \
    } while (0)

    // prologue: stages 0 and 1
    LOAD_STAGE(0, 0);
    cp_commit();
    LOAD_STAGE(1, GK);
    cp_commit();

    int cur = 0;
    for (int ks = 0; ks < nstage; ks++) {
        cp_wait<1>();
        __syncthreads();

#pragma unroll
        for (int kk = 0; kk < GK; kk += 8) {
            unsigned a[4][4], b[4][2];
#pragma unroll
            for (int mi = 0; mi < 4; mi++) {
                const int m = wm + mi * 16 + grp;
                a[mi][0] = __float_as_uint(As[cur][kk + tig    ][m]);
                a[mi][1] = __float_as_uint(As[cur][kk + tig    ][m + 8]);
                a[mi][2] = __float_as_uint(As[cur][kk + tig + 4][m]);
                a[mi][3] = __float_as_uint(As[cur][kk + tig + 4][m + 8]);
            }
#pragma unroll
            for (int ni = 0; ni < 4; ni++) {
                const int n = wn + ni * 8 + grp;
                b[ni][0] = __float_as_uint(Bs[cur][kk + tig    ][n]);
                b[ni][1] = __float_as_uint(Bs[cur][kk + tig + 4][n]);
            }
#pragma unroll
            for (int mi = 0; mi < 4; mi++)
#pragma unroll
                for (int ni = 0; ni < 4; ni++) {
                    asm volatile(
                        "mma.sync.aligned.m16n8k8.row.col.f32.tf32.tf32.f32 "
                        "{%0,%1,%2,%3}, {%4,%5,%6,%7}, {%8,%9}, {%0,%1,%2,%3};\n"
                        : "+f"(acc[mi][ni][0]), "+f"(acc[mi][ni][1]),
                          "+f"(acc[mi][ni][2]), "+f"(acc[mi][ni][3])
                        : "r"(a[mi][0]), "r"(a[mi][1]), "r"(a[mi][2]), "r"(a[mi][3]),
                          "r"(b[ni][0]), "r"(b[ni][1]));
                }
        }

        if (ks + 2 < nstage) {
            const int buf = cur + 2 >= GSTAGE ? cur + 2 - GSTAGE : cur + 2;
            LOAD_STAGE(buf, (ks + 2) * GK);
        }
        cp_commit();
        cur = cur + 1 >= GSTAGE ? 0 : cur + 1;
    }

    // epilogue
#pragma unroll
    for (int mi = 0; mi < 4; mi++) {
        const int row = bm + wm + mi * 16 + grp;
#pragma unroll
        for (int ni = 0; ni < 4; ni++) {
            const int col = bn + wn + ni * 8 + tig * 2;
            float2 v0 = make_float2(acc[mi][ni][0], acc[mi][ni][1]);
            float2 v1 = make_float2(acc[mi][ni][2], acc[mi][ni][3]);
            *(float2*)(Cp + (size_t)row * N + col)       = v0;
            *(float2*)(Cp + (size_t)(row + 8) * N + col) = v1;
        }
    }
#undef LOAD_STAGE
}

// ---------------- transpose + tf32-round: A[M][K] -> AT[K][M] --------------
__global__ void transpose_round_kernel(const float* __restrict__ A,
                                       float* __restrict__ AT, int M, int K)
{
    __shared__ float t[32][33];
    const int kx = blockIdx.x * 32;
    const int my = blockIdx.y * 32;
    const int tx = threadIdx.x, ty = threadIdx.y;
#pragma unroll
    for (int i = 0; i < 32; i += 8)
        t[ty + i][tx] = A[(size_t)(my + ty + i) * K + kx + tx];
    __syncthreads();
#pragma unroll
    for (int i = 0; i < 32; i += 8)
        AT[(size_t)(kx + ty + i) * M + my + tx] = round_tf32(t[tx][ty + i]);
}

// ---------------- tf32 round-copy (for x -> GEMM1 B) -----------------------
__global__ void round_copy_kernel(const float* __restrict__ in,
                                  float* __restrict__ out, int n4)
{
    const int i = blockIdx.x * blockDim.x + threadIdx.x;
    if (i >= n4) return;
    float4 v = ((const float4*)in)[i];
    v.x = round_tf32(v.x); v.y = round_tf32(v.y);
    v.z = round_tf32(v.z); v.w = round_tf32(v.w);
    ((float4*)out)[i] = v;
}

// ---------------- block reduction helper -----------------------------------
__device__ __forceinline__ void block_reduce2(float& s, float& ss) {
#pragma unroll
    for (int o = 16; o > 0; o >>= 1) {
        s  += __shfl_down_sync(0xFFFFFFFFu, s,  o);
        ss += __shfl_down_sync(0xFFFFFFFFu, ss, o);
    }
    __shared__ float as_[32], ass_[32];
    int lane = threadIdx.x & 31, wid = threadIdx.x >> 5;
    if (lane == 0) { as_[wid] = s; ass_[wid] = ss; }
    __syncthreads();
    int nw = blockDim.x >> 5;
    if (wid == 0) {
        s  = (lane < nw) ? as_[lane]  : 0.f;
        ss = (lane < nw) ? ass_[lane] : 0.f;
#pragma unroll
        for (int o = 16; o > 0; o >>= 1) {
            s  += __shfl_down_sync(0xFFFFFFFFu, s,  o);
            ss += __shfl_down_sync(0xFFFFFFFFu, ss, o);
        }
    }
}

// ---------------- GroupNorm (+ReLU), in-place; one block per (b, group) ----
template <bool ROUND>
__global__ void gn_relu_kernel(float* __restrict__ data,
                               const float* __restrict__ scale,
                               const float* __restrict__ bias,
                               int C, int cpg)
{
    const int G  = C / cpg;
    const int b  = blockIdx.x / G;
    const int gi = blockIdx.x % G;
    float* p = data + ((size_t)b * C + (size_t)gi * cpg) * HW;
    const int n4 = (cpg * HW) >> 2;

    float s = 0.f, ss = 0.f;
    for (int i = threadIdx.x; i < n4; i += blockDim.x) {
        float4 v = ((const float4*)p)[i];
        s  += v.x + v.y + v.z + v.w;
        ss += v.x * v.x + v.y * v.y + v.z * v.z + v.w * v.w;
    }
    block_reduce2(s, ss);
    __shared__ float sh_mean, sh_rstd;
    if (threadIdx.x == 0) {
        const float n = (float)(cpg * HW);
        float mean = s / n;
        float var  = ss / n - mean * mean;
        sh_mean = mean;
        sh_rstd = rsqrtf(var + 1e-5f);
    }
    __syncthreads();
    const float mean = sh_mean, rstd = sh_rstd;
    for (int i = threadIdx.x; i < n4; i += blockDim.x) {
        int c = gi * cpg + (i * 4) / HW;
        const float a = rstd * scale[c];
        const float d = bias[c] - mean * a;
        float4 v = ((const float4*)p)[i];
        v.x = fmaxf(v.x * a + d, 0.f);
        v.y = fmaxf(v.y * a + d, 0.f);
        v.z = fmaxf(v.z * a + d, 0.f);
        v.w = fmaxf(v.w * a + d, 0.f);
        if (ROUND) {
            v.x = round_tf32(v.x); v.y = round_tf32(v.y);
            v.z = round_tf32(v.z); v.w = round_tf32(v.w);
        }
        ((float4*)p)[i] = v;
    }
}

// ---------------- GN3 + residual + ReLU -> output --------------------------
__global__ void gn_res_relu_kernel(const float* __restrict__ in,
                                   const float* __restrict__ xres,
                                   const float* __restrict__ scale,
                                   const float* __restrict__ bias,
                                   float* __restrict__ out,
                                   int C, int cpg)
{
    const int G  = C / cpg;
    const int b  = blockIdx.x / G;
    const int gi = blockIdx.x % G;
    const size_t base = ((size_t)b * C + (size_t)gi * cpg) * HW;
    const float* p = in + base;
    const float* r = xres + base;
    float* o = out + base;
    const int n4 = (cpg * HW) >> 2;

    float s = 0.f, ss = 0.f;
    for (int i = threadIdx.x; i < n4; i += blockDim.x) {
        float4 v = ((const float4*)p)[i];
        s  += v.x + v.y + v.z + v.w;
        ss += v.x * v.x + v.y * v.y + v.z * v.z + v.w * v.w;
    }
    block_reduce2(s, ss);
    __shared__ float sh_mean, sh_rstd;
    if (threadIdx.x == 0) {
        const float n = (float)(cpg * HW);
        float mean = s / n;
        float var  = ss / n - mean * mean;
        sh_mean = mean;
        sh_rstd = rsqrtf(var + 1e-5f);
    }
    __syncthreads();
    const float mean = sh_mean, rstd = sh_rstd;
    for (int i = threadIdx.x; i < n4; i += blockDim.x) {
        int c = gi * cpg + (i * 4) / HW;
        const float a = rstd * scale[c];
        const float d = bias[c] - mean * a;
        float4 v = ((const float4*)p)[i];
        float4 rr = ((const float4*)r)[i];
        v.x = fmaxf(v.x * a + d + rr.x, 0.f);
        v.y = fmaxf(v.y * a + d + rr.y, 0.f);
        v.z = fmaxf(v.z * a + d + rr.z, 0.f);
        v.w = fmaxf(v.w * a + d + rr.w, 0.f);
        ((float4*)o)[i] = v;
    }
}

// ---------------- 3x3 offset conv (27 out ch), pad=1, channel-split 2 ------
__global__ void __launch_bounds__(256) conv_off_kernel(
    const float* __restrict__ in,    // g_out1 [B][CB][H][W]
    const float* __restrict__ w,     // [27][CB][3][3]
    float* __restrict__ omp)         // [2][B][27][H][W]
{
    const int bx = blockIdx.x;   // 0..3
    const int by = blockIdx.y;   // 0..3
    const int b    = blockIdx.z >> 1;
    const int half = blockIdx.z & 1;
    const int tid = threadIdx.x;
    const int tx = tid & 15, ty = tid >> 4;

    __shared__ float s_in[8][18][18];
    __shared__ float s_w[8][9][28];     // j padded 27->28 (zero)

    float acc[28];
#pragma unroll
    for (int j = 0; j < 28; j++) acc[j] = 0.f;

    const int x0 = bx * 16, y0 = by * 16;
    const int cbase = half * 128;
    const float* inb = in + (size_t)b * CB * HW;

    for (int c0 = cbase; c0 < cbase + 128; c0 += 8) {
        for (int e = tid; e < 8 * 18 * 18; e += 256) {
            int c = e / 324;
            int r = (e / 18) % 18;
            int col = e % 18;
            int y = y0 + r - 1, x = x0 + col - 1;
            float v = 0.f;
            if (y >= 0 && y < H_ && x >= 0 && x < W_)
                v = inb[(size_t)(c0 + c) * HW + y * W_ + x];
            s_in[c][r][col] = v;
        }
        for (int e = tid; e < 8 * 9 * 28; e += 256) {
            int c = e / (9 * 28);
            int k = (e / 28) % 9;
            int j = e % 28;
            s_w[c][k][j] = (j < 27) ? w[((size_t)j * CB + c0 + c) * 9 + k] : 0.f;
        }
        __syncthreads();
#pragma unroll
        for (int c = 0; c < 8; c++) {
#pragma unroll
            for (int k = 0; k < 9; k++) {
                const float v = s_in[c][ty + k / 3][tx + k % 3];
                const float4* wr = (const float4*)&s_w[c][k][0];
#pragma unroll
                for (int q = 0; q < 7; q++) {
                    const float4 w4 = wr[q];
                    acc[q * 4 + 0] += v * w4.x;
                    acc[q * 4 + 1] += v * w4.y;
                    acc[q * 4 + 2] += v * w4.z;
                    acc[q * 4 + 3] += v * w4.w;
                }
            }
        }
        __syncthreads();
    }
    const int hw = (y0 + ty) * W_ + x0 + tx;
    float* op = omp + (size_t)half * B_ * 27 * HW + (size_t)b * 27 * HW;
#pragma unroll
    for (int j = 0; j < 27; j++)
        op[(size_t)j * HW + hw] = acc[j];
}

// ---------------- deformable bilinear sampling (reads conv partials) -------
__global__ void __launch_bounds__(256) deform_sample_kernel(
    const float* __restrict__ out1,
    const float* __restrict__ omp,   // [2][B][27][H][W]
    const float* __restrict__ boff,  // [27]
    float* __restrict__ sampled)
{
    const int idx = blockIdx.x * blockDim.x + threadIdx.x;
    if (idx >= B_ * KOFF * HW) return;
    const int hw = idx % HW;
    const int k  = (idx / HW) % KOFF;
    const int b  = idx / (HW * KOFF);
    const int h = hw / W_, w = hw % W_;

    const float* o0 = omp + (size_t)b * 27 * HW;
    const float* o1 = o0 + (size_t)B_ * 27 * HW;
    const float offx = o0[(size_t)k * HW + hw] + o1[(size_t)k * HW + hw] + boff[k];
    const float offy = o0[(size_t)(KOFF + k) * HW + hw] + o1[(size_t)(KOFF + k) * HW + hw]
                     + boff[KOFF + k];
    const float mraw = o0[(size_t)(18 + k) * HW + hw] + o1[(size_t)(18 + k) * HW + hw]
                     + boff[18 + k];
    const float mval = 1.f / (1.f + expf(-mraw));

    const float py = (float)(h + k / 3 - 1) + offy;
    const float px = (float)(w + k % 3 - 1) + offx;
    const float y0f = floorf(py), x0f = floorf(px);
    const int y0 = (int)y0f, x0 = (int)x0f;
    const float wy1 = py - y0f, wx1 = px - x0f;
    const float wy0 = 1.f - wy1, wx0 = 1.f - wx1;
    const int y1 = y0 + 1, x1 = x0 + 1;
    const bool vy0 = (y0 >= 0) && (y0 < H_), vy1 = (y1 >= 0) && (y1 < H_);
    const bool vx0 = (x0 >= 0) && (x0 < W_), vx1 = (x1 >= 0) && (x1 < W_);
    const int cy0 = min(max(y0, 0), H_ - 1), cy1 = min(max(y1, 0), H_ - 1);
    const int cx0 = min(max(x0, 0), W_ - 1), cx1 = min(max(x1, 0), W_ - 1);
    const int i00 = cy0 * W_ + cx0, i01 = cy0 * W_ + cx1;
    const int i10 = cy1 * W_ + cx0, i11 = cy1 * W_ + cx1;
    const float w00 = (vy0 && vx0) ? wy0 * wx0 * mval : 0.f;
    const float w01 = (vy0 && vx1) ? wy0 * wx1 * mval : 0.f;
    const float w10 = (vy1 && vx0) ? wy1 * wx0 * mval : 0.f;
    const float w11 = (vy1 && vx1) ? wy1 * wx1 * mval : 0.f;

    const float* base = out1 + (size_t)b * CB * HW;
    const size_t obase = (size_t)b * CB * KOFF * HW + (size_t)k * HW + hw;
#pragma unroll 8
    for (int c = 0; c < CB; c++) {
        const float* p = base + (size_t)c * HW;
        float v = w00 * p[i00] + w01 * p[i01] + w10 * p[i10] + w11 * p[i11];
        sampled[obase + (size_t)c * (KOFF * HW)] = round_tf32(v);
    }
}

// ---------------- host launcher --------------------------------------------
extern "C" void kernel_launch(void* const* d_in, const int* in_sizes, int n_in,
                              void* d_out, int out_size)
{
    const float* x     = (const float*)d_in[0];
    const float* w1    = (const float*)d_in[1];
    const float* gn1s  = (const float*)d_in[2];
    const float* gn1b  = (const float*)d_in[3];
    const float* w_off = (const float*)d_in[4];
    const float* b_off = (const float*)d_in[5];
    const float* w2    = (const float*)d_in[6];
    const float* gn2s  = (const float*)d_in[7];
    const float* gn2b  = (const float*)d_in[8];
    const float* w3    = (const float*)d_in[9];
    const float* gn3s  = (const float*)d_in[10];
    const float* gn3b  = (const float*)d_in[11];
    float* out = (float*)d_out;

    float *p_out1, *p_omp, *p_samp, *p_out2, *p_out3, *p_at1, *p_at2, *p_at3;
    cudaGetSymbolAddress((void**)&p_out1, g_out1);
    cudaGetSymbolAddress((void**)&p_omp,  g_omp);
    cudaGetSymbolAddress((void**)&p_samp, g_samp);
    cudaGetSymbolAddress((void**)&p_out2, g_out2);
    cudaGetSymbolAddress((void**)&p_out3, g_out3);
    cudaGetSymbolAddress((void**)&p_at1,  g_at1);
    cudaGetSymbolAddress((void**)&p_at2,  g_at2);
    cudaGetSymbolAddress((void**)&p_at3,  g_at3);

    cudaFuncSetAttribute(tf32_gemm_kernel,
                         cudaFuncAttributeMaxDynamicSharedMemorySize, GEMM_SMEM);

    // 0a) transpose + round weights
    transpose_round_kernel<<<dim3(CIN/32, CB/32), dim3(32, 8)>>>(w1, p_at1, CB, CIN);
    transpose_round_kernel<<<dim3(CB*KOFF/32, CB/32), dim3(32, 8)>>>(w2, p_at2, CB, CB*KOFF);
    transpose_round_kernel<<<dim3(CB/32, CIN/32), dim3(32, 8)>>>(w3, p_at3, CIN, CB);
    // 0b) round x into g_out3 (GEMM1's B; g_out3 is rewritten later by GEMM3)
    round_copy_kernel<<<(B_*CIN*HW/4 + 255)/256, 256>>>(x, p_out3, B_*CIN*HW/4);

    // 1) out1 = w1 @ x            (M=256, K=1024, N=4096, batch 4)
    tf32_gemm_kernel<<<dim3(HW/128, CB/128, B_), 256, GEMM_SMEM>>>(
        p_at1, p_out3, p_out1, CB, HW, CIN, (size_t)CIN*HW, (size_t)CB*HW);

    // 2) GN1 + ReLU (in place, full precision — feeds conv/deform)
    gn_relu_kernel<false><<<B_*32, 512>>>(p_out1, gn1s, gn1b, CB, CB/32);

    // 3) offset conv, channel-split 2 -> partials (combined inside deform)
    conv_off_kernel<<<dim3(W_/16, H_/16, B_*2), 256>>>(p_out1, w_off, p_omp);

    // 4) deform sample * sigmoid(mask) -> rounded [b][c*9+k][hw]
    deform_sample_kernel<<<(B_*KOFF*HW + 255)/256, 256>>>(p_out1, p_omp, b_off, p_samp);

    // 5) out2 = w2_flat @ sampled (M=256, K=2304, N=4096, batch 4)
    tf32_gemm_kernel<<<dim3(HW/128, CB/128, B_), 256, GEMM_SMEM>>>(
        p_at2, p_samp, p_out2, CB, HW, CB*KOFF,
        (size_t)CB*KOFF*HW, (size_t)CB*HW);

    // 6) GN2 + ReLU (in place, rounded — feeds GEMM3 B)
    gn_relu_kernel<true><<<B_*32, 512>>>(p_out2, gn2s, gn2b, CB, CB/32);

    // 7) out3 = w3 @ out2         (M=1024, K=256, N=4096, batch 4)
    tf32_gemm_kernel<<<dim3(HW/128, CIN/128, B_), 256, GEMM_SMEM>>>(
        p_at3, p_out2, p_out3, CIN, HW, CB, (size_t)CB*HW, (size_t)CIN*HW);

    // 8) out = relu(GN3(out3) + x)
    gn_res_relu_kernel<<<B_*32, 1024>>>(p_out3, x, gn3s, gn3b, out, CIN, CIN/32);
}

// round 8
// speedup vs baseline: 3.0180x; 1.0374x over previous
#include <cuda_runtime.h>
#include <math.h>

#define B_   4
#define CIN  1024
#define CB   256
#define H_   64
#define W_   64
#define HW   (H_*W_)
#define KOFF 9

// ---------------- scratch (device globals; no runtime allocation) ----------
__device__ float g_out1[(size_t)B_*CB*HW];              // 16.7 MB
__device__ float g_omp [(size_t)2*B_*27*HW];            // conv partial sums
__device__ float g_samp[(size_t)B_*CB*KOFF*HW];         // 151 MB
__device__ float g_out2[(size_t)B_*CB*HW];              // 16.7 MB
__device__ float g_out3[(size_t)B_*CIN*HW];             // 67 MB (also rounded-x before GEMM3)
__device__ float g_ap1[(size_t)CIN*CB];                 // w1 perm  [K/8][M/16][32][4]
__device__ float g_ap2[(size_t)CB*KOFF*CB];             // w2 perm
__device__ float g_ap3[(size_t)CB*CIN];                 // w3 perm

__device__ __forceinline__ unsigned f2tf32(float f) {
    unsigned u;
    asm("cvt.rna.tf32.f32 %0, %1;" : "=r"(u) : "f"(f));
    return u;
}
__device__ __forceinline__ float round_tf32(float f) {
    return __uint_as_float(f2tf32(f));
}

__device__ __forceinline__ void cp_async16(void* smem_dst, const void* gsrc) {
    unsigned s = (unsigned)__cvta_generic_to_shared(smem_dst);
    asm volatile("cp.async.cg.shared.global [%0], [%1], 16;\n" :: "r"(s), "l"(gsrc));
}
__device__ __forceinline__ void cp_commit() {
    asm volatile("cp.async.commit_group;\n");
}
template <int N>
__device__ __forceinline__ void cp_wait() {
    asm volatile("cp.async.wait_group %0;\n" :: "n"(N));
}

// ---------------- batched TF32 tensor-core GEMM: C[b] = Aperm @ B[b] -------
// AP: weights in fragment-permuted order: [K/8][M/16][lane32][4xf32], each
//     16B chunk = one thread's m16n8k8 A-fragment (pre-rounded tf32 bits).
// B:  [K,N] row-major (pre-rounded tf32 bits). C: [M,N].
// Requires M%128==0, N%128==0, K%16==0, K/16>=3.
// CTA tile 128x128, 4-stage cp.async pipeline, K=16 per stage.
// 8 warps as 2(M)x4(N), warp tile 64x32, mma m16n8k8.tf32.
#define GSTAGE   4
#define GK       16
#define GROW     136
#define A_STG    (GK * 128)            // floats per A stage (8 KB)
#define B_STG    (GK * GROW)           // floats per B stage (8.5 KB)
#define GEMM_SMEM ((GSTAGE * (A_STG + B_STG)) * 4)
__global__ void __launch_bounds__(256, 2) tf32_gemm_kernel(
    const float* __restrict__ AP, const float* __restrict__ Bm,
    float* __restrict__ Cm, int M, int N, int K,
    size_t strideB, size_t strideC)
{
    extern __shared__ float sm_[];
    // A stage layout: [kb2(2)][mb(8)][lane(32)][4]
    float (*As)[2][8][32][4] = (float(*)[2][8][32][4])sm_;
    float (*Bs)[GK][GROW]    = (float(*)[GK][GROW])(sm_ + GSTAGE * A_STG);

    const float* Bp = Bm + (size_t)blockIdx.z * strideB;
    float*       Cp = Cm + (size_t)blockIdx.z * strideC;
    const int bm = blockIdx.y * 128;
    const int bn = blockIdx.x * 128;
    const int nmb = M >> 4;            // m-blocks in full matrix
    const int mb0 = bm >> 4;           // first m-block of this CTA

    const int tid  = threadIdx.x;
    const int lane = tid & 31;
    const int warp = tid >> 5;
    const int wmb = (warp & 1) * 4;     // warp m-block offset (x16 rows)
    const int wn  = (warp >> 1) * 32;   // warp N offset
    const int grp = lane >> 2;          // 0..7
    const int tig = lane & 3;           // 0..3

    float acc[4][4][4];
#pragma unroll
    for (int mi = 0; mi < 4; mi++)
#pragma unroll
        for (int ni = 0; ni < 4; ni++)
#pragma unroll
            for (int i = 0; i < 4; i++) acc[mi][ni][i] = 0.f;

    const int nstage = K / GK;

    // stage loader: A = 512 chunks (2/thread), B = 512 chunks (2/thread)
#define LOAD_STAGE(buf, ks)                                                   \
    do {                                                                      \
        _Pragma("unroll")                                                     \
        for (int j = 0; j < 2; j++) {                                         \
            const int id  = tid + 256 * j;                                    \
            const int kb2 = id >> 8;                                          \
            const int rem = id & 255;                                         \
            const int mb  = rem >> 5;                                         \
            const int ln  = rem & 31;                                         \
            cp_async16(&As[buf][kb2][mb][ln][0],                              \
                AP + (((size_t)((ks) * 2 + kb2) * nmb + mb0 + mb) * 32 + ln) * 4); \
            const int kk  = id >> 5;                                          \
            const int col = (id & 31) * 4;                                    \
            cp_async16(&Bs[buf][kk][col],                                     \
                Bp + (size_t)((ks) * GK + kk) * N + bn + col);                \
        }                                                                     \
    } while (0)

    // prologue: stages 0..2
    LOAD_STAGE(0, 0); cp_commit();
    LOAD_STAGE(1, 1); cp_commit();
    LOAD_STAGE(2, 2); cp_commit();

    int cur = 0;
    for (int ks = 0; ks < nstage; ks++) {
        cp_wait<2>();
        __syncthreads();

#pragma unroll
        for (int kb2 = 0; kb2 < 2; kb2++) {
            unsigned a[4][4], b[4][2];
#pragma unroll
            for (int mi = 0; mi < 4; mi++) {
                const float4 av = *(const float4*)&As[cur][kb2][wmb + mi][lane][0];
                a[mi][0] = __float_as_uint(av.x);
                a[mi][1] = __float_as_uint(av.y);
                a[mi][2] = __float_as_uint(av.z);
                a[mi][3] = __float_as_uint(av.w);
            }
#pragma unroll
            for (int ni = 0; ni < 4; ni++) {
                const int n = wn + ni * 8 + grp;
                b[ni][0] = __float_as_uint(Bs[cur][kb2 * 8 + tig    ][n]);
                b[ni][1] = __float_as_uint(Bs[cur][kb2 * 8 + tig + 4][n]);
            }
#pragma unroll
            for (int mi = 0; mi < 4; mi++)
#pragma unroll
                for (int ni = 0; ni < 4; ni++) {
                    asm volatile(
                        "mma.sync.aligned.m16n8k8.row.col.f32.tf32.tf32.f32 "
                        "{%0,%1,%2,%3}, {%4,%5,%6,%7}, {%8,%9}, {%0,%1,%2,%3};\n"
                        : "+f"(acc[mi][ni][0]), "+f"(acc[mi][ni][1]),
                          "+f"(acc[mi][ni][2]), "+f"(acc[mi][ni][3])
                        : "r"(a[mi][0]), "r"(a[mi][1]), "r"(a[mi][2]), "r"(a[mi][3]),
                          "r"(b[ni][0]), "r"(b[ni][1]));
                }
        }

        if (ks + 3 < nstage) {
            const int buf = (cur + 3) & 3;
            LOAD_STAGE(buf, ks + 3);
        }
        cp_commit();
        cur = (cur + 1) & 3;
    }

    // epilogue: row = bm + (warp&1)*64 + mi*16 + grp (+8)
#pragma unroll
    for (int mi = 0; mi < 4; mi++) {
        const int row = bm + (warp & 1) * 64 + mi * 16 + grp;
#pragma unroll
        for (int ni = 0; ni < 4; ni++) {
            const int col = bn + wn + ni * 8 + tig * 2;
            float2 v0 = make_float2(acc[mi][ni][0], acc[mi][ni][1]);
            float2 v1 = make_float2(acc[mi][ni][2], acc[mi][ni][3]);
            *(float2*)(Cp + (size_t)row * N + col)       = v0;
            *(float2*)(Cp + (size_t)(row + 8) * N + col) = v1;
        }
    }
#undef LOAD_STAGE
}

// ---------------- weight permute + tf32-round: A[M][K] -> fragment order ---
// AP[((kb*(M/16)+mb)*32 + lane)*4 + v] = round(A[mb*16+grp(v)][kb*8+tig(v)])
__global__ void aperm_round_kernel(const float* __restrict__ A,
                                   float* __restrict__ AP, int M, int K)
{
    const int i = blockIdx.x * blockDim.x + threadIdx.x;
    if (i >= M * K) return;
    const int blk = i >> 7;
    const int l   = (i >> 2) & 31;
    const int v   = i & 3;
    const int nmb = M >> 4;
    const int kb = blk / nmb, mb = blk % nmb;
    const int tig = (l & 3) + ((v >> 1) << 2);
    const int grp = (l >> 2) + ((v & 1) << 3);
    const int m = mb * 16 + grp;
    const int k = kb * 8 + tig;
    AP[i] = round_tf32(A[(size_t)m * K + k]);
}

// ---------------- tf32 round-copy (for x -> GEMM1 B) -----------------------
__global__ void round_copy_kernel(const float* __restrict__ in,
                                  float* __restrict__ out, int n4)
{
    const int i = blockIdx.x * blockDim.x + threadIdx.x;
    if (i >= n4) return;
    float4 v = ((const float4*)in)[i];
    v.x = round_tf32(v.x); v.y = round_tf32(v.y);
    v.z = round_tf32(v.z); v.w = round_tf32(v.w);
    ((float4*)out)[i] = v;
}

// ---------------- block reduction helper -----------------------------------
__device__ __forceinline__ void block_reduce2(float& s, float& ss) {
#pragma unroll
    for (int o = 16; o > 0; o >>= 1) {
        s  += __shfl_down_sync(0xFFFFFFFFu, s,  o);
        ss += __shfl_down_sync(0xFFFFFFFFu, ss, o);
    }
    __shared__ float as_[32], ass_[32];
    int lane = threadIdx.x & 31, wid = threadIdx.x >> 5;
    if (lane == 0) { as_[wid] = s; ass_[wid] = ss; }
    __syncthreads();
    int nw = blockDim.x >> 5;
    if (wid == 0) {
        s  = (lane < nw) ? as_[lane]  : 0.f;
        ss = (lane < nw) ? ass_[lane] : 0.f;
#pragma unroll
        for (int o = 16; o > 0; o >>= 1) {
            s  += __shfl_down_sync(0xFFFFFFFFu, s,  o);
            ss += __shfl_down_sync(0xFFFFFFFFu, ss, o);
        }
    }
}

// ---------------- GroupNorm (+ReLU), in-place; one block per (b, group) ----
template <bool ROUND>
__global__ void gn_relu_kernel(float* __restrict__ data,
                               const float* __restrict__ scale,
                               const float* __restrict__ bias,
                               int C, int cpg)
{
    const int G  = C / cpg;
    const int b  = blockIdx.x / G;
    const int gi = blockIdx.x % G;
    float* p = data + ((size_t)b * C + (size_t)gi * cpg) * HW;
    const int n4 = (cpg * HW) >> 2;

    float s = 0.f, ss = 0.f;
    for (int i = threadIdx.x; i < n4; i += blockDim.x) {
        float4 v = ((const float4*)p)[i];
        s  += v.x + v.y + v.z + v.w;
        ss += v.x * v.x + v.y * v.y + v.z * v.z + v.w * v.w;
    }
    block_reduce2(s, ss);
    __shared__ float sh_mean, sh_rstd;
    if (threadIdx.x == 0) {
        const float n = (float)(cpg * HW);
        float mean = s / n;
        float var  = ss / n - mean * mean;
        sh_mean = mean;
        sh_rstd = rsqrtf(var + 1e-5f);
    }
    __syncthreads();
    const float mean = sh_mean, rstd = sh_rstd;
    for (int i = threadIdx.x; i < n4; i += blockDim.x) {
        int c = gi * cpg + (i * 4) / HW;
        const float a = rstd * scale[c];
        const float d = bias[c] - mean * a;
        float4 v = ((const float4*)p)[i];
        v.x = fmaxf(v.x * a + d, 0.f);
        v.y = fmaxf(v.y * a + d, 0.f);
        v.z = fmaxf(v.z * a + d, 0.f);
        v.w = fmaxf(v.w * a + d, 0.f);
        if (ROUND) {
            v.x = round_tf32(v.x); v.y = round_tf32(v.y);
            v.z = round_tf32(v.z); v.w = round_tf32(v.w);
        }
        ((float4*)p)[i] = v;
    }
}

// ---------------- GN3 + residual + ReLU -> output --------------------------
__global__ void gn_res_relu_kernel(const float* __restrict__ in,
                                   const float* __restrict__ xres,
                                   const float* __restrict__ scale,
                                   const float* __restrict__ bias,
                                   float* __restrict__ out,
                                   int C, int cpg)
{
    const int G  = C / cpg;
    const int b  = blockIdx.x / G;
    const int gi = blockIdx.x % G;
    const size_t base = ((size_t)b * C + (size_t)gi * cpg) * HW;
    const float* p = in + base;
    const float* r = xres + base;
    float* o = out + base;
    const int n4 = (cpg * HW) >> 2;

    float s = 0.f, ss = 0.f;
    for (int i = threadIdx.x; i < n4; i += blockDim.x) {
        float4 v = ((const float4*)p)[i];
        s  += v.x + v.y + v.z + v.w;
        ss += v.x * v.x + v.y * v.y + v.z * v.z + v.w * v.w;
    }
    block_reduce2(s, ss);
    __shared__ float sh_mean, sh_rstd;
    if (threadIdx.x == 0) {
        const float n = (float)(cpg * HW);
        float mean = s / n;
        float var  = ss / n - mean * mean;
        sh_mean = mean;
        sh_rstd = rsqrtf(var + 1e-5f);
    }
    __syncthreads();
    const float mean = sh_mean, rstd = sh_rstd;
    for (int i = threadIdx.x; i < n4; i += blockDim.x) {
        int c = gi * cpg + (i * 4) / HW;
        const float a = rstd * scale[c];
        const float d = bias[c] - mean * a;
        float4 v = ((const float4*)p)[i];
        float4 rr = ((const float4*)r)[i];
        v.x = fmaxf(v.x * a + d + rr.x, 0.f);
        v.y = fmaxf(v.y * a + d + rr.y, 0.f);
        v.z = fmaxf(v.z * a + d + rr.z, 0.f);
        v.w = fmaxf(v.w * a + d + rr.w, 0.f);
        ((float4*)o)[i] = v;
    }
}

// ---------------- 3x3 offset conv (27 out ch), pad=1, channel-split 2 ------
__global__ void __launch_bounds__(256) conv_off_kernel(
    const float* __restrict__ in,    // g_out1 [B][CB][H][W]
    const float* __restrict__ w,     // [27][CB][3][3]
    float* __restrict__ omp)         // [2][B][27][H][W]
{
    const int bx = blockIdx.x;   // 0..3
    const int by = blockIdx.y;   // 0..3
    const int b    = blockIdx.z >> 1;
    const int half = blockIdx.z & 1;
    const int tid = threadIdx.x;
    const int tx = tid & 15, ty = tid >> 4;

    __shared__ float s_in[8][18][18];
    __shared__ float s_w[8][9][28];     // j padded 27->28 (zero)

    float acc[28];
#pragma unroll
    for (int j = 0; j < 28; j++) acc[j] = 0.f;

    const int x0 = bx * 16, y0 = by * 16;
    const int cbase = half * 128;
    const float* inb = in + (size_t)b * CB * HW;

    for (int c0 = cbase; c0 < cbase + 128; c0 += 8) {
        for (int e = tid; e < 8 * 18 * 18; e += 256) {
            int c = e / 324;
            int r = (e / 18) % 18;
            int col = e % 18;
            int y = y0 + r - 1, x = x0 + col - 1;
            float v = 0.f;
            if (y >= 0 && y < H_ && x >= 0 && x < W_)
                v = inb[(size_t)(c0 + c) * HW + y * W_ + x];
            s_in[c][r][col] = v;
        }
        for (int e = tid; e < 8 * 9 * 28; e += 256) {
            int c = e / (9 * 28);
            int k = (e / 28) % 9;
            int j = e % 28;
            s_w[c][k][j] = (j < 27) ? w[((size_t)j * CB + c0 + c) * 9 + k] : 0.f;
        }
        __syncthreads();
#pragma unroll
        for (int c = 0; c < 8; c++) {
#pragma unroll
            for (int k = 0; k < 9; k++) {
                const float v = s_in[c][ty + k / 3][tx + k % 3];
                const float4* wr = (const float4*)&s_w[c][k][0];
#pragma unroll
                for (int q = 0; q < 7; q++) {
                    const float4 w4 = wr[q];
                    acc[q * 4 + 0] += v * w4.x;
                    acc[q * 4 + 1] += v * w4.y;
                    acc[q * 4 + 2] += v * w4.z;
                    acc[q * 4 + 3] += v * w4.w;
                }
            }
        }
        __syncthreads();
    }
    const int hw = (y0 + ty) * W_ + x0 + tx;
    float* op = omp + (size_t)half * B_ * 27 * HW + (size_t)b * 27 * HW;
#pragma unroll
    for (int j = 0; j < 27; j++)
        op[(size_t)j * HW + hw] = acc[j];
}

// ---------------- deformable bilinear sampling (reads conv partials) -------
__global__ void __launch_bounds__(256) deform_sample_kernel(
    const float* __restrict__ out1,
    const float* __restrict__ omp,   // [2][B][27][H][W]
    const float* __restrict__ boff,  // [27]
    float* __restrict__ sampled)
{
    const int idx = blockIdx.x * blockDim.x + threadIdx.x;
    if (idx >= B_ * KOFF * HW) return;
    const int hw = idx % HW;
    const int k  = (idx / HW) % KOFF;
    const int b  = idx / (HW * KOFF);
    const int h = hw / W_, w = hw % W_;

    const float* o0 = omp + (size_t)b * 27 * HW;
    const float* o1 = o0 + (size_t)B_ * 27 * HW;
    const float offx = o0[(size_t)k * HW + hw] + o1[(size_t)k * HW + hw] + boff[k];
    const float offy = o0[(size_t)(KOFF + k) * HW + hw] + o1[(size_t)(KOFF + k) * HW + hw]
                     + boff[KOFF + k];
    const float mraw = o0[(size_t)(18 + k) * HW + hw] + o1[(size_t)(18 + k) * HW + hw]
                     + boff[18 + k];
    const float mval = 1.f / (1.f + expf(-mraw));

    const float py = (float)(h + k / 3 - 1) + offy;
    const float px = (float)(w + k % 3 - 1) + offx;
    const float y0f = floorf(py), x0f = floorf(px);
    const int y0 = (int)y0f, x0 = (int)x0f;
    const float wy1 = py - y0f, wx1 = px - x0f;
    const float wy0 = 1.f - wy1, wx0 = 1.f - wx1;
    const int y1 = y0 + 1, x1 = x0 + 1;
    const bool vy0 = (y0 >= 0) && (y0 < H_), vy1 = (y1 >= 0) && (y1 < H_);
    const bool vx0 = (x0 >= 0) && (x0 < W_), vx1 = (x1 >= 0) && (x1 < W_);
    const int cy0 = min(max(y0, 0), H_ - 1), cy1 = min(max(y1, 0), H_ - 1);
    const int cx0 = min(max(x0, 0), W_ - 1), cx1 = min(max(x1, 0), W_ - 1);
    const int i00 = cy0 * W_ + cx0, i01 = cy0 * W_ + cx1;
    const int i10 = cy1 * W_ + cx0, i11 = cy1 * W_ + cx1;
    const float w00 = (vy0 && vx0) ? wy0 * wx0 * mval : 0.f;
    const float w01 = (vy0 && vx1) ? wy0 * wx1 * mval : 0.f;
    const float w10 = (vy1 && vx0) ? wy1 * wx0 * mval : 0.f;
    const float w11 = (vy1 && vx1) ? wy1 * wx1 * mval : 0.f;

    const float* base = out1 + (size_t)b * CB * HW;
    const size_t obase = (size_t)b * CB * KOFF * HW + (size_t)k * HW + hw;
#pragma unroll 8
    for (int c = 0; c < CB; c++) {
        const float* p = base + (size_t)c * HW;
        float v = w00 * p[i00] + w01 * p[i01] + w10 * p[i10] + w11 * p[i11];
        sampled[obase + (size_t)c * (KOFF * HW)] = round_tf32(v);
    }
}

// ---------------- host launcher --------------------------------------------
extern "C" void kernel_launch(void* const* d_in, const int* in_sizes, int n_in,
                              void* d_out, int out_size)
{
    const float* x     = (const float*)d_in[0];
    const float* w1    = (const float*)d_in[1];
    const float* gn1s  = (const float*)d_in[2];
    const float* gn1b  = (const float*)d_in[3];
    const float* w_off = (const float*)d_in[4];
    const float* b_off = (const float*)d_in[5];
    const float* w2    = (const float*)d_in[6];
    const float* gn2s  = (const float*)d_in[7];
    const float* gn2b  = (const float*)d_in[8];
    const float* w3    = (const float*)d_in[9];
    const float* gn3s  = (const float*)d_in[10];
    const float* gn3b  = (const float*)d_in[11];
    float* out = (float*)d_out;

    float *p_out1, *p_omp, *p_samp, *p_out2, *p_out3, *p_ap1, *p_ap2, *p_ap3;
    cudaGetSymbolAddress((void**)&p_out1, g_out1);
    cudaGetSymbolAddress((void**)&p_omp,  g_omp);
    cudaGetSymbolAddress((void**)&p_samp, g_samp);
    cudaGetSymbolAddress((void**)&p_out2, g_out2);
    cudaGetSymbolAddress((void**)&p_out3, g_out3);
    cudaGetSymbolAddress((void**)&p_ap1,  g_ap1);
    cudaGetSymbolAddress((void**)&p_ap2,  g_ap2);
    cudaGetSymbolAddress((void**)&p_ap3,  g_ap3);

    cudaFuncSetAttribute(tf32_gemm_kernel,
                         cudaFuncAttributeMaxDynamicSharedMemorySize, GEMM_SMEM);

    // launch order puts gemm1 at captured index 3 (0-based) for ncu visibility
    // 0) permute+round w1; round x
    aperm_round_kernel<<<(CB*CIN + 255)/256, 256>>>(w1, p_ap1, CB, CIN);
    round_copy_kernel<<<(B_*CIN*HW/4 + 255)/256, 256>>>(x, p_out3, B_*CIN*HW/4);
    aperm_round_kernel<<<(CB*CB*KOFF + 255)/256, 256>>>(w2, p_ap2, CB, CB*KOFF);

    // 1) out1 = w1 @ x            (M=256, K=1024, N=4096, batch 4)
    tf32_gemm_kernel<<<dim3(HW/128, CB/128, B_), 256, GEMM_SMEM>>>(
        p_ap1, p_out3, p_out1, CB, HW, CIN, (size_t)CIN*HW, (size_t)CB*HW);

    // 2) GN1 + ReLU (in place, full precision — feeds conv/deform)
    gn_relu_kernel<false><<<B_*32, 512>>>(p_out1, gn1s, gn1b, CB, CB/32);

    // permute+round w3 (needed before gemm3)
    aperm_round_kernel<<<(CIN*CB + 255)/256, 256>>>(w3, p_ap3, CIN, CB);

    // 3) offset conv, channel-split 2 -> partials (combined inside deform)
    conv_off_kernel<<<dim3(W_/16, H_/16, B_*2), 256>>>(p_out1, w_off, p_omp);

    // 4) deform sample * sigmoid(mask) -> rounded [b][c*9+k][hw]
    deform_sample_kernel<<<(B_*KOFF*HW + 255)/256, 256>>>(p_out1, p_omp, b_off, p_samp);

    // 5) out2 = w2_flat @ sampled (M=256, K=2304, N=4096, batch 4)
    tf32_gemm_kernel<<<dim3(HW/128, CB/128, B_), 256, GEMM_SMEM>>>(
        p_ap2, p_samp, p_out2, CB, HW, CB*KOFF,
        (size_t)CB*KOFF*HW, (size_t)CB*HW);

    // 6) GN2 + ReLU (in place, rounded — feeds GEMM3 B)
    gn_relu_kernel<true><<<B_*32, 512>>>(p_out2, gn2s, gn2b, CB, CB/32);

    // 7) out3 = w3 @ out2         (M=1024, K=256, N=4096, batch 4)
    tf32_gemm_kernel<<<dim3(HW/128, CIN/128, B_), 256, GEMM_SMEM>>>(
        p_ap3, p_out2, p_out3, CIN, HW, CB, (size_t)CB*HW, (size_t)CIN*HW);

    // 8) out = relu(GN3(out3) + x)
    gn_res_relu_kernel<<<B_*32, 1024>>>(p_out3, x, gn3s, gn3b, out, CIN, CIN/32);
}

// round 9
// speedup vs baseline: 3.0552x; 1.0123x over previous
#include <cuda_runtime.h>
#include <math.h>

#define B_   4
#define CIN  1024
#define CB   256
#define H_   64
#define W_   64
#define HW   (H_*W_)
#define KOFF 9

// ---------------- scratch (device globals; no runtime allocation) ----------
__device__ float g_out1[(size_t)B_*CB*HW];              // 16.7 MB
__device__ float g_omp [(size_t)2*B_*27*HW];            // conv partial sums
__device__ float g_samp[(size_t)B_*CB*KOFF*HW];         // 151 MB
__device__ float g_out2[(size_t)B_*CB*HW];              // 16.7 MB
__device__ float g_out3[(size_t)B_*CIN*HW];             // 67 MB (also rounded-x before GEMM3)
__device__ float g_ap1[(size_t)CIN*CB];                 // w1 perm  [K/8][M/16][32][4]
__device__ float g_ap2[(size_t)CB*KOFF*CB];             // w2 perm
__device__ float g_ap3[(size_t)CB*CIN];                 // w3 perm

__device__ __forceinline__ unsigned f2tf32(float f) {
    unsigned u;
    asm("cvt.rna.tf32.f32 %0, %1;" : "=r"(u) : "f"(f));
    return u;
}
__device__ __forceinline__ float round_tf32(float f) {
    return __uint_as_float(f2tf32(f));
}

__device__ __forceinline__ void cp_async16(void* smem_dst, const void* gsrc) {
    unsigned s = (unsigned)__cvta_generic_to_shared(smem_dst);
    asm volatile("cp.async.cg.shared.global [%0], [%1], 16;\n" :: "r"(s), "l"(gsrc));
}
__device__ __forceinline__ void cp_commit() {
    asm volatile("cp.async.commit_group;\n");
}
template <int N>
__device__ __forceinline__ void cp_wait() {
    asm volatile("cp.async.wait_group %0;\n" :: "n"(N));
}

// ---------------- batched TF32 tensor-core GEMM: C[b] = Aperm @ B[b] -------
// AP: weights in fragment-permuted order: [K/8][M/16][lane32][4xf32], each
//     16B chunk = one thread's m16n8k8 A-fragment (pre-rounded tf32 bits).
// B:  [K,N] row-major (pre-rounded tf32 bits). C: [M,N].
// Requires M%128==0, N%128==0, K%32==0, K/32>=2.
// CTA tile 128x128, 3-stage cp.async pipeline, K=32 per stage (4 substeps).
// 8 warps as 2(M)x4(N), warp tile 64x32, mma m16n8k8.tf32.
#define GSTAGE   3
#define GK       32
#define GROW     136
#define A_STG    (GK * 128)            // floats per A stage (16 KB)
#define B_STG    (GK * GROW)           // floats per B stage (17.4 KB)
#define GEMM_SMEM ((GSTAGE * (A_STG + B_STG)) * 4)
__global__ void __launch_bounds__(256, 2) tf32_gemm_kernel(
    const float* __restrict__ AP, const float* __restrict__ Bm,
    float* __restrict__ Cm, int M, int N, int K,
    size_t strideB, size_t strideC)
{
    extern __shared__ float sm_[];
    // A stage layout: [kb2(4)][mb(8)][lane(32)][4]
    float (*As)[4][8][32][4] = (float(*)[4][8][32][4])sm_;
    float (*Bs)[GK][GROW]    = (float(*)[GK][GROW])(sm_ + GSTAGE * A_STG);

    const float* Bp = Bm + (size_t)blockIdx.z * strideB;
    float*       Cp = Cm + (size_t)blockIdx.z * strideC;
    const int bm = blockIdx.y * 128;
    const int bn = blockIdx.x * 128;
    const int nmb = M >> 4;            // m-blocks in full matrix
    const int mb0 = bm >> 4;           // first m-block of this CTA

    const int tid  = threadIdx.x;
    const int lane = tid & 31;
    const int warp = tid >> 5;
    const int wmb = (warp & 1) * 4;     // warp m-block offset (x16 rows)
    const int wn  = (warp >> 1) * 32;   // warp N offset
    const int grp = lane >> 2;          // 0..7
    const int tig = lane & 3;           // 0..3

    float acc[4][4][4];
#pragma unroll
    for (int mi = 0; mi < 4; mi++)
#pragma unroll
        for (int ni = 0; ni < 4; ni++)
#pragma unroll
            for (int i = 0; i < 4; i++) acc[mi][ni][i] = 0.f;

    const int nstage = K / GK;

    // stage loader: A = 1024 chunks (4/thread), B = 1024 chunks (4/thread)
#define LOAD_STAGE(buf, ks)                                                   \
    do {                                                                      \
        _Pragma("unroll")                                                     \
        for (int j = 0; j < 4; j++) {                                         \
            const int id  = tid + 256 * j;                                    \
            const int kb2 = id >> 8;                                          \
            const int rem = id & 255;                                         \
            const int mb  = rem >> 5;                                         \
            const int ln  = rem & 31;                                         \
            cp_async16(&As[buf][kb2][mb][ln][0],                              \
                AP + (((size_t)((ks) * 4 + kb2) * nmb + mb0 + mb) * 32 + ln) * 4); \
            const int kk  = id >> 5;                                          \
            const int col = (id & 31) * 4;                                    \
            cp_async16(&Bs[buf][kk][col],                                     \
                Bp + (size_t)((ks) * GK + kk) * N + bn + col);                \
        }                                                                     \
    } while (0)

    // prologue: stages 0..1
    LOAD_STAGE(0, 0); cp_commit();
    LOAD_STAGE(1, 1); cp_commit();

    int cur = 0;
    for (int ks = 0; ks < nstage; ks++) {
        cp_wait<1>();
        __syncthreads();

#pragma unroll
        for (int kb2 = 0; kb2 < 4; kb2++) {
            unsigned a[4][4], b[4][2];
#pragma unroll
            for (int mi = 0; mi < 4; mi++) {
                const float4 av = *(const float4*)&As[cur][kb2][wmb + mi][lane][0];
                a[mi][0] = __float_as_uint(av.x);
                a[mi][1] = __float_as_uint(av.y);
                a[mi][2] = __float_as_uint(av.z);
                a[mi][3] = __float_as_uint(av.w);
            }
#pragma unroll
            for (int ni = 0; ni < 4; ni++) {
                const int n = wn + ni * 8 + grp;
                b[ni][0] = __float_as_uint(Bs[cur][kb2 * 8 + tig    ][n]);
                b[ni][1] = __float_as_uint(Bs[cur][kb2 * 8 + tig + 4][n]);
            }
#pragma unroll
            for (int mi = 0; mi < 4; mi++)
#pragma unroll
                for (int ni = 0; ni < 4; ni++) {
                    asm volatile(
                        "mma.sync.aligned.m16n8k8.row.col.f32.tf32.tf32.f32 "
                        "{%0,%1,%2,%3}, {%4,%5,%6,%7}, {%8,%9}, {%0,%1,%2,%3};\n"
                        : "+f"(acc[mi][ni][0]), "+f"(acc[mi][ni][1]),
                          "+f"(acc[mi][ni][2]), "+f"(acc[mi][ni][3])
                        : "r"(a[mi][0]), "r"(a[mi][1]), "r"(a[mi][2]), "r"(a[mi][3]),
                          "r"(b[ni][0]), "r"(b[ni][1]));
                }
        }

        if (ks + 2 < nstage) {
            const int buf = cur + 2 >= GSTAGE ? cur + 2 - GSTAGE : cur + 2;
            LOAD_STAGE(buf, ks + 2);
        }
        cp_commit();
        cur = cur + 1 >= GSTAGE ? 0 : cur + 1;
    }

    // epilogue: row = bm + (warp&1)*64 + mi*16 + grp (+8)
#pragma unroll
    for (int mi = 0; mi < 4; mi++) {
        const int row = bm + (warp & 1) * 64 + mi * 16 + grp;
#pragma unroll
        for (int ni = 0; ni < 4; ni++) {
            const int col = bn + wn + ni * 8 + tig * 2;
            float2 v0 = make_float2(acc[mi][ni][0], acc[mi][ni][1]);
            float2 v1 = make_float2(acc[mi][ni][2], acc[mi][ni][3]);
            *(float2*)(Cp + (size_t)row * N + col)       = v0;
            *(float2*)(Cp + (size_t)(row + 8) * N + col) = v1;
        }
    }
#undef LOAD_STAGE
}

// ---------------- weight permute + tf32-round: A[M][K] -> fragment order ---
__global__ void aperm_round_kernel(const float* __restrict__ A,
                                   float* __restrict__ AP, int M, int K)
{
    const int i = blockIdx.x * blockDim.x + threadIdx.x;
    if (i >= M * K) return;
    const int blk = i >> 7;
    const int l   = (i >> 2) & 31;
    const int v   = i & 3;
    const int nmb = M >> 4;
    const int kb = blk / nmb, mb = blk % nmb;
    const int tig = (l & 3) + ((v >> 1) << 2);
    const int grp = (l >> 2) + ((v & 1) << 3);
    const int m = mb * 16 + grp;
    const int k = kb * 8 + tig;
    AP[i] = round_tf32(A[(size_t)m * K + k]);
}

// ---------------- tf32 round-copy (for x -> GEMM1 B) -----------------------
__global__ void round_copy_kernel(const float* __restrict__ in,
                                  float* __restrict__ out, int n4)
{
    const int i = blockIdx.x * blockDim.x + threadIdx.x;
    if (i >= n4) return;
    float4 v = ((const float4*)in)[i];
    v.x = round_tf32(v.x); v.y = round_tf32(v.y);
    v.z = round_tf32(v.z); v.w = round_tf32(v.w);
    ((float4*)out)[i] = v;
}

// ---------------- block reduction helper -----------------------------------
__device__ __forceinline__ void block_reduce2(float& s, float& ss) {
#pragma unroll
    for (int o = 16; o > 0; o >>= 1) {
        s  += __shfl_down_sync(0xFFFFFFFFu, s,  o);
        ss += __shfl_down_sync(0xFFFFFFFFu, ss, o);
    }
    __shared__ float as_[32], ass_[32];
    int lane = threadIdx.x & 31, wid = threadIdx.x >> 5;
    if (lane == 0) { as_[wid] = s; ass_[wid] = ss; }
    __syncthreads();
    int nw = blockDim.x >> 5;
    if (wid == 0) {
        s  = (lane < nw) ? as_[lane]  : 0.f;
        ss = (lane < nw) ? ass_[lane] : 0.f;
#pragma unroll
        for (int o = 16; o > 0; o >>= 1) {
            s  += __shfl_down_sync(0xFFFFFFFFu, s,  o);
            ss += __shfl_down_sync(0xFFFFFFFFu, ss, o);
        }
    }
}

// ---------------- GroupNorm (+ReLU), in-place; one block per (b, group) ----
template <bool ROUND>
__global__ void gn_relu_kernel(float* __restrict__ data,
                               const float* __restrict__ scale,
                               const float* __restrict__ bias,
                               int C, int cpg)
{
    const int G  = C / cpg;
    const int b  = blockIdx.x / G;
    const int gi = blockIdx.x % G;
    float* p = data + ((size_t)b * C + (size_t)gi * cpg) * HW;
    const int n4 = (cpg * HW) >> 2;

    float s = 0.f, ss = 0.f;
    for (int i = threadIdx.x; i < n4; i += blockDim.x) {
        float4 v = ((const float4*)p)[i];
        s  += v.x + v.y + v.z + v.w;
        ss += v.x * v.x + v.y * v.y + v.z * v.z + v.w * v.w;
    }
    block_reduce2(s, ss);
    __shared__ float sh_mean, sh_rstd;
    if (threadIdx.x == 0) {
        const float n = (float)(cpg * HW);
        float mean = s / n;
        float var  = ss / n - mean * mean;
        sh_mean = mean;
        sh_rstd = rsqrtf(var + 1e-5f);
    }
    __syncthreads();
    const float mean = sh_mean, rstd = sh_rstd;
    for (int i = threadIdx.x; i < n4; i += blockDim.x) {
        int c = gi * cpg + (i * 4) / HW;
        const float a = rstd * scale[c];
        const float d = bias[c] - mean * a;
        float4 v = ((const float4*)p)[i];
        v.x = fmaxf(v.x * a + d, 0.f);
        v.y = fmaxf(v.y * a + d, 0.f);
        v.z = fmaxf(v.z * a + d, 0.f);
        v.w = fmaxf(v.w * a + d, 0.f);
        if (ROUND) {
            v.x = round_tf32(v.x); v.y = round_tf32(v.y);
            v.z = round_tf32(v.z); v.w = round_tf32(v.w);
        }
        ((float4*)p)[i] = v;
    }
}

// ---------------- GN3 + residual + ReLU -> output --------------------------
__global__ void gn_res_relu_kernel(const float* __restrict__ in,
                                   const float* __restrict__ xres,
                                   const float* __restrict__ scale,
                                   const float* __restrict__ bias,
                                   float* __restrict__ out,
                                   int C, int cpg)
{
    const int G  = C / cpg;
    const int b  = blockIdx.x / G;
    const int gi = blockIdx.x % G;
    const size_t base = ((size_t)b * C + (size_t)gi * cpg) * HW;
    const float* p = in + base;
    const float* r = xres + base;
    float* o = out + base;
    const int n4 = (cpg * HW) >> 2;

    float s = 0.f, ss = 0.f;
    for (int i = threadIdx.x; i < n4; i += blockDim.x) {
        float4 v = ((const float4*)p)[i];
        s  += v.x + v.y + v.z + v.w;
        ss += v.x * v.x + v.y * v.y + v.z * v.z + v.w * v.w;
    }
    block_reduce2(s, ss);
    __shared__ float sh_mean, sh_rstd;
    if (threadIdx.x == 0) {
        const float n = (float)(cpg * HW);
        float mean = s / n;
        float var  = ss / n - mean * mean;
        sh_mean = mean;
        sh_rstd = rsqrtf(var + 1e-5f);
    }
    __syncthreads();
    const float mean = sh_mean, rstd = sh_rstd;
    for (int i = threadIdx.x; i < n4; i += blockDim.x) {
        int c = gi * cpg + (i * 4) / HW;
        const float a = rstd * scale[c];
        const float d = bias[c] - mean * a;
        float4 v = ((const float4*)p)[i];
        float4 rr = ((const float4*)r)[i];
        v.x = fmaxf(v.x * a + d + rr.x, 0.f);
        v.y = fmaxf(v.y * a + d + rr.y, 0.f);
        v.z = fmaxf(v.z * a + d + rr.z, 0.f);
        v.w = fmaxf(v.w * a + d + rr.w, 0.f);
        ((float4*)o)[i] = v;
    }
}

// ---------------- 3x3 offset conv (27 out ch), pad=1, channel-split 2 ------
__global__ void __launch_bounds__(256) conv_off_kernel(
    const float* __restrict__ in,    // g_out1 [B][CB][H][W]
    const float* __restrict__ w,     // [27][CB][3][3]
    float* __restrict__ omp)         // [2][B][27][H][W]
{
    const int bx = blockIdx.x;   // 0..3
    const int by = blockIdx.y;   // 0..3
    const int b    = blockIdx.z >> 1;
    const int half = blockIdx.z & 1;
    const int tid = threadIdx.x;
    const int tx = tid & 15, ty = tid >> 4;

    __shared__ float s_in[8][18][18];
    __shared__ float s_w[8][9][28];     // j padded 27->28 (zero)

    float acc[28];
#pragma unroll
    for (int j = 0; j < 28; j++) acc[j] = 0.f;

    const int x0 = bx * 16, y0 = by * 16;
    const int cbase = half * 128;
    const float* inb = in + (size_t)b * CB * HW;

    for (int c0 = cbase; c0 < cbase + 128; c0 += 8) {
        for (int e = tid; e < 8 * 18 * 18; e += 256) {
            int c = e / 324;
            int r = (e / 18) % 18;
            int col = e % 18;
            int y = y0 + r - 1, x = x0 + col - 1;
            float v = 0.f;
            if (y >= 0 && y < H_ && x >= 0 && x < W_)
                v = inb[(size_t)(c0 + c) * HW + y * W_ + x];
            s_in[c][r][col] = v;
        }
        for (int e = tid; e < 8 * 9 * 28; e += 256) {
            int c = e / (9 * 28);
            int k = (e / 28) % 9;
            int j = e % 28;
            s_w[c][k][j] = (j < 27) ? w[((size_t)j * CB + c0 + c) * 9 + k] : 0.f;
        }
        __syncthreads();
#pragma unroll
        for (int c = 0; c < 8; c++) {
#pragma unroll
            for (int k = 0; k < 9; k++) {
                const float v = s_in[c][ty + k / 3][tx + k % 3];
                const float4* wr = (const float4*)&s_w[c][k][0];
#pragma unroll
                for (int q = 0; q < 7; q++) {
                    const float4 w4 = wr[q];
                    acc[q * 4 + 0] += v * w4.x;
                    acc[q * 4 + 1] += v * w4.y;
                    acc[q * 4 + 2] += v * w4.z;
                    acc[q * 4 + 3] += v * w4.w;
                }
            }
        }
        __syncthreads();
    }
    const int hw = (y0 + ty) * W_ + x0 + tx;
    float* op = omp + (size_t)half * B_ * 27 * HW + (size_t)b * 27 * HW;
#pragma unroll
    for (int j = 0; j < 27; j++)
        op[(size_t)j * HW + hw] = acc[j];
}

// ---------------- deformable bilinear sampling (reads conv partials) -------
__global__ void __launch_bounds__(256) deform_sample_kernel(
    const float* __restrict__ out1,
    const float* __restrict__ omp,   // [2][B][27][H][W]
    const float* __restrict__ boff,  // [27]
    float* __restrict__ sampled)
{
    const int idx = blockIdx.x * blockDim.x + threadIdx.x;
    if (idx >= B_ * KOFF * HW) return;
    const int hw = idx % HW;
    const int k  = (idx / HW) % KOFF;
    const int b  = idx / (HW * KOFF);
    const int h = hw / W_, w = hw % W_;

    const float* o0 = omp + (size_t)b * 27 * HW;
    const float* o1 = o0 + (size_t)B_ * 27 * HW;
    const float offx = o0[(size_t)k * HW + hw] + o1[(size_t)k * HW + hw] + boff[k];
    const float offy = o0[(size_t)(KOFF + k) * HW + hw] + o1[(size_t)(KOFF + k) * HW + hw]
                     + boff[KOFF + k];
    const float mraw = o0[(size_t)(18 + k) * HW + hw] + o1[(size_t)(18 + k) * HW + hw]
                     + boff[18 + k];
    const float mval = 1.f / (1.f + expf(-mraw));

    const float py = (float)(h + k / 3 - 1) + offy;
    const float px = (float)(w + k % 3 - 1) + offx;
    const float y0f = floorf(py), x0f = floorf(px);
    const int y0 = (int)y0f, x0 = (int)x0f;
    const float wy1 = py - y0f, wx1 = px - x0f;
    const float wy0 = 1.f - wy1, wx0 = 1.f - wx1;
    const int y1 = y0 + 1, x1 = x0 + 1;
    const bool vy0 = (y0 >= 0) && (y0 < H_), vy1 = (y1 >= 0) && (y1 < H_);
    const bool vx0 = (x0 >= 0) && (x0 < W_), vx1 = (x1 >= 0) && (x1 < W_);
    const int cy0 = min(max(y0, 0), H_ - 1), cy1 = min(max(y1, 0), H_ - 1);
    const int cx0 = min(max(x0, 0), W_ - 1), cx1 = min(max(x1, 0), W_ - 1);
    const int i00 = cy0 * W_ + cx0, i01 = cy0 * W_ + cx1;
    const int i10 = cy1 * W_ + cx0, i11 = cy1 * W_ + cx1;
    const float w00 = (vy0 && vx0) ? wy0 * wx0 * mval : 0.f;
    const float w01 = (vy0 && vx1) ? wy0 * wx1 * mval : 0.f;
    const float w10 = (vy1 && vx0) ? wy1 * wx0 * mval : 0.f;
    const float w11 = (vy1 && vx1) ? wy1 * wx1 * mval : 0.f;

    const float* base = out1 + (size_t)b * CB * HW;
    const size_t obase = (size_t)b * CB * KOFF * HW + (size_t)k * HW + hw;
#pragma unroll 8
    for (int c = 0; c < CB; c++) {
        const float* p = base + (size_t)c * HW;
        float v = w00 * p[i00] + w01 * p[i01] + w10 * p[i10] + w11 * p[i11];
        sampled[obase + (size_t)c * (KOFF * HW)] = round_tf32(v);
    }
}

// ---------------- host launcher --------------------------------------------
extern "C" void kernel_launch(void* const* d_in, const int* in_sizes, int n_in,
                              void* d_out, int out_size)
{
    const float* x     = (const float*)d_in[0];
    const float* w1    = (const float*)d_in[1];
    const float* gn1s  = (const float*)d_in[2];
    const float* gn1b  = (const float*)d_in[3];
    const float* w_off = (const float*)d_in[4];
    const float* b_off = (const float*)d_in[5];
    const float* w2    = (const float*)d_in[6];
    const float* gn2s  = (const float*)d_in[7];
    const float* gn2b  = (const float*)d_in[8];
    const float* w3    = (const float*)d_in[9];
    const float* gn3s  = (const float*)d_in[10];
    const float* gn3b  = (const float*)d_in[11];
    float* out = (float*)d_out;

    float *p_out1, *p_omp, *p_samp, *p_out2, *p_out3, *p_ap1, *p_ap2, *p_ap3;
    cudaGetSymbolAddress((void**)&p_out1, g_out1);
    cudaGetSymbolAddress((void**)&p_omp,  g_omp);
    cudaGetSymbolAddress((void**)&p_samp, g_samp);
    cudaGetSymbolAddress((void**)&p_out2, g_out2);
    cudaGetSymbolAddress((void**)&p_out3, g_out3);
    cudaGetSymbolAddress((void**)&p_ap1,  g_ap1);
    cudaGetSymbolAddress((void**)&p_ap2,  g_ap2);
    cudaGetSymbolAddress((void**)&p_ap3,  g_ap3);

    cudaFuncSetAttribute(tf32_gemm_kernel,
                         cudaFuncAttributeMaxDynamicSharedMemorySize, GEMM_SMEM);

    // launch order keeps gemm1 at captured index 3 (0-based) for ncu visibility
    aperm_round_kernel<<<(CB*CIN + 255)/256, 256>>>(w1, p_ap1, CB, CIN);
    round_copy_kernel<<<(B_*CIN*HW/4 + 255)/256, 256>>>(x, p_out3, B_*CIN*HW/4);
    aperm_round_kernel<<<(CB*CB*KOFF + 255)/256, 256>>>(w2, p_ap2, CB, CB*KOFF);

    // 1) out1 = w1 @ x            (M=256, K=1024, N=4096, batch 4)
    tf32_gemm_kernel<<<dim3(HW/128, CB/128, B_), 256, GEMM_SMEM>>>(
        p_ap1, p_out3, p_out1, CB, HW, CIN, (size_t)CIN*HW, (size_t)CB*HW);

    // 2) GN1 + ReLU (in place, full precision — feeds conv/deform)
    gn_relu_kernel<false><<<B_*32, 512>>>(p_out1, gn1s, gn1b, CB, CB/32);

    // permute+round w3 (needed before gemm3)
    aperm_round_kernel<<<(CIN*CB + 255)/256, 256>>>(w3, p_ap3, CIN, CB);

    // 3) offset conv, channel-split 2 -> partials (combined inside deform)
    conv_off_kernel<<<dim3(W_/16, H_/16, B_*2), 256>>>(p_out1, w_off, p_omp);

    // 4) deform sample * sigmoid(mask) -> rounded [b][c*9+k][hw]
    deform_sample_kernel<<<(B_*KOFF*HW + 255)/256, 256>>>(p_out1, p_omp, b_off, p_samp);

    // 5) out2 = w2_flat @ sampled (M=256, K=2304, N=4096, batch 4)
    tf32_gemm_kernel<<<dim3(HW/128, CB/128, B_), 256, GEMM_SMEM>>>(
        p_ap2, p_samp, p_out2, CB, HW, CB*KOFF,
        (size_t)CB*KOFF*HW, (size_t)CB*HW);

    // 6) GN2 + ReLU (in place, rounded — feeds GEMM3 B)
    gn_relu_kernel<true><<<B_*32, 512>>>(p_out2, gn2s, gn2b, CB, CB/32);

    // 7) out3 = w3 @ out2         (M=1024, K=256, N=4096, batch 4)
    tf32_gemm_kernel<<<dim3(HW/128, CIN/128, B_), 256, GEMM_SMEM>>>(
        p_ap3, p_out2, p_out3, CIN, HW, CB, (size_t)CB*HW, (size_t)CIN*HW);

    // 8) out = relu(GN3(out3) + x)
    gn_res_relu_kernel<<<B_*32, 1024>>>(p_out3, x, gn3s, gn3b, out, CIN, CIN/32);
}

// round 10
// speedup vs baseline: 3.2493x; 1.0635x over previous
#include <cuda_runtime.h>
#include <math.h>

#define B_   4
#define CIN  1024
#define CB   256
#define H_   64
#define W_   64
#define HW   (H_*W_)
#define KOFF 9

// ---------------- scratch (device globals; no runtime allocation) ----------
__device__ float g_out1[(size_t)B_*CB*HW];              // 16.7 MB
__device__ float g_omp [(size_t)4*B_*27*HW];            // conv partial sums (4-way)
__device__ float g_samp[(size_t)B_*CB*KOFF*HW];         // 151 MB
__device__ float g_out2[(size_t)B_*CB*HW];              // 16.7 MB
__device__ float g_out3[(size_t)B_*CIN*HW];             // 67 MB (also rounded-x before GEMM3)
__device__ float g_ap1[(size_t)CIN*CB];                 // w1 perm  [K/8][M/16][32][4]
__device__ float g_ap2[(size_t)CB*KOFF*CB];             // w2 perm
__device__ float g_ap3[(size_t)CB*CIN];                 // w3 perm
__device__ float g_gnp[(size_t)B_*32*32*2];             // GN3 tile partials [b][g][tile][2]
__device__ float g_gn3[(size_t)B_*32*2];                // GN3 mean/rstd per (b,g)

__device__ __forceinline__ unsigned f2tf32(float f) {
    unsigned u;
    asm("cvt.rna.tf32.f32 %0, %1;" : "=r"(u) : "f"(f));
    return u;
}
__device__ __forceinline__ float round_tf32(float f) {
    return __uint_as_float(f2tf32(f));
}

__device__ __forceinline__ void cp_async16(void* smem_dst, const void* gsrc) {
    unsigned s = (unsigned)__cvta_generic_to_shared(smem_dst);
    asm volatile("cp.async.cg.shared.global [%0], [%1], 16;\n" :: "r"(s), "l"(gsrc));
}
__device__ __forceinline__ void cp_commit() {
    asm volatile("cp.async.commit_group;\n");
}
template <int N>
__device__ __forceinline__ void cp_wait() {
    asm volatile("cp.async.wait_group %0;\n" :: "n"(N));
}

// ---------------- batched TF32 tensor-core GEMM: C[b] = Aperm @ B[b] -------
// AP: weights in fragment-permuted order (pre-rounded tf32 bits).
// B: [K,N] row-major (pre-rounded tf32 bits). C: [M,N].
// If gstats != nullptr (GEMM3 only): also emit per-tile GroupNorm partial
// sums for 32-row groups: gstats[((z*32 + bm/32 + gl)*(N/128) + bn/128)*2].
#define GSTAGE   3
#define GK       32
#define GROW     136
#define A_STG    (GK * 128)
#define B_STG    (GK * GROW)
#define GEMM_SMEM ((GSTAGE * (A_STG + B_STG)) * 4)
__global__ void __launch_bounds__(256, 2) tf32_gemm_kernel(
    const float* __restrict__ AP, const float* __restrict__ Bm,
    float* __restrict__ Cm, int M, int N, int K,
    size_t strideB, size_t strideC, float* __restrict__ gstats)
{
    extern __shared__ float sm_[];
    float (*As)[4][8][32][4] = (float(*)[4][8][32][4])sm_;
    float (*Bs)[GK][GROW]    = (float(*)[GK][GROW])(sm_ + GSTAGE * A_STG);

    const float* Bp = Bm + (size_t)blockIdx.z * strideB;
    float*       Cp = Cm + (size_t)blockIdx.z * strideC;
    const int bm = blockIdx.y * 128;
    const int bn = blockIdx.x * 128;
    const int nmb = M >> 4;
    const int mb0 = bm >> 4;

    const int tid  = threadIdx.x;
    const int lane = tid & 31;
    const int warp = tid >> 5;
    const int wmb = (warp & 1) * 4;
    const int wn  = (warp >> 1) * 32;
    const int grp = lane >> 2;
    const int tig = lane & 3;

    float acc[4][4][4];
#pragma unroll
    for (int mi = 0; mi < 4; mi++)
#pragma unroll
        for (int ni = 0; ni < 4; ni++)
#pragma unroll
            for (int i = 0; i < 4; i++) acc[mi][ni][i] = 0.f;

    const int nstage = K / GK;

#define LOAD_STAGE(buf, ks)                                                   \
    do {                                                                      \
        _Pragma("unroll")                                                     \
        for (int j = 0; j < 4; j++) {                                         \
            const int id  = tid + 256 * j;                                    \
            const int kb2 = id >> 8;                                          \
            const int rem = id & 255;                                         \
            const int mb  = rem >> 5;                                         \
            const int ln  = rem & 31;                                         \
            cp_async16(&As[buf][kb2][mb][ln][0],                              \
                AP + (((size_t)((ks) * 4 + kb2) * nmb + mb0 + mb) * 32 + ln) * 4); \
            const int kk  = id >> 5;                                          \
            const int col = (id & 31) * 4;                                    \
            cp_async16(&Bs[buf][kk][col],                                     \
                Bp + (size_t)((ks) * GK + kk) * N + bn + col);                \
        }                                                                     \
    } while (0)

    LOAD_STAGE(0, 0); cp_commit();
    LOAD_STAGE(1, 1); cp_commit();

    int cur = 0;
    for (int ks = 0; ks < nstage; ks++) {
        cp_wait<1>();
        __syncthreads();

#pragma unroll
        for (int kb2 = 0; kb2 < 4; kb2++) {
            unsigned a[4][4], b[4][2];
#pragma unroll
            for (int mi = 0; mi < 4; mi++) {
                const float4 av = *(const float4*)&As[cur][kb2][wmb + mi][lane][0];
                a[mi][0] = __float_as_uint(av.x);
                a[mi][1] = __float_as_uint(av.y);
                a[mi][2] = __float_as_uint(av.z);
                a[mi][3] = __float_as_uint(av.w);
            }
#pragma unroll
            for (int ni = 0; ni < 4; ni++) {
                const int n = wn + ni * 8 + grp;
                b[ni][0] = __float_as_uint(Bs[cur][kb2 * 8 + tig    ][n]);
                b[ni][1] = __float_as_uint(Bs[cur][kb2 * 8 + tig + 4][n]);
            }
#pragma unroll
            for (int mi = 0; mi < 4; mi++)
#pragma unroll
                for (int ni = 0; ni < 4; ni++) {
                    asm volatile(
                        "mma.sync.aligned.m16n8k8.row.col.f32.tf32.tf32.f32 "
                        "{%0,%1,%2,%3}, {%4,%5,%6,%7}, {%8,%9}, {%0,%1,%2,%3};\n"
                        : "+f"(acc[mi][ni][0]), "+f"(acc[mi][ni][1]),
                          "+f"(acc[mi][ni][2]), "+f"(acc[mi][ni][3])
                        : "r"(a[mi][0]), "r"(a[mi][1]), "r"(a[mi][2]), "r"(a[mi][3]),
                          "r"(b[ni][0]), "r"(b[ni][1]));
                }
        }

        if (ks + 2 < nstage) {
            const int buf = cur + 2 >= GSTAGE ? cur + 2 - GSTAGE : cur + 2;
            LOAD_STAGE(buf, ks + 2);
        }
        cp_commit();
        cur = cur + 1 >= GSTAGE ? 0 : cur + 1;
    }

    // epilogue: store C
#pragma unroll
    for (int mi = 0; mi < 4; mi++) {
        const int row = bm + (warp & 1) * 64 + mi * 16 + grp;
#pragma unroll
        for (int ni = 0; ni < 4; ni++) {
            const int col = bn + wn + ni * 8 + tig * 2;
            float2 v0 = make_float2(acc[mi][ni][0], acc[mi][ni][1]);
            float2 v1 = make_float2(acc[mi][ni][2], acc[mi][ni][3]);
            *(float2*)(Cp + (size_t)row * N + col)       = v0;
            *(float2*)(Cp + (size_t)(row + 8) * N + col) = v1;
        }
    }

    // optional GN-stat epilogue (32-row groups; GEMM3 only)
    if (gstats) {
        // per-thread partials for the 2 groups this warp touches:
        // gl(mi) = (warp&1)*2 + (mi>>1)
        float s0 = 0.f, q0 = 0.f, s1 = 0.f, q1 = 0.f;
#pragma unroll
        for (int mi = 0; mi < 4; mi++) {
            float s = 0.f, q = 0.f;
#pragma unroll
            for (int ni = 0; ni < 4; ni++)
#pragma unroll
                for (int i = 0; i < 4; i++) {
                    const float v = acc[mi][ni][i];
                    s += v; q += v * v;
                }
            if (mi < 2) { s0 += s; q0 += q; } else { s1 += s; q1 += q; }
        }
#pragma unroll
        for (int o = 16; o > 0; o >>= 1) {
            s0 += __shfl_down_sync(0xFFFFFFFFu, s0, o);
            q0 += __shfl_down_sync(0xFFFFFFFFu, q0, o);
            s1 += __shfl_down_sync(0xFFFFFFFFu, s1, o);
            q1 += __shfl_down_sync(0xFFFFFFFFu, q1, o);
        }
        __syncthreads();              // stage smem no longer needed; reuse
        float* red = sm_;             // [8 warps][4]
        if (lane == 0) {
            red[warp * 4 + 0] = s0; red[warp * 4 + 1] = q0;
            red[warp * 4 + 2] = s1; red[warp * 4 + 3] = q1;
        }
        __syncthreads();
        if (tid < 4) {                // tid = gl (0..3)
            const int par = tid >> 1;         // warp&1 parity owning this gl
            const int off = (tid & 1) * 2;    // which pair within red row
            float s = 0.f, q = 0.f;
#pragma unroll
            for (int j = 0; j < 4; j++) {
                const int w = par + j * 2;
                s += red[w * 4 + off];
                q += red[w * 4 + off + 1];
            }
            const size_t gi = (((size_t)blockIdx.z * 32 + (bm >> 5) + tid) * (N >> 7)
                               + (bn >> 7)) * 2;
            gstats[gi]     = s;
            gstats[gi + 1] = q;
        }
    }
#undef LOAD_STAGE
}

// ---------------- GN3 stats reduce: partials -> mean/rstd ------------------
__global__ void gn3_reduce_kernel(const float* __restrict__ gnp,
                                  float* __restrict__ gn3)
{
    const int i = threadIdx.x;       // 0..127 = b*32 + g
    if (i >= B_ * 32) return;
    float s = 0.f, q = 0.f;
    const float* p = gnp + (size_t)i * 32 * 2;
#pragma unroll
    for (int t = 0; t < 32; t++) { s += p[t * 2]; q += p[t * 2 + 1]; }
    const float n = 32.f * HW;       // 32 channels x 4096 pixels
    const float mean = s / n;
    const float var  = q / n - mean * mean;
    gn3[i * 2]     = mean;
    gn3[i * 2 + 1] = rsqrtf(var + 1e-5f);
}

// ---------------- weight permute + tf32-round: A[M][K] -> fragment order ---
__global__ void aperm_round_kernel(const float* __restrict__ A,
                                   float* __restrict__ AP, int M, int K)
{
    const int i = blockIdx.x * blockDim.x + threadIdx.x;
    if (i >= M * K) return;
    const int blk = i >> 7;
    const int l   = (i >> 2) & 31;
    const int v   = i & 3;
    const int nmb = M >> 4;
    const int kb = blk / nmb, mb = blk % nmb;
    const int tig = (l & 3) + ((v >> 1) << 2);
    const int grp = (l >> 2) + ((v & 1) << 3);
    const int m = mb * 16 + grp;
    const int k = kb * 8 + tig;
    AP[i] = round_tf32(A[(size_t)m * K + k]);
}

// ---------------- tf32 round-copy (for x -> GEMM1 B) -----------------------
__global__ void round_copy_kernel(const float* __restrict__ in,
                                  float* __restrict__ out, int n4)
{
    const int i = blockIdx.x * blockDim.x + threadIdx.x;
    if (i >= n4) return;
    float4 v = ((const float4*)in)[i];
    v.x = round_tf32(v.x); v.y = round_tf32(v.y);
    v.z = round_tf32(v.z); v.w = round_tf32(v.w);
    ((float4*)out)[i] = v;
}

// ---------------- block reduction helper -----------------------------------
__device__ __forceinline__ void block_reduce2(float& s, float& ss) {
#pragma unroll
    for (int o = 16; o > 0; o >>= 1) {
        s  += __shfl_down_sync(0xFFFFFFFFu, s,  o);
        ss += __shfl_down_sync(0xFFFFFFFFu, ss, o);
    }
    __shared__ float as_[32], ass_[32];
    int lane = threadIdx.x & 31, wid = threadIdx.x >> 5;
    if (lane == 0) { as_[wid] = s; ass_[wid] = ss; }
    __syncthreads();
    int nw = blockDim.x >> 5;
    if (wid == 0) {
        s  = (lane < nw) ? as_[lane]  : 0.f;
        ss = (lane < nw) ? ass_[lane] : 0.f;
#pragma unroll
        for (int o = 16; o > 0; o >>= 1) {
            s  += __shfl_down_sync(0xFFFFFFFFu, s,  o);
            ss += __shfl_down_sync(0xFFFFFFFFu, ss, o);
        }
    }
}

// ---------------- GroupNorm (+ReLU), in-place; one block per (b, group) ----
template <bool ROUND>
__global__ void gn_relu_kernel(float* __restrict__ data,
                               const float* __restrict__ scale,
                               const float* __restrict__ bias,
                               int C, int cpg)
{
    const int G  = C / cpg;
    const int b  = blockIdx.x / G;
    const int gi = blockIdx.x % G;
    float* p = data + ((size_t)b * C + (size_t)gi * cpg) * HW;
    const int n4 = (cpg * HW) >> 2;

    float s = 0.f, ss = 0.f;
    for (int i = threadIdx.x; i < n4; i += blockDim.x) {
        float4 v = ((const float4*)p)[i];
        s  += v.x + v.y + v.z + v.w;
        ss += v.x * v.x + v.y * v.y + v.z * v.z + v.w * v.w;
    }
    block_reduce2(s, ss);
    __shared__ float sh_mean, sh_rstd;
    if (threadIdx.x == 0) {
        const float n = (float)(cpg * HW);
        float mean = s / n;
        float var  = ss / n - mean * mean;
        sh_mean = mean;
        sh_rstd = rsqrtf(var + 1e-5f);
    }
    __syncthreads();
    const float mean = sh_mean, rstd = sh_rstd;
    for (int i = threadIdx.x; i < n4; i += blockDim.x) {
        int c = gi * cpg + (i * 4) / HW;
        const float a = rstd * scale[c];
        const float d = bias[c] - mean * a;
        float4 v = ((const float4*)p)[i];
        v.x = fmaxf(v.x * a + d, 0.f);
        v.y = fmaxf(v.y * a + d, 0.f);
        v.z = fmaxf(v.z * a + d, 0.f);
        v.w = fmaxf(v.w * a + d, 0.f);
        if (ROUND) {
            v.x = round_tf32(v.x); v.y = round_tf32(v.y);
            v.z = round_tf32(v.z); v.w = round_tf32(v.w);
        }
        ((float4*)p)[i] = v;
    }
}

// ---------------- GN3 apply (single pass) + residual + ReLU -> output ------
__global__ void gn_res_apply_kernel(const float* __restrict__ in,
                                    const float* __restrict__ xres,
                                    const float* __restrict__ gn3,
                                    const float* __restrict__ scale,
                                    const float* __restrict__ bias,
                                    float* __restrict__ out)
{
    const int G = 32, cpg = CIN / 32;
    const int b  = blockIdx.x / G;
    const int gi = blockIdx.x % G;
    const size_t base = ((size_t)b * CIN + (size_t)gi * cpg) * HW;
    const float* p = in + base;
    const float* r = xres + base;
    float* o = out + base;
    const int n4 = (cpg * HW) >> 2;
    const float mean = gn3[blockIdx.x * 2];
    const float rstd = gn3[blockIdx.x * 2 + 1];

    for (int i = threadIdx.x; i < n4; i += blockDim.x) {
        int c = gi * cpg + (i * 4) / HW;
        const float a = rstd * scale[c];
        const float d = bias[c] - mean * a;
        float4 v = ((const float4*)p)[i];
        float4 rr = ((const float4*)r)[i];
        v.x = fmaxf(v.x * a + d + rr.x, 0.f);
        v.y = fmaxf(v.y * a + d + rr.y, 0.f);
        v.z = fmaxf(v.z * a + d + rr.z, 0.f);
        v.w = fmaxf(v.w * a + d + rr.w, 0.f);
        ((float4*)o)[i] = v;
    }
}

// ---------------- 3x3 offset conv (27 out ch), pad=1, channel-split 4 ------
__global__ void __launch_bounds__(256) conv_off_kernel(
    const float* __restrict__ in,    // g_out1 [B][CB][H][W]
    const float* __restrict__ w,     // [27][CB][3][3]
    float* __restrict__ omp)         // [4][B][27][H][W]
{
    const int bx = blockIdx.x;
    const int by = blockIdx.y;
    const int b = blockIdx.z >> 2;
    const int q = blockIdx.z & 3;
    const int tid = threadIdx.x;
    const int tx = tid & 15, ty = tid >> 4;

    __shared__ float s_in[8][18][18];
    __shared__ float s_w[8][9][28];

    float acc[28];
#pragma unroll
    for (int j = 0; j < 28; j++) acc[j] = 0.f;

    const int x0 = bx * 16, y0 = by * 16;
    const int cbase = q * 64;
    const float* inb = in + (size_t)b * CB * HW;

    for (int c0 = cbase; c0 < cbase + 64; c0 += 8) {
        for (int e = tid; e < 8 * 18 * 18; e += 256) {
            int c = e / 324;
            int r = (e / 18) % 18;
            int col = e % 18;
            int y = y0 + r - 1, x = x0 + col - 1;
            float v = 0.f;
            if (y >= 0 && y < H_ && x >= 0 && x < W_)
                v = inb[(size_t)(c0 + c) * HW + y * W_ + x];
            s_in[c][r][col] = v;
        }
        for (int e = tid; e < 8 * 9 * 28; e += 256) {
            int c = e / (9 * 28);
            int k = (e / 28) % 9;
            int j = e % 28;
            s_w[c][k][j] = (j < 27) ? w[((size_t)j * CB + c0 + c) * 9 + k] : 0.f;
        }
        __syncthreads();
#pragma unroll
        for (int c = 0; c < 8; c++) {
#pragma unroll
            for (int k = 0; k < 9; k++) {
                const float v = s_in[c][ty + k / 3][tx + k % 3];
                const float4* wr = (const float4*)&s_w[c][k][0];
#pragma unroll
                for (int qq = 0; qq < 7; qq++) {
                    const float4 w4 = wr[qq];
                    acc[qq * 4 + 0] += v * w4.x;
                    acc[qq * 4 + 1] += v * w4.y;
                    acc[qq * 4 + 2] += v * w4.z;
                    acc[qq * 4 + 3] += v * w4.w;
                }
            }
        }
        __syncthreads();
    }
    const int hw = (y0 + ty) * W_ + x0 + tx;
    float* op = omp + (size_t)q * B_ * 27 * HW + (size_t)b * 27 * HW;
#pragma unroll
    for (int j = 0; j < 27; j++)
        op[(size_t)j * HW + hw] = acc[j];
}

// ---------------- deformable bilinear sampling (reads 4 conv partials) -----
__global__ void __launch_bounds__(256) deform_sample_kernel(
    const float* __restrict__ out1,
    const float* __restrict__ omp,   // [4][B][27][H][W]
    const float* __restrict__ boff,  // [27]
    float* __restrict__ sampled)
{
    const int idx = blockIdx.x * blockDim.x + threadIdx.x;
    if (idx >= B_ * KOFF * HW) return;
    const int hw = idx % HW;
    const int k  = (idx / HW) % KOFF;
    const int b  = idx / (HW * KOFF);
    const int h = hw / W_, w = hw % W_;

    const size_t qstride = (size_t)B_ * 27 * HW;
    const float* o0 = omp + (size_t)b * 27 * HW;
    float offx = boff[k], offy = boff[KOFF + k], mraw = boff[18 + k];
#pragma unroll
    for (int q = 0; q < 4; q++) {
        const float* oq = o0 + q * qstride;
        offx += oq[(size_t)k * HW + hw];
        offy += oq[(size_t)(KOFF + k) * HW + hw];
        mraw += oq[(size_t)(18 + k) * HW + hw];
    }
    const float mval = 1.f / (1.f + expf(-mraw));

    const float py = (float)(h + k / 3 - 1) + offy;
    const float px = (float)(w + k % 3 - 1) + offx;
    const float y0f = floorf(py), x0f = floorf(px);
    const int y0 = (int)y0f, x0 = (int)x0f;
    const float wy1 = py - y0f, wx1 = px - x0f;
    const float wy0 = 1.f - wy1, wx0 = 1.f - wx1;
    const int y1 = y0 + 1, x1 = x0 + 1;
    const bool vy0 = (y0 >= 0) && (y0 < H_), vy1 = (y1 >= 0) && (y1 < H_);
    const bool vx0 = (x0 >= 0) && (x0 < W_), vx1 = (x1 >= 0) && (x1 < W_);
    const int cy0 = min(max(y0, 0), H_ - 1), cy1 = min(max(y1, 0), H_ - 1);
    const int cx0 = min(max(x0, 0), W_ - 1), cx1 = min(max(x1, 0), W_ - 1);
    const int i00 = cy0 * W_ + cx0, i01 = cy0 * W_ + cx1;
    const int i10 = cy1 * W_ + cx0, i11 = cy1 * W_ + cx1;
    const float w00 = (vy0 && vx0) ? wy0 * wx0 * mval : 0.f;
    const float w01 = (vy0 && vx1) ? wy0 * wx1 * mval : 0.f;
    const float w10 = (vy1 && vx0) ? wy1 * wx0 * mval : 0.f;
    const float w11 = (vy1 && vx1) ? wy1 * wx1 * mval : 0.f;

    const float* base = out1 + (size_t)b * CB * HW;
    const size_t obase = (size_t)b * CB * KOFF * HW + (size_t)k * HW + hw;
#pragma unroll 8
    for (int c = 0; c < CB; c++) {
        const float* p = base + (size_t)c * HW;
        float v = w00 * p[i00] + w01 * p[i01] + w10 * p[i10] + w11 * p[i11];
        sampled[obase + (size_t)c * (KOFF * HW)] = round_tf32(v);
    }
}

// ---------------- host launcher --------------------------------------------
extern "C" void kernel_launch(void* const* d_in, const int* in_sizes, int n_in,
                              void* d_out, int out_size)
{
    const float* x     = (const float*)d_in[0];
    const float* w1    = (const float*)d_in[1];
    const float* gn1s  = (const float*)d_in[2];
    const float* gn1b  = (const float*)d_in[3];
    const float* w_off = (const float*)d_in[4];
    const float* b_off = (const float*)d_in[5];
    const float* w2    = (const float*)d_in[6];
    const float* gn2s  = (const float*)d_in[7];
    const float* gn2b  = (const float*)d_in[8];
    const float* w3    = (const float*)d_in[9];
    const float* gn3s  = (const float*)d_in[10];
    const float* gn3b  = (const float*)d_in[11];
    float* out = (float*)d_out;

    float *p_out1, *p_omp, *p_samp, *p_out2, *p_out3, *p_ap1, *p_ap2, *p_ap3,
          *p_gnp, *p_gn3;
    cudaGetSymbolAddress((void**)&p_out1, g_out1);
    cudaGetSymbolAddress((void**)&p_omp,  g_omp);
    cudaGetSymbolAddress((void**)&p_samp, g_samp);
    cudaGetSymbolAddress((void**)&p_out2, g_out2);
    cudaGetSymbolAddress((void**)&p_out3, g_out3);
    cudaGetSymbolAddress((void**)&p_ap1,  g_ap1);
    cudaGetSymbolAddress((void**)&p_ap2,  g_ap2);
    cudaGetSymbolAddress((void**)&p_ap3,  g_ap3);
    cudaGetSymbolAddress((void**)&p_gnp,  g_gnp);
    cudaGetSymbolAddress((void**)&p_gn3,  g_gn3);

    cudaFuncSetAttribute(tf32_gemm_kernel,
                         cudaFuncAttributeMaxDynamicSharedMemorySize, GEMM_SMEM);

    // launch order keeps gemm1 at captured index 3 (0-based) for ncu visibility
    aperm_round_kernel<<<(CB*CIN + 255)/256, 256>>>(w1, p_ap1, CB, CIN);
    round_copy_kernel<<<(B_*CIN*HW/4 + 255)/256, 256>>>(x, p_out3, B_*CIN*HW/4);
    aperm_round_kernel<<<(CB*CB*KOFF + 255)/256, 256>>>(w2, p_ap2, CB, CB*KOFF);

    // 1) out1 = w1 @ x            (M=256, K=1024, N=4096, batch 4)
    tf32_gemm_kernel<<<dim3(HW/128, CB/128, B_), 256, GEMM_SMEM>>>(
        p_ap1, p_out3, p_out1, CB, HW, CIN, (size_t)CIN*HW, (size_t)CB*HW, nullptr);

    // 2) GN1 + ReLU (in place, full precision — feeds conv/deform)
    gn_relu_kernel<false><<<B_*32, 512>>>(p_out1, gn1s, gn1b, CB, CB/32);

    // permute+round w3 (needed before gemm3)
    aperm_round_kernel<<<(CIN*CB + 255)/256, 256>>>(w3, p_ap3, CIN, CB);

    // 3) offset conv, channel-split 4 -> partials (combined inside deform)
    conv_off_kernel<<<dim3(W_/16, H_/16, B_*4), 256>>>(p_out1, w_off, p_omp);

    // 4) deform sample * sigmoid(mask) -> rounded [b][c*9+k][hw]
    deform_sample_kernel<<<(B_*KOFF*HW + 255)/256, 256>>>(p_out1, p_omp, b_off, p_samp);

    // 5) out2 = w2_flat @ sampled (M=256, K=2304, N=4096, batch 4)
    tf32_gemm_kernel<<<dim3(HW/128, CB/128, B_), 256, GEMM_SMEM>>>(
        p_ap2, p_samp, p_out2, CB, HW, CB*KOFF,
        (size_t)CB*KOFF*HW, (size_t)CB*HW, nullptr);

    // 6) GN2 + ReLU (in place, rounded — feeds GEMM3 B)
    gn_relu_kernel<true><<<B_*32, 512>>>(p_out2, gn2s, gn2b, CB, CB/32);

    // 7) out3 = w3 @ out2 + GN3 tile stats (M=1024, K=256, N=4096, batch 4)
    tf32_gemm_kernel<<<dim3(HW/128, CIN/128, B_), 256, GEMM_SMEM>>>(
        p_ap3, p_out2, p_out3, CIN, HW, CB, (size_t)CB*HW, (size_t)CIN*HW, p_gnp);

    // 7b) reduce tile stats -> mean/rstd per (b, group)
    gn3_reduce_kernel<<<1, 128>>>(p_gnp, p_gn3);

    // 8) out = relu(GN3(out3) + x)  — single pass
    gn_res_apply_kernel<<<B_*32, 1024>>>(p_out3, x, p_gn3, gn3s, gn3b, out);
}

// round 11
// speedup vs baseline: 3.4625x; 1.0656x over previous
#include <cuda_runtime.h>
#include <math.h>

#define B_   4
#define CIN  1024
#define CB   256
#define H_   64
#define W_   64
#define HW   (H_*W_)
#define KOFF 9

// ---------------- scratch (device globals; no runtime allocation) ----------
__device__ float g_out1[(size_t)B_*CB*HW];              // 16.7 MB
__device__ float g_omp [(size_t)4*B_*27*HW];            // conv partial sums (4-way)
__device__ float g_samp[(size_t)B_*CB*KOFF*HW];         // 151 MB
__device__ float g_out2[(size_t)B_*CB*HW];              // 16.7 MB
__device__ float g_out3[(size_t)B_*CIN*HW];             // 67 MB (GEMM3 out)
__device__ float g_ap1[(size_t)CIN*CB];                 // w1 perm  [K/8][M/16][32][4]
__device__ float g_ap2[(size_t)CB*KOFF*CB];             // w2 perm
__device__ float g_ap3[(size_t)CB*CIN];                 // w3 perm
__device__ float g_gnp[(size_t)B_*32*32*2];             // GN3 tile partials [b][g][tile][2]
__device__ float g_gn3[(size_t)B_*32*2];                // GN3 mean/rstd per (b,g)

__device__ __forceinline__ unsigned f2tf32(float f) {
    unsigned u;
    asm("cvt.rna.tf32.f32 %0, %1;" : "=r"(u) : "f"(f));
    return u;
}
__device__ __forceinline__ float round_tf32(float f) {
    return __uint_as_float(f2tf32(f));
}

__device__ __forceinline__ void cp_async16(void* smem_dst, const void* gsrc) {
    unsigned s = (unsigned)__cvta_generic_to_shared(smem_dst);
    asm volatile("cp.async.cg.shared.global [%0], [%1], 16;\n" :: "r"(s), "l"(gsrc));
}
__device__ __forceinline__ void cp_commit() {
    asm volatile("cp.async.commit_group;\n");
}
template <int N>
__device__ __forceinline__ void cp_wait() {
    asm volatile("cp.async.wait_group %0;\n" :: "n"(N));
}

// ---------------- batched TF32 tensor-core GEMM: C[b] = Aperm @ B[b] -------
// AP: weights in fragment-permuted order (pre-rounded tf32 bits).
// B: [K,N] row-major (f32; hardware truncates to tf32 = RZ — bias removed by
//    the GroupNorm that always follows).
// If gstats != nullptr (GEMM3 only): emit per-tile GroupNorm partials.
#define GSTAGE   3
#define GK       32
#define GROW     136
#define A_STG    (GK * 128)
#define B_STG    (GK * GROW)
#define GEMM_SMEM ((GSTAGE * (A_STG + B_STG)) * 4)
__global__ void __launch_bounds__(256, 2) tf32_gemm_kernel(
    const float* __restrict__ AP, const float* __restrict__ Bm,
    float* __restrict__ Cm, int M, int N, int K,
    size_t strideB, size_t strideC, float* __restrict__ gstats)
{
    extern __shared__ float sm_[];
    float (*As)[4][8][32][4] = (float(*)[4][8][32][4])sm_;
    float (*Bs)[GK][GROW]    = (float(*)[GK][GROW])(sm_ + GSTAGE * A_STG);

    const float* Bp = Bm + (size_t)blockIdx.z * strideB;
    float*       Cp = Cm + (size_t)blockIdx.z * strideC;
    const int bm = blockIdx.y * 128;
    const int bn = blockIdx.x * 128;
    const int nmb = M >> 4;
    const int mb0 = bm >> 4;

    const int tid  = threadIdx.x;
    const int lane = tid & 31;
    const int warp = tid >> 5;
    const int wmb = (warp & 1) * 4;
    const int wn  = (warp >> 1) * 32;
    const int grp = lane >> 2;
    const int tig = lane & 3;

    float acc[4][4][4];
#pragma unroll
    for (int mi = 0; mi < 4; mi++)
#pragma unroll
        for (int ni = 0; ni < 4; ni++)
#pragma unroll
            for (int i = 0; i < 4; i++) acc[mi][ni][i] = 0.f;

    const int nstage = K / GK;

#define LOAD_STAGE(buf, ks)                                                   \
    do {                                                                      \
        _Pragma("unroll")                                                     \
        for (int j = 0; j < 4; j++) {                                         \
            const int id  = tid + 256 * j;                                    \
            const int kb2 = id >> 8;                                          \
            const int rem = id & 255;                                         \
            const int mb  = rem >> 5;                                         \
            const int ln  = rem & 31;                                         \
            cp_async16(&As[buf][kb2][mb][ln][0],                              \
                AP + (((size_t)((ks) * 4 + kb2) * nmb + mb0 + mb) * 32 + ln) * 4); \
            const int kk  = id >> 5;                                          \
            const int col = (id & 31) * 4;                                    \
            cp_async16(&Bs[buf][kk][col],                                     \
                Bp + (size_t)((ks) * GK + kk) * N + bn + col);                \
        }                                                                     \
    } while (0)

    LOAD_STAGE(0, 0); cp_commit();
    LOAD_STAGE(1, 1); cp_commit();

    int cur = 0;
    for (int ks = 0; ks < nstage; ks++) {
        cp_wait<1>();
        __syncthreads();

#pragma unroll
        for (int kb2 = 0; kb2 < 4; kb2++) {
            unsigned a[4][4], b[4][2];
#pragma unroll
            for (int mi = 0; mi < 4; mi++) {
                const float4 av = *(const float4*)&As[cur][kb2][wmb + mi][lane][0];
                a[mi][0] = __float_as_uint(av.x);
                a[mi][1] = __float_as_uint(av.y);
                a[mi][2] = __float_as_uint(av.z);
                a[mi][3] = __float_as_uint(av.w);
            }
#pragma unroll
            for (int ni = 0; ni < 4; ni++) {
                const int n = wn + ni * 8 + grp;
                b[ni][0] = __float_as_uint(Bs[cur][kb2 * 8 + tig    ][n]);
                b[ni][1] = __float_as_uint(Bs[cur][kb2 * 8 + tig + 4][n]);
            }
#pragma unroll
            for (int mi = 0; mi < 4; mi++)
#pragma unroll
                for (int ni = 0; ni < 4; ni++) {
                    asm volatile(
                        "mma.sync.aligned.m16n8k8.row.col.f32.tf32.tf32.f32 "
                        "{%0,%1,%2,%3}, {%4,%5,%6,%7}, {%8,%9}, {%0,%1,%2,%3};\n"
                        : "+f"(acc[mi][ni][0]), "+f"(acc[mi][ni][1]),
                          "+f"(acc[mi][ni][2]), "+f"(acc[mi][ni][3])
                        : "r"(a[mi][0]), "r"(a[mi][1]), "r"(a[mi][2]), "r"(a[mi][3]),
                          "r"(b[ni][0]), "r"(b[ni][1]));
                }
        }

        if (ks + 2 < nstage) {
            const int buf = cur + 2 >= GSTAGE ? cur + 2 - GSTAGE : cur + 2;
            LOAD_STAGE(buf, ks + 2);
        }
        cp_commit();
        cur = cur + 1 >= GSTAGE ? 0 : cur + 1;
    }

    // epilogue: store C
#pragma unroll
    for (int mi = 0; mi < 4; mi++) {
        const int row = bm + (warp & 1) * 64 + mi * 16 + grp;
#pragma unroll
        for (int ni = 0; ni < 4; ni++) {
            const int col = bn + wn + ni * 8 + tig * 2;
            float2 v0 = make_float2(acc[mi][ni][0], acc[mi][ni][1]);
            float2 v1 = make_float2(acc[mi][ni][2], acc[mi][ni][3]);
            *(float2*)(Cp + (size_t)row * N + col)       = v0;
            *(float2*)(Cp + (size_t)(row + 8) * N + col) = v1;
        }
    }

    // optional GN-stat epilogue (32-row groups; GEMM3 only)
    if (gstats) {
        float s0 = 0.f, q0 = 0.f, s1 = 0.f, q1 = 0.f;
#pragma unroll
        for (int mi = 0; mi < 4; mi++) {
            float s = 0.f, q = 0.f;
#pragma unroll
            for (int ni = 0; ni < 4; ni++)
#pragma unroll
                for (int i = 0; i < 4; i++) {
                    const float v = acc[mi][ni][i];
                    s += v; q += v * v;
                }
            if (mi < 2) { s0 += s; q0 += q; } else { s1 += s; q1 += q; }
        }
#pragma unroll
        for (int o = 16; o > 0; o >>= 1) {
            s0 += __shfl_down_sync(0xFFFFFFFFu, s0, o);
            q0 += __shfl_down_sync(0xFFFFFFFFu, q0, o);
            s1 += __shfl_down_sync(0xFFFFFFFFu, s1, o);
            q1 += __shfl_down_sync(0xFFFFFFFFu, q1, o);
        }
        __syncthreads();
        float* red = sm_;
        if (lane == 0) {
            red[warp * 4 + 0] = s0; red[warp * 4 + 1] = q0;
            red[warp * 4 + 2] = s1; red[warp * 4 + 3] = q1;
        }
        __syncthreads();
        if (tid < 4) {
            const int par = tid >> 1;
            const int off = (tid & 1) * 2;
            float s = 0.f, q = 0.f;
#pragma unroll
            for (int j = 0; j < 4; j++) {
                const int w = par + j * 2;
                s += red[w * 4 + off];
                q += red[w * 4 + off + 1];
            }
            const size_t gi = (((size_t)blockIdx.z * 32 + (bm >> 5) + tid) * (N >> 7)
                               + (bn >> 7)) * 2;
            gstats[gi]     = s;
            gstats[gi + 1] = q;
        }
    }
#undef LOAD_STAGE
}

// ---------------- GN3 stats reduce: partials -> mean/rstd ------------------
__global__ void gn3_reduce_kernel(const float* __restrict__ gnp,
                                  float* __restrict__ gn3)
{
    const int i = threadIdx.x;
    if (i >= B_ * 32) return;
    float s = 0.f, q = 0.f;
    const float* p = gnp + (size_t)i * 32 * 2;
#pragma unroll
    for (int t = 0; t < 32; t++) { s += p[t * 2]; q += p[t * 2 + 1]; }
    const float n = 32.f * HW;
    const float mean = s / n;
    const float var  = q / n - mean * mean;
    gn3[i * 2]     = mean;
    gn3[i * 2 + 1] = rsqrtf(var + 1e-5f);
}

// ---------------- weight permute + tf32-round: A[M][K] -> fragment order ---
__global__ void aperm_round_kernel(const float* __restrict__ A,
                                   float* __restrict__ AP, int M, int K)
{
    const int i = blockIdx.x * blockDim.x + threadIdx.x;
    if (i >= M * K) return;
    const int blk = i >> 7;
    const int l   = (i >> 2) & 31;
    const int v   = i & 3;
    const int nmb = M >> 4;
    const int kb = blk / nmb, mb = blk % nmb;
    const int tig = (l & 3) + ((v >> 1) << 2);
    const int grp = (l >> 2) + ((v & 1) << 3);
    const int m = mb * 16 + grp;
    const int k = kb * 8 + tig;
    AP[i] = round_tf32(A[(size_t)m * K + k]);
}

// ---------------- block reduction helper -----------------------------------
__device__ __forceinline__ void block_reduce2(float& s, float& ss) {
#pragma unroll
    for (int o = 16; o > 0; o >>= 1) {
        s  += __shfl_down_sync(0xFFFFFFFFu, s,  o);
        ss += __shfl_down_sync(0xFFFFFFFFu, ss, o);
    }
    __shared__ float as_[32], ass_[32];
    int lane = threadIdx.x & 31, wid = threadIdx.x >> 5;
    if (lane == 0) { as_[wid] = s; ass_[wid] = ss; }
    __syncthreads();
    int nw = blockDim.x >> 5;
    if (wid == 0) {
        s  = (lane < nw) ? as_[lane]  : 0.f;
        ss = (lane < nw) ? ass_[lane] : 0.f;
#pragma unroll
        for (int o = 16; o > 0; o >>= 1) {
            s  += __shfl_down_sync(0xFFFFFFFFu, s,  o);
            ss += __shfl_down_sync(0xFFFFFFFFu, ss, o);
        }
    }
}

// ---------------- GroupNorm (+ReLU), in-place; one block per (b, group) ----
__global__ void gn_relu_kernel(float* __restrict__ data,
                               const float* __restrict__ scale,
                               const float* __restrict__ bias,
                               int C, int cpg)
{
    const int G  = C / cpg;
    const int b  = blockIdx.x / G;
    const int gi = blockIdx.x % G;
    float* p = data + ((size_t)b * C + (size_t)gi * cpg) * HW;
    const int n4 = (cpg * HW) >> 2;

    float s = 0.f, ss = 0.f;
    for (int i = threadIdx.x; i < n4; i += blockDim.x) {
        float4 v = ((const float4*)p)[i];
        s  += v.x + v.y + v.z + v.w;
        ss += v.x * v.x + v.y * v.y + v.z * v.z + v.w * v.w;
    }
    block_reduce2(s, ss);
    __shared__ float sh_mean, sh_rstd;
    if (threadIdx.x == 0) {
        const float n = (float)(cpg * HW);
        float mean = s / n;
        float var  = ss / n - mean * mean;
        sh_mean = mean;
        sh_rstd = rsqrtf(var + 1e-5f);
    }
    __syncthreads();
    const float mean = sh_mean, rstd = sh_rstd;
    for (int i = threadIdx.x; i < n4; i += blockDim.x) {
        int c = gi * cpg + (i * 4) / HW;
        const float a = rstd * scale[c];
        const float d = bias[c] - mean * a;
        float4 v = ((const float4*)p)[i];
        v.x = fmaxf(v.x * a + d, 0.f);
        v.y = fmaxf(v.y * a + d, 0.f);
        v.z = fmaxf(v.z * a + d, 0.f);
        v.w = fmaxf(v.w * a + d, 0.f);
        ((float4*)p)[i] = v;
    }
}

// ---------------- GN3 apply (flat elementwise) + residual + ReLU -----------
__global__ void gn_res_apply_kernel(const float* __restrict__ in,
                                    const float* __restrict__ xres,
                                    const float* __restrict__ gn3,
                                    const float* __restrict__ scale,
                                    const float* __restrict__ bias,
                                    float* __restrict__ out)
{
    const int idx = blockIdx.x * blockDim.x + threadIdx.x;
    if (idx >= B_ * CIN * HW / 4) return;
    const int i4 = idx * 4;
    const int b = i4 / (CIN * HW);
    const int c = (i4 / HW) % CIN;
    const int g = b * 32 + (c >> 5);
    const float mean = gn3[g * 2];
    const float rstd = gn3[g * 2 + 1];
    const float a = rstd * scale[c];
    const float d = bias[c] - mean * a;
    float4 v = ((const float4*)in)[idx];
    float4 rr = ((const float4*)xres)[idx];
    v.x = fmaxf(v.x * a + d + rr.x, 0.f);
    v.y = fmaxf(v.y * a + d + rr.y, 0.f);
    v.z = fmaxf(v.z * a + d + rr.z, 0.f);
    v.w = fmaxf(v.w * a + d + rr.w, 0.f);
    ((float4*)out)[idx] = v;
}

// ---------------- 3x3 offset conv (27 out ch), pad=1, channel-split 4 ------
__global__ void __launch_bounds__(256) conv_off_kernel(
    const float* __restrict__ in,
    const float* __restrict__ w,
    float* __restrict__ omp)         // [4][B][27][H][W]
{
    const int bx = blockIdx.x;
    const int by = blockIdx.y;
    const int b = blockIdx.z >> 2;
    const int q = blockIdx.z & 3;
    const int tid = threadIdx.x;
    const int tx = tid & 15, ty = tid >> 4;

    __shared__ float s_in[8][18][18];
    __shared__ float s_w[8][9][28];

    float acc[28];
#pragma unroll
    for (int j = 0; j < 28; j++) acc[j] = 0.f;

    const int x0 = bx * 16, y0 = by * 16;
    const int cbase = q * 64;
    const float* inb = in + (size_t)b * CB * HW;

    for (int c0 = cbase; c0 < cbase + 64; c0 += 8) {
        for (int e = tid; e < 8 * 18 * 18; e += 256) {
            int c = e / 324;
            int r = (e / 18) % 18;
            int col = e % 18;
            int y = y0 + r - 1, x = x0 + col - 1;
            float v = 0.f;
            if (y >= 0 && y < H_ && x >= 0 && x < W_)
                v = inb[(size_t)(c0 + c) * HW + y * W_ + x];
            s_in[c][r][col] = v;
        }
        for (int e = tid; e < 8 * 9 * 28; e += 256) {
            int c = e / (9 * 28);
            int k = (e / 28) % 9;
            int j = e % 28;
            s_w[c][k][j] = (j < 27) ? w[((size_t)j * CB + c0 + c) * 9 + k] : 0.f;
        }
        __syncthreads();
#pragma unroll
        for (int c = 0; c < 8; c++) {
#pragma unroll
            for (int k = 0; k < 9; k++) {
                const float v = s_in[c][ty + k / 3][tx + k % 3];
                const float4* wr = (const float4*)&s_w[c][k][0];
#pragma unroll
                for (int qq = 0; qq < 7; qq++) {
                    const float4 w4 = wr[qq];
                    acc[qq * 4 + 0] += v * w4.x;
                    acc[qq * 4 + 1] += v * w4.y;
                    acc[qq * 4 + 2] += v * w4.z;
                    acc[qq * 4 + 3] += v * w4.w;
                }
            }
        }
        __syncthreads();
    }
    const int hw = (y0 + ty) * W_ + x0 + tx;
    float* op = omp + (size_t)q * B_ * 27 * HW + (size_t)b * 27 * HW;
#pragma unroll
    for (int j = 0; j < 27; j++)
        op[(size_t)j * HW + hw] = acc[j];
}

// ---------------- deformable bilinear sampling (reads 4 conv partials) -----
__global__ void __launch_bounds__(256) deform_sample_kernel(
    const float* __restrict__ out1,
    const float* __restrict__ omp,   // [4][B][27][H][W]
    const float* __restrict__ boff,
    float* __restrict__ sampled)
{
    const int idx = blockIdx.x * blockDim.x + threadIdx.x;
    if (idx >= B_ * KOFF * HW) return;
    const int hw = idx % HW;
    const int k  = (idx / HW) % KOFF;
    const int b  = idx / (HW * KOFF);
    const int h = hw / W_, w = hw % W_;

    const size_t qstride = (size_t)B_ * 27 * HW;
    const float* o0 = omp + (size_t)b * 27 * HW;
    float offx = boff[k], offy = boff[KOFF + k], mraw = boff[18 + k];
#pragma unroll
    for (int q = 0; q < 4; q++) {
        const float* oq = o0 + q * qstride;
        offx += oq[(size_t)k * HW + hw];
        offy += oq[(size_t)(KOFF + k) * HW + hw];
        mraw += oq[(size_t)(18 + k) * HW + hw];
    }
    const float mval = 1.f / (1.f + expf(-mraw));

    const float py = (float)(h + k / 3 - 1) + offy;
    const float px = (float)(w + k % 3 - 1) + offx;
    const float y0f = floorf(py), x0f = floorf(px);
    const int y0 = (int)y0f, x0 = (int)x0f;
    const float wy1 = py - y0f, wx1 = px - x0f;
    const float wy0 = 1.f - wy1, wx0 = 1.f - wx1;
    const int y1 = y0 + 1, x1 = x0 + 1;
    const bool vy0 = (y0 >= 0) && (y0 < H_), vy1 = (y1 >= 0) && (y1 < H_);
    const bool vx0 = (x0 >= 0) && (x0 < W_), vx1 = (x1 >= 0) && (x1 < W_);
    const int cy0 = min(max(y0, 0), H_ - 1), cy1 = min(max(y1, 0), H_ - 1);
    const int cx0 = min(max(x0, 0), W_ - 1), cx1 = min(max(x1, 0), W_ - 1);
    const int i00 = cy0 * W_ + cx0, i01 = cy0 * W_ + cx1;
    const int i10 = cy1 * W_ + cx0, i11 = cy1 * W_ + cx1;
    const float w00 = (vy0 && vx0) ? wy0 * wx0 * mval : 0.f;
    const float w01 = (vy0 && vx1) ? wy0 * wx1 * mval : 0.f;
    const float w10 = (vy1 && vx0) ? wy1 * wx0 * mval : 0.f;
    const float w11 = (vy1 && vx1) ? wy1 * wx1 * mval : 0.f;

    const float* base = out1 + (size_t)b * CB * HW;
    const size_t obase = (size_t)b * CB * KOFF * HW + (size_t)k * HW + hw;
#pragma unroll 8
    for (int c = 0; c < CB; c++) {
        const float* p = base + (size_t)c * HW;
        float v = w00 * p[i00] + w01 * p[i01] + w10 * p[i10] + w11 * p[i11];
        sampled[obase + (size_t)c * (KOFF * HW)] = round_tf32(v);
    }
}

// ---------------- host launcher --------------------------------------------
extern "C" void kernel_launch(void* const* d_in, const int* in_sizes, int n_in,
                              void* d_out, int out_size)
{
    const float* x     = (const float*)d_in[0];
    const float* w1    = (const float*)d_in[1];
    const float* gn1s  = (const float*)d_in[2];
    const float* gn1b  = (const float*)d_in[3];
    const float* w_off = (const float*)d_in[4];
    const float* b_off = (const float*)d_in[5];
    const float* w2    = (const float*)d_in[6];
    const float* gn2s  = (const float*)d_in[7];
    const float* gn2b  = (const float*)d_in[8];
    const float* w3    = (const float*)d_in[9];
    const float* gn3s  = (const float*)d_in[10];
    const float* gn3b  = (const float*)d_in[11];
    float* out = (float*)d_out;

    float *p_out1, *p_omp, *p_samp, *p_out2, *p_out3, *p_ap1, *p_ap2, *p_ap3,
          *p_gnp, *p_gn3;
    cudaGetSymbolAddress((void**)&p_out1, g_out1);
    cudaGetSymbolAddress((void**)&p_omp,  g_omp);
    cudaGetSymbolAddress((void**)&p_samp, g_samp);
    cudaGetSymbolAddress((void**)&p_out2, g_out2);
    cudaGetSymbolAddress((void**)&p_out3, g_out3);
    cudaGetSymbolAddress((void**)&p_ap1,  g_ap1);
    cudaGetSymbolAddress((void**)&p_ap2,  g_ap2);
    cudaGetSymbolAddress((void**)&p_ap3,  g_ap3);
    cudaGetSymbolAddress((void**)&p_gnp,  g_gnp);
    cudaGetSymbolAddress((void**)&p_gn3,  g_gn3);

    cudaFuncSetAttribute(tf32_gemm_kernel,
                         cudaFuncAttributeMaxDynamicSharedMemorySize, GEMM_SMEM);

    // launch order keeps gemm1 at captured index 3 (0-based) for ncu visibility
    aperm_round_kernel<<<(CB*CIN + 255)/256, 256>>>(w1, p_ap1, CB, CIN);
    aperm_round_kernel<<<(CB*CB*KOFF + 255)/256, 256>>>(w2, p_ap2, CB, CB*KOFF);
    aperm_round_kernel<<<(CIN*CB + 255)/256, 256>>>(w3, p_ap3, CIN, CB);

    // 1) out1 = w1 @ x   (B = raw x; hw tf32-truncation, bias absorbed by GN1)
    tf32_gemm_kernel<<<dim3(HW/128, CB/128, B_), 256, GEMM_SMEM>>>(
        p_ap1, x, p_out1, CB, HW, CIN, (size_t)CIN*HW, (size_t)CB*HW, nullptr);

    // 2) GN1 + ReLU (in place — feeds conv/deform)
    gn_relu_kernel<<<B_*32, 1024>>>(p_out1, gn1s, gn1b, CB, CB/32);

    // 3) offset conv, channel-split 4 -> partials (combined inside deform)
    conv_off_kernel<<<dim3(W_/16, H_/16, B_*4), 256>>>(p_out1, w_off, p_omp);

    // 4) deform sample * sigmoid(mask) -> rounded [b][c*9+k][hw]
    deform_sample_kernel<<<(B_*KOFF*HW + 255)/256, 256>>>(p_out1, p_omp, b_off, p_samp);

    // 5) out2 = w2_flat @ sampled (M=256, K=2304, N=4096, batch 4)
    tf32_gemm_kernel<<<dim3(HW/128, CB/128, B_), 256, GEMM_SMEM>>>(
        p_ap2, p_samp, p_out2, CB, HW, CB*KOFF,
        (size_t)CB*KOFF*HW, (size_t)CB*HW, nullptr);

    // 6) GN2 + ReLU (in place; GEMM3 truncates B to tf32 in hw)
    gn_relu_kernel<<<B_*32, 1024>>>(p_out2, gn2s, gn2b, CB, CB/32);

    // 7) out3 = w3 @ out2 + GN3 tile stats
    tf32_gemm_kernel<<<dim3(HW/128, CIN/128, B_), 256, GEMM_SMEM>>>(
        p_ap3, p_out2, p_out3, CIN, HW, CB, (size_t)CB*HW, (size_t)CIN*HW, p_gnp);

    // 7b) reduce tile stats -> mean/rstd per (b, group)
    gn3_reduce_kernel<<<1, 128>>>(p_gnp, p_gn3);

    // 8) out = relu(GN3(out3) + x)  — flat single pass, full chip
    gn_res_apply_kernel<<<(B_*CIN*HW/4 + 255)/256, 256>>>(
        p_out3, x, p_gn3, gn3s, gn3b, out);
}

// round 12
// speedup vs baseline: 3.5067x; 1.0128x over previous
#include <cuda_runtime.h>
#include <math.h>

#define B_   4
#define CIN  1024
#define CB   256
#define H_   64
#define W_   64
#define HW   (H_*W_)
#define KOFF 9
#define CQ   8                        // conv channel-split ways
#define DSPLIT 2                      // deform channel-split ways

// ---------------- scratch (device globals; no runtime allocation) ----------
__device__ float g_out1[(size_t)B_*CB*HW];              // 16.7 MB
__device__ float g_omp [(size_t)CQ*B_*27*HW];           // conv partial sums (8-way)
__device__ float g_samp[(size_t)B_*CB*KOFF*HW];         // 151 MB
__device__ float g_out2[(size_t)B_*CB*HW];              // 16.7 MB
__device__ float g_out3[(size_t)B_*CIN*HW];             // 67 MB (GEMM3 out)
__device__ float g_ap1[(size_t)CIN*CB];                 // w1 perm  [K/8][M/16][32][4]
__device__ float g_ap2[(size_t)CB*KOFF*CB];             // w2 perm
__device__ float g_ap3[(size_t)CB*CIN];                 // w3 perm
__device__ float g_gnp[(size_t)B_*32*32*2];             // GN3 tile partials [b][g][tile][2]
__device__ float g_gn3[(size_t)B_*32*2];                // GN3 mean/rstd per (b,g)

__device__ __forceinline__ unsigned f2tf32(float f) {
    unsigned u;
    asm("cvt.rna.tf32.f32 %0, %1;" : "=r"(u) : "f"(f));
    return u;
}
__device__ __forceinline__ float round_tf32(float f) {
    return __uint_as_float(f2tf32(f));
}

__device__ __forceinline__ void cp_async16(void* smem_dst, const void* gsrc) {
    unsigned s = (unsigned)__cvta_generic_to_shared(smem_dst);
    asm volatile("cp.async.cg.shared.global [%0], [%1], 16;\n" :: "r"(s), "l"(gsrc));
}
__device__ __forceinline__ void cp_commit() {
    asm volatile("cp.async.commit_group;\n");
}
template <int N>
__device__ __forceinline__ void cp_wait() {
    asm volatile("cp.async.wait_group %0;\n" :: "n"(N));
}

// ---------------- batched TF32 tensor-core GEMM: C[b] = Aperm @ B[b] -------
#define GSTAGE   3
#define GK       32
#define GROW     136
#define A_STG    (GK * 128)
#define B_STG    (GK * GROW)
#define GEMM_SMEM ((GSTAGE * (A_STG + B_STG)) * 4)
__global__ void __launch_bounds__(256, 2) tf32_gemm_kernel(
    const float* __restrict__ AP, const float* __restrict__ Bm,
    float* __restrict__ Cm, int M, int N, int K,
    size_t strideB, size_t strideC, float* __restrict__ gstats)
{
    extern __shared__ float sm_[];
    float (*As)[4][8][32][4] = (float(*)[4][8][32][4])sm_;
    float (*Bs)[GK][GROW]    = (float(*)[GK][GROW])(sm_ + GSTAGE * A_STG);

    const float* Bp = Bm + (size_t)blockIdx.z * strideB;
    float*       Cp = Cm + (size_t)blockIdx.z * strideC;
    const int bm = blockIdx.y * 128;
    const int bn = blockIdx.x * 128;
    const int nmb = M >> 4;
    const int mb0 = bm >> 4;

    const int tid  = threadIdx.x;
    const int lane = tid & 31;
    const int warp = tid >> 5;
    const int wmb = (warp & 1) * 4;
    const int wn  = (warp >> 1) * 32;
    const int grp = lane >> 2;
    const int tig = lane & 3;

    float acc[4][4][4];
#pragma unroll
    for (int mi = 0; mi < 4; mi++)
#pragma unroll
        for (int ni = 0; ni < 4; ni++)
#pragma unroll
            for (int i = 0; i < 4; i++) acc[mi][ni][i] = 0.f;

    const int nstage = K / GK;

#define LOAD_STAGE(buf, ks)                                                   \
    do {                                                                      \
        _Pragma("unroll")                                                     \
        for (int j = 0; j < 4; j++) {                                         \
            const int id  = tid + 256 * j;                                    \
            const int kb2 = id >> 8;                                          \
            const int rem = id & 255;                                         \
            const int mb  = rem >> 5;                                         \
            const int ln  = rem & 31;                                         \
            cp_async16(&As[buf][kb2][mb][ln][0],                              \
                AP + (((size_t)((ks) * 4 + kb2) * nmb + mb0 + mb) * 32 + ln) * 4); \
            const int kk  = id >> 5;                                          \
            const int col = (id & 31) * 4;                                    \
            cp_async16(&Bs[buf][kk][col],                                     \
                Bp + (size_t)((ks) * GK + kk) * N + bn + col);                \
        }                                                                     \
    } while (0)

    LOAD_STAGE(0, 0); cp_commit();
    LOAD_STAGE(1, 1); cp_commit();

    int cur = 0;
    for (int ks = 0; ks < nstage; ks++) {
        cp_wait<1>();
        __syncthreads();

#pragma unroll
        for (int kb2 = 0; kb2 < 4; kb2++) {
            unsigned a[4][4], b[4][2];
#pragma unroll
            for (int mi = 0; mi < 4; mi++) {
                const float4 av = *(const float4*)&As[cur][kb2][wmb + mi][lane][0];
                a[mi][0] = __float_as_uint(av.x);
                a[mi][1] = __float_as_uint(av.y);
                a[mi][2] = __float_as_uint(av.z);
                a[mi][3] = __float_as_uint(av.w);
            }
#pragma unroll
            for (int ni = 0; ni < 4; ni++) {
                const int n = wn + ni * 8 + grp;
                b[ni][0] = __float_as_uint(Bs[cur][kb2 * 8 + tig    ][n]);
                b[ni][1] = __float_as_uint(Bs[cur][kb2 * 8 + tig + 4][n]);
            }
#pragma unroll
            for (int mi = 0; mi < 4; mi++)
#pragma unroll
                for (int ni = 0; ni < 4; ni++) {
                    asm volatile(
                        "mma.sync.aligned.m16n8k8.row.col.f32.tf32.tf32.f32 "
                        "{%0,%1,%2,%3}, {%4,%5,%6,%7}, {%8,%9}, {%0,%1,%2,%3};\n"
                        : "+f"(acc[mi][ni][0]), "+f"(acc[mi][ni][1]),
                          "+f"(acc[mi][ni][2]), "+f"(acc[mi][ni][3])
                        : "r"(a[mi][0]), "r"(a[mi][1]), "r"(a[mi][2]), "r"(a[mi][3]),
                          "r"(b[ni][0]), "r"(b[ni][1]));
                }
        }

        if (ks + 2 < nstage) {
            const int buf = cur + 2 >= GSTAGE ? cur + 2 - GSTAGE : cur + 2;
            LOAD_STAGE(buf, ks + 2);
        }
        cp_commit();
        cur = cur + 1 >= GSTAGE ? 0 : cur + 1;
    }

    // epilogue: store C
#pragma unroll
    for (int mi = 0; mi < 4; mi++) {
        const int row = bm + (warp & 1) * 64 + mi * 16 + grp;
#pragma unroll
        for (int ni = 0; ni < 4; ni++) {
            const int col = bn + wn + ni * 8 + tig * 2;
            float2 v0 = make_float2(acc[mi][ni][0], acc[mi][ni][1]);
            float2 v1 = make_float2(acc[mi][ni][2], acc[mi][ni][3]);
            *(float2*)(Cp + (size_t)row * N + col)       = v0;
            *(float2*)(Cp + (size_t)(row + 8) * N + col) = v1;
        }
    }

    // optional GN-stat epilogue (32-row groups; GEMM3 only)
    if (gstats) {
        float s0 = 0.f, q0 = 0.f, s1 = 0.f, q1 = 0.f;
#pragma unroll
        for (int mi = 0; mi < 4; mi++) {
            float s = 0.f, q = 0.f;
#pragma unroll
            for (int ni = 0; ni < 4; ni++)
#pragma unroll
                for (int i = 0; i < 4; i++) {
                    const float v = acc[mi][ni][i];
                    s += v; q += v * v;
                }
            if (mi < 2) { s0 += s; q0 += q; } else { s1 += s; q1 += q; }
        }
#pragma unroll
        for (int o = 16; o > 0; o >>= 1) {
            s0 += __shfl_down_sync(0xFFFFFFFFu, s0, o);
            q0 += __shfl_down_sync(0xFFFFFFFFu, q0, o);
            s1 += __shfl_down_sync(0xFFFFFFFFu, s1, o);
            q1 += __shfl_down_sync(0xFFFFFFFFu, q1, o);
        }
        __syncthreads();
        float* red = sm_;
        if (lane == 0) {
            red[warp * 4 + 0] = s0; red[warp * 4 + 1] = q0;
            red[warp * 4 + 2] = s1; red[warp * 4 + 3] = q1;
        }
        __syncthreads();
        if (tid < 4) {
            const int par = tid >> 1;
            const int off = (tid & 1) * 2;
            float s = 0.f, q = 0.f;
#pragma unroll
            for (int j = 0; j < 4; j++) {
                const int w = par + j * 2;
                s += red[w * 4 + off];
                q += red[w * 4 + off + 1];
            }
            const size_t gi = (((size_t)blockIdx.z * 32 + (bm >> 5) + tid) * (N >> 7)
                               + (bn >> 7)) * 2;
            gstats[gi]     = s;
            gstats[gi + 1] = q;
        }
    }
#undef LOAD_STAGE
}

// ---------------- GN3 stats reduce: partials -> mean/rstd ------------------
__global__ void gn3_reduce_kernel(const float* __restrict__ gnp,
                                  float* __restrict__ gn3)
{
    const int i = threadIdx.x;
    if (i >= B_ * 32) return;
    float s = 0.f, q = 0.f;
    const float* p = gnp + (size_t)i * 32 * 2;
#pragma unroll
    for (int t = 0; t < 32; t++) { s += p[t * 2]; q += p[t * 2 + 1]; }
    const float n = 32.f * HW;
    const float mean = s / n;
    const float var  = q / n - mean * mean;
    gn3[i * 2]     = mean;
    gn3[i * 2 + 1] = rsqrtf(var + 1e-5f);
}

// ---------------- weight permute + tf32-round: A[M][K] -> fragment order ---
__global__ void aperm_round_kernel(const float* __restrict__ A,
                                   float* __restrict__ AP, int M, int K)
{
    const int i = blockIdx.x * blockDim.x + threadIdx.x;
    if (i >= M * K) return;
    const int blk = i >> 7;
    const int l   = (i >> 2) & 31;
    const int v   = i & 3;
    const int nmb = M >> 4;
    const int kb = blk / nmb, mb = blk % nmb;
    const int tig = (l & 3) + ((v >> 1) << 2);
    const int grp = (l >> 2) + ((v & 1) << 3);
    const int m = mb * 16 + grp;
    const int k = kb * 8 + tig;
    AP[i] = round_tf32(A[(size_t)m * K + k]);
}

// ---------------- block reduction helper -----------------------------------
__device__ __forceinline__ void block_reduce2(float& s, float& ss) {
#pragma unroll
    for (int o = 16; o > 0; o >>= 1) {
        s  += __shfl_down_sync(0xFFFFFFFFu, s,  o);
        ss += __shfl_down_sync(0xFFFFFFFFu, ss, o);
    }
    __shared__ float as_[32], ass_[32];
    int lane = threadIdx.x & 31, wid = threadIdx.x >> 5;
    if (lane == 0) { as_[wid] = s; ass_[wid] = ss; }
    __syncthreads();
    int nw = blockDim.x >> 5;
    if (wid == 0) {
        s  = (lane < nw) ? as_[lane]  : 0.f;
        ss = (lane < nw) ? ass_[lane] : 0.f;
#pragma unroll
        for (int o = 16; o > 0; o >>= 1) {
            s  += __shfl_down_sync(0xFFFFFFFFu, s,  o);
            ss += __shfl_down_sync(0xFFFFFFFFu, ss, o);
        }
    }
}

// ---------------- GroupNorm (+ReLU), in-place; one block per (b, group) ----
__global__ void gn_relu_kernel(float* __restrict__ data,
                               const float* __restrict__ scale,
                               const float* __restrict__ bias,
                               int C, int cpg)
{
    const int G  = C / cpg;
    const int b  = blockIdx.x / G;
    const int gi = blockIdx.x % G;
    float* p = data + ((size_t)b * C + (size_t)gi * cpg) * HW;
    const int n4 = (cpg * HW) >> 2;

    float s = 0.f, ss = 0.f;
    for (int i = threadIdx.x; i < n4; i += blockDim.x) {
        float4 v = ((const float4*)p)[i];
        s  += v.x + v.y + v.z + v.w;
        ss += v.x * v.x + v.y * v.y + v.z * v.z + v.w * v.w;
    }
    block_reduce2(s, ss);
    __shared__ float sh_mean, sh_rstd;
    if (threadIdx.x == 0) {
        const float n = (float)(cpg * HW);
        float mean = s / n;
        float var  = ss / n - mean * mean;
        sh_mean = mean;
        sh_rstd = rsqrtf(var + 1e-5f);
    }
    __syncthreads();
    const float mean = sh_mean, rstd = sh_rstd;
    for (int i = threadIdx.x; i < n4; i += blockDim.x) {
        int c = gi * cpg + (i * 4) / HW;
        const float a = rstd * scale[c];
        const float d = bias[c] - mean * a;
        float4 v = ((const float4*)p)[i];
        v.x = fmaxf(v.x * a + d, 0.f);
        v.y = fmaxf(v.y * a + d, 0.f);
        v.z = fmaxf(v.z * a + d, 0.f);
        v.w = fmaxf(v.w * a + d, 0.f);
        ((float4*)p)[i] = v;
    }
}

// ---------------- GN3 apply (flat elementwise) + residual + ReLU -----------
__global__ void gn_res_apply_kernel(const float* __restrict__ in,
                                    const float* __restrict__ xres,
                                    const float* __restrict__ gn3,
                                    const float* __restrict__ scale,
                                    const float* __restrict__ bias,
                                    float* __restrict__ out)
{
    const int idx = blockIdx.x * blockDim.x + threadIdx.x;
    if (idx >= B_ * CIN * HW / 4) return;
    const int i4 = idx * 4;
    const int b = i4 / (CIN * HW);
    const int c = (i4 / HW) % CIN;
    const int g = b * 32 + (c >> 5);
    const float mean = gn3[g * 2];
    const float rstd = gn3[g * 2 + 1];
    const float a = rstd * scale[c];
    const float d = bias[c] - mean * a;
    float4 v = ((const float4*)in)[idx];
    float4 rr = ((const float4*)xres)[idx];
    v.x = fmaxf(v.x * a + d + rr.x, 0.f);
    v.y = fmaxf(v.y * a + d + rr.y, 0.f);
    v.z = fmaxf(v.z * a + d + rr.z, 0.f);
    v.w = fmaxf(v.w * a + d + rr.w, 0.f);
    ((float4*)out)[idx] = v;
}

// ---------------- 3x3 offset conv (27 out ch), pad=1, channel-split 8 ------
__global__ void __launch_bounds__(256) conv_off_kernel(
    const float* __restrict__ in,
    const float* __restrict__ w,
    float* __restrict__ omp)         // [CQ][B][27][H][W]
{
    const int bx = blockIdx.x;
    const int by = blockIdx.y;
    const int b = blockIdx.z >> 3;
    const int q = blockIdx.z & 7;
    const int tid = threadIdx.x;
    const int tx = tid & 15, ty = tid >> 4;

    __shared__ float s_in[8][18][18];
    __shared__ float s_w[8][9][28];

    float acc[28];
#pragma unroll
    for (int j = 0; j < 28; j++) acc[j] = 0.f;

    const int x0 = bx * 16, y0 = by * 16;
    const int cbase = q * (CB / CQ);
    const float* inb = in + (size_t)b * CB * HW;

    for (int c0 = cbase; c0 < cbase + CB / CQ; c0 += 8) {
        for (int e = tid; e < 8 * 18 * 18; e += 256) {
            int c = e / 324;
            int r = (e / 18) % 18;
            int col = e % 18;
            int y = y0 + r - 1, x = x0 + col - 1;
            float v = 0.f;
            if (y >= 0 && y < H_ && x >= 0 && x < W_)
                v = inb[(size_t)(c0 + c) * HW + y * W_ + x];
            s_in[c][r][col] = v;
        }
        for (int e = tid; e < 8 * 9 * 28; e += 256) {
            int c = e / (9 * 28);
            int k = (e / 28) % 9;
            int j = e % 28;
            s_w[c][k][j] = (j < 27) ? w[((size_t)j * CB + c0 + c) * 9 + k] : 0.f;
        }
        __syncthreads();
#pragma unroll
        for (int c = 0; c < 8; c++) {
#pragma unroll
            for (int k = 0; k < 9; k++) {
                const float v = s_in[c][ty + k / 3][tx + k % 3];
                const float4* wr = (const float4*)&s_w[c][k][0];
#pragma unroll
                for (int qq = 0; qq < 7; qq++) {
                    const float4 w4 = wr[qq];
                    acc[qq * 4 + 0] += v * w4.x;
                    acc[qq * 4 + 1] += v * w4.y;
                    acc[qq * 4 + 2] += v * w4.z;
                    acc[qq * 4 + 3] += v * w4.w;
                }
            }
        }
        __syncthreads();
    }
    const int hw = (y0 + ty) * W_ + x0 + tx;
    float* op = omp + (size_t)q * B_ * 27 * HW + (size_t)b * 27 * HW;
#pragma unroll
    for (int j = 0; j < 27; j++)
        op[(size_t)j * HW + hw] = acc[j];
}

// ---------------- deformable bilinear sampling (reads CQ conv partials) ----
// Channel-split DSPLIT ways for occupancy: idx covers [DSPLIT][B][K][HW].
__global__ void __launch_bounds__(256) deform_sample_kernel(
    const float* __restrict__ out1,
    const float* __restrict__ omp,   // [CQ][B][27][H][W]
    const float* __restrict__ boff,
    float* __restrict__ sampled)
{
    const int idx = blockIdx.x * blockDim.x + threadIdx.x;
    if (idx >= DSPLIT * B_ * KOFF * HW) return;
    const int hw = idx % HW;
    const int k  = (idx / HW) % KOFF;
    const int b  = (idx / (HW * KOFF)) % B_;
    const int half = idx / (HW * KOFF * B_);
    const int h = hw / W_, w = hw % W_;

    const size_t qstride = (size_t)B_ * 27 * HW;
    const float* o0 = omp + (size_t)b * 27 * HW;
    float offx = boff[k], offy = boff[KOFF + k], mraw = boff[18 + k];
#pragma unroll
    for (int q = 0; q < CQ; q++) {
        const float* oq = o0 + q * qstride;
        offx += oq[(size_t)k * HW + hw];
        offy += oq[(size_t)(KOFF + k) * HW + hw];
        mraw += oq[(size_t)(18 + k) * HW + hw];
    }
    const float mval = 1.f / (1.f + expf(-mraw));

    const float py = (float)(h + k / 3 - 1) + offy;
    const float px = (float)(w + k % 3 - 1) + offx;
    const float y0f = floorf(py), x0f = floorf(px);
    const int y0 = (int)y0f, x0 = (int)x0f;
    const float wy1 = py - y0f, wx1 = px - x0f;
    const float wy0 = 1.f - wy1, wx0 = 1.f - wx1;
    const int y1 = y0 + 1, x1 = x0 + 1;
    const bool vy0 = (y0 >= 0) && (y0 < H_), vy1 = (y1 >= 0) && (y1 < H_);
    const bool vx0 = (x0 >= 0) && (x0 < W_), vx1 = (x1 >= 0) && (x1 < W_);
    const int cy0 = min(max(y0, 0), H_ - 1), cy1 = min(max(y1, 0), H_ - 1);
    const int cx0 = min(max(x0, 0), W_ - 1), cx1 = min(max(x1, 0), W_ - 1);
    const int i00 = cy0 * W_ + cx0, i01 = cy0 * W_ + cx1;
    const int i10 = cy1 * W_ + cx0, i11 = cy1 * W_ + cx1;
    const float w00 = (vy0 && vx0) ? wy0 * wx0 * mval : 0.f;
    const float w01 = (vy0 && vx1) ? wy0 * wx1 * mval : 0.f;
    const float w10 = (vy1 && vx0) ? wy1 * wx0 * mval : 0.f;
    const float w11 = (vy1 && vx1) ? wy1 * wx1 * mval : 0.f;

    const int c0 = half * (CB / DSPLIT);
    const float* base = out1 + (size_t)b * CB * HW;
    const size_t obase = (size_t)b * CB * KOFF * HW + (size_t)k * HW + hw;
#pragma unroll 8
    for (int c = c0; c < c0 + CB / DSPLIT; c++) {
        const float* p = base + (size_t)c * HW;
        float v = w00 * p[i00] + w01 * p[i01] + w10 * p[i10] + w11 * p[i11];
        sampled[obase + (size_t)c * (KOFF * HW)] = round_tf32(v);
    }
}

// ---------------- host launcher --------------------------------------------
extern "C" void kernel_launch(void* const* d_in, const int* in_sizes, int n_in,
                              void* d_out, int out_size)
{
    const float* x     = (const float*)d_in[0];
    const float* w1    = (const float*)d_in[1];
    const float* gn1s  = (const float*)d_in[2];
    const float* gn1b  = (const float*)d_in[3];
    const float* w_off = (const float*)d_in[4];
    const float* b_off = (const float*)d_in[5];
    const float* w2    = (const float*)d_in[6];
    const float* gn2s  = (const float*)d_in[7];
    const float* gn2b  = (const float*)d_in[8];
    const float* w3    = (const float*)d_in[9];
    const float* gn3s  = (const float*)d_in[10];
    const float* gn3b  = (const float*)d_in[11];
    float* out = (float*)d_out;

    float *p_out1, *p_omp, *p_samp, *p_out2, *p_out3, *p_ap1, *p_ap2, *p_ap3,
          *p_gnp, *p_gn3;
    cudaGetSymbolAddress((void**)&p_out1, g_out1);
    cudaGetSymbolAddress((void**)&p_omp,  g_omp);
    cudaGetSymbolAddress((void**)&p_samp, g_samp);
    cudaGetSymbolAddress((void**)&p_out2, g_out2);
    cudaGetSymbolAddress((void**)&p_out3, g_out3);
    cudaGetSymbolAddress((void**)&p_ap1,  g_ap1);
    cudaGetSymbolAddress((void**)&p_ap2,  g_ap2);
    cudaGetSymbolAddress((void**)&p_ap3,  g_ap3);
    cudaGetSymbolAddress((void**)&p_gnp,  g_gnp);
    cudaGetSymbolAddress((void**)&p_gn3,  g_gn3);

    cudaFuncSetAttribute(tf32_gemm_kernel,
                         cudaFuncAttributeMaxDynamicSharedMemorySize, GEMM_SMEM);

    // launch order keeps gemm1 at captured index 3 (0-based) for ncu visibility
    aperm_round_kernel<<<(CB*CIN + 255)/256, 256>>>(w1, p_ap1, CB, CIN);
    aperm_round_kernel<<<(CB*CB*KOFF + 255)/256, 256>>>(w2, p_ap2, CB, CB*KOFF);
    aperm_round_kernel<<<(CIN*CB + 255)/256, 256>>>(w3, p_ap3, CIN, CB);

    // 1) out1 = w1 @ x   (B = raw x; hw tf32-truncation, bias absorbed by GN1)
    tf32_gemm_kernel<<<dim3(HW/128, CB/128, B_), 256, GEMM_SMEM>>>(
        p_ap1, x, p_out1, CB, HW, CIN, (size_t)CIN*HW, (size_t)CB*HW, nullptr);

    // 2) GN1 + ReLU (in place — feeds conv/deform)
    gn_relu_kernel<<<B_*32, 1024>>>(p_out1, gn1s, gn1b, CB, CB/32);

    // 3) offset conv, channel-split 8 -> partials (combined inside deform)
    conv_off_kernel<<<dim3(W_/16, H_/16, B_*CQ), 256>>>(p_out1, w_off, p_omp);

    // 4) deform sample * sigmoid(mask) -> rounded [b][c*9+k][hw], 2-way split
    deform_sample_kernel<<<(DSPLIT*B_*KOFF*HW + 255)/256, 256>>>(
        p_out1, p_omp, b_off, p_samp);

    // 5) out2 = w2_flat @ sampled (M=256, K=2304, N=4096, batch 4)
    tf32_gemm_kernel<<<dim3(HW/128, CB/128, B_), 256, GEMM_SMEM>>>(
        p_ap2, p_samp, p_out2, CB, HW, CB*KOFF,
        (size_t)CB*KOFF*HW, (size_t)CB*HW, nullptr);

    // 6) GN2 + ReLU (in place; GEMM3 truncates B to tf32 in hw)
    gn_relu_kernel<<<B_*32, 1024>>>(p_out2, gn2s, gn2b, CB, CB/32);

    // 7) out3 = w3 @ out2 + GN3 tile stats
    tf32_gemm_kernel<<<dim3(HW/128, CIN/128, B_), 256, GEMM_SMEM>>>(
        p_ap3, p_out2, p_out3, CIN, HW, CB, (size_t)CB*HW, (size_t)CIN*HW, p_gnp);

    // 7b) reduce tile stats -> mean/rstd per (b, group)
    gn3_reduce_kernel<<<1, 128>>>(p_gnp, p_gn3);

    // 8) out = relu(GN3(out3) + x)  — flat single pass, full chip
    gn_res_apply_kernel<<<(B_*CIN*HW/4 + 255)/256, 256>>>(
        p_out3, x, p_gn3, gn3s, gn3b, out);
}